// round 1
// baseline (speedup 1.0000x reference)
#include <cuda_runtime.h>
#include <math.h>

// Problem constants
#define kB 4
#define kS 1024
#define kD 1024
#define kN 16
#define kH 64
#define kBN 64  // kB * kN

// Scratch (device globals: allocation-free rule)
__device__ float g_h[(size_t)kB * kS * kD];        // 16 MB   linear-in output
__device__ float g_p[(size_t)kBN * kS * kH];       // 16 MB   p[bn][s][h]
__device__ float g_xsum[kBN * kH];                 // 16 KB   xsum[bn][h]
__device__ float g_t[(size_t)kBN * kS * kH];       // 16 MB   t[bn][o][e]
__device__ float g_scores[(size_t)kBN * kS * kS];  // 256 MB  scores[bn][s][o]
__device__ float g_ao[(size_t)kB * kS * kD];       // 16 MB   attn out, [b*s][d] layout

// ---------------------------------------------------------------------------
// 128x128x8 NT SGEMM: C[M,N] = alpha * A[M,K] @ B[N,K]^T (+ bias[N])
// Grid: (N/128, M/128, batch). 256 threads, 8x8 micro-tile per thread.
// ---------------------------------------------------------------------------
__global__ __launch_bounds__(256, 2) void gemm_nt_128(
    const float* __restrict__ Ag, const float* __restrict__ Bg,
    const float* __restrict__ bias, float* __restrict__ Cg,
    int K, int lda, int ldb, int ldc,
    long long sA, long long sB, long long sC, float alpha)
{
    const float* A  = Ag + (size_t)blockIdx.z * sA;
    const float* Bm = Bg + (size_t)blockIdx.z * sB;
    float*       C  = Cg + (size_t)blockIdx.z * sC;

    __shared__ float As[8][128];
    __shared__ float Bs[8][128];

    const int tid  = threadIdx.x;
    const int tx   = tid & 15;
    const int ty   = tid >> 4;
    const int row0 = blockIdx.y * 128;
    const int col0 = blockIdx.x * 128;

    const int lr = tid >> 1;        // 0..127
    const int lc = (tid & 1) * 4;   // 0 or 4

    const float* Ap = A  + (size_t)(row0 + lr) * lda + lc;
    const float* Bp = Bm + (size_t)(col0 + lr) * ldb + lc;

    float acc[8][8];
#pragma unroll
    for (int i = 0; i < 8; i++)
#pragma unroll
        for (int j = 0; j < 8; j++) acc[i][j] = 0.f;

    float4 va = *(const float4*)Ap;
    float4 vb = *(const float4*)Bp;

    for (int k0 = 0; k0 < K; k0 += 8) {
        As[lc + 0][lr] = va.x; As[lc + 1][lr] = va.y;
        As[lc + 2][lr] = va.z; As[lc + 3][lr] = va.w;
        Bs[lc + 0][lr] = vb.x; Bs[lc + 1][lr] = vb.y;
        Bs[lc + 2][lr] = vb.z; Bs[lc + 3][lr] = vb.w;
        __syncthreads();
        if (k0 + 8 < K) {
            va = *(const float4*)(Ap + k0 + 8);
            vb = *(const float4*)(Bp + k0 + 8);
        }
#pragma unroll
        for (int kk = 0; kk < 8; kk++) {
            float a[8], b[8];
            *(float4*)&a[0] = *(const float4*)&As[kk][ty * 8];
            *(float4*)&a[4] = *(const float4*)&As[kk][ty * 8 + 4];
            *(float4*)&b[0] = *(const float4*)&Bs[kk][tx * 8];
            *(float4*)&b[4] = *(const float4*)&Bs[kk][tx * 8 + 4];
#pragma unroll
            for (int i = 0; i < 8; i++)
#pragma unroll
                for (int j = 0; j < 8; j++)
                    acc[i][j] += a[i] * b[j];
        }
        __syncthreads();
    }

#pragma unroll
    for (int i = 0; i < 8; i++) {
        const int r = row0 + ty * 8 + i;
        float* Cp = C + (size_t)r * ldc + col0 + tx * 8;
        float o[8];
        if (bias) {
            const float* bp = bias + col0 + tx * 8;
#pragma unroll
            for (int j = 0; j < 8; j++) o[j] = acc[i][j] * alpha + bp[j];
        } else {
#pragma unroll
            for (int j = 0; j < 8; j++) o[j] = acc[i][j] * alpha;
        }
        *(float4*)(Cp)     = *(float4*)&o[0];
        *(float4*)(Cp + 4) = *(float4*)&o[4];
    }
}

// ---------------------------------------------------------------------------
// Per-(b,s,n) softmax over head_dim=64, writes p[bn][s][h], accumulates xsum.
// Grid: (64 bn, 16 s-chunks of 64). 256 threads = 8 warps x 8 rows each.
// ---------------------------------------------------------------------------
__global__ __launch_bounds__(256) void softmax_hd(const float* __restrict__ h,
                                                  float* __restrict__ p,
                                                  float* __restrict__ xsum)
{
    const int bn = blockIdx.x;
    const int b = bn >> 4, n = bn & 15;
    const int warp = threadIdx.x >> 5, lane = threadIdx.x & 31;
    __shared__ float sxs[64];
    if (threadIdx.x < 64) sxs[threadIdx.x] = 0.f;
    __syncthreads();
    float acc0 = 0.f, acc1 = 0.f;
#pragma unroll
    for (int i = 0; i < 8; i++) {
        const int s = blockIdx.y * 64 + warp * 8 + i;
        const float* row = h + (size_t)(b * kS + s) * kD + n * kH;
        float v0 = row[lane], v1 = row[lane + 32];
        float m = fmaxf(v0, v1);
#pragma unroll
        for (int off = 16; off; off >>= 1)
            m = fmaxf(m, __shfl_xor_sync(0xffffffffu, m, off));
        float e0 = __expf(v0 - m), e1 = __expf(v1 - m);
        float ssum = e0 + e1;
#pragma unroll
        for (int off = 16; off; off >>= 1)
            ssum += __shfl_xor_sync(0xffffffffu, ssum, off);
        const float inv = 1.f / ssum;
        e0 *= inv; e1 *= inv;
        float* prow = p + ((size_t)bn * kS + s) * kH;
        prow[lane] = e0; prow[lane + 32] = e1;
        acc0 += e0; acc1 += e1;
    }
    atomicAdd(&sxs[lane], acc0);
    atomicAdd(&sxs[lane + 32], acc1);
    __syncthreads();
    if (threadIdx.x < 64) atomicAdd(&xsum[bn * 64 + threadIdx.x], sxs[threadIdx.x]);
}

__global__ void zero_xsum(float* __restrict__ xsum)
{
    const int i = blockIdx.x * blockDim.x + threadIdx.x;
    if (i < kBN * kH) xsum[i] = 0.f;
}

// ---------------------------------------------------------------------------
// t[bn][o][e] = sum_h W[o][n][e][h] * xsum[bn][h]. One warp per (o,n,e).
// Grid: 1048576 warps / 8 = 131072 blocks of 256.
// ---------------------------------------------------------------------------
__global__ __launch_bounds__(256) void compute_t(const float* __restrict__ W,
                                                 const float* __restrict__ xsum,
                                                 float* __restrict__ t)
{
    const int gw   = blockIdx.x * 8 + (threadIdx.x >> 5);
    const int lane = threadIdx.x & 31;
    const int e = gw & 63;
    const int n = (gw >> 6) & 15;
    const int o = gw >> 10;
    const float* w = W + (((size_t)o * 16 + n) * 64 + e) * 64;
    const float w0 = w[lane], w1 = w[lane + 32];
    const float* xs = xsum + n * 64;  // b stride = 16*64 = 1024 floats
    float r0 = w0 * xs[lane]        + w1 * xs[lane + 32];
    float r1 = w0 * xs[1024 + lane] + w1 * xs[1024 + lane + 32];
    float r2 = w0 * xs[2048 + lane] + w1 * xs[2048 + lane + 32];
    float r3 = w0 * xs[3072 + lane] + w1 * xs[3072 + lane + 32];
#pragma unroll
    for (int off = 16; off; off >>= 1) {
        r0 += __shfl_xor_sync(0xffffffffu, r0, off);
        r1 += __shfl_xor_sync(0xffffffffu, r1, off);
        r2 += __shfl_xor_sync(0xffffffffu, r2, off);
        r3 += __shfl_xor_sync(0xffffffffu, r3, off);
    }
    if (lane == 0)      t[(((size_t)( 0 + n)) * kS + o) * kH + e] = r0;
    else if (lane == 1) t[(((size_t)(16 + n)) * kS + o) * kH + e] = r1;
    else if (lane == 2) t[(((size_t)(32 + n)) * kS + o) * kH + e] = r2;
    else if (lane == 3) t[(((size_t)(48 + n)) * kS + o) * kH + e] = r3;
}

// ---------------------------------------------------------------------------
// Row softmax over 1024 elements, in place. One block (256 thr) per row.
// ---------------------------------------------------------------------------
__global__ __launch_bounds__(256) void softmax_row(float* __restrict__ S)
{
    float* r = S + (size_t)blockIdx.x * kS;
    float4 v = ((float4*)r)[threadIdx.x];
    __shared__ float sred[8];
    const int warp = threadIdx.x >> 5, lane = threadIdx.x & 31;

    float m = fmaxf(fmaxf(v.x, v.y), fmaxf(v.z, v.w));
#pragma unroll
    for (int off = 16; off; off >>= 1)
        m = fmaxf(m, __shfl_xor_sync(0xffffffffu, m, off));
    if (lane == 0) sred[warp] = m;
    __syncthreads();
    float bm = sred[0];
#pragma unroll
    for (int i = 1; i < 8; i++) bm = fmaxf(bm, sred[i]);
    __syncthreads();

    v.x = __expf(v.x - bm); v.y = __expf(v.y - bm);
    v.z = __expf(v.z - bm); v.w = __expf(v.w - bm);
    float s = v.x + v.y + v.z + v.w;
#pragma unroll
    for (int off = 16; off; off >>= 1)
        s += __shfl_xor_sync(0xffffffffu, s, off);
    if (lane == 0) sred[warp] = s;
    __syncthreads();
    float bs = sred[0];
#pragma unroll
    for (int i = 1; i < 8; i++) bs += sred[i];
    const float inv = 1.f / bs;
    v.x *= inv; v.y *= inv; v.z *= inv; v.w *= inv;
    ((float4*)r)[threadIdx.x] = v;
}

// ---------------------------------------------------------------------------
// NN batched GEMM: out[bn][s][h] = sum_o attn[bn][s][o] * p[bn][o][h]
// Writes directly into g_ao at [b*S+s][n*64+h]. BM=128, BN=64, BK=16.
// Grid: (1, 8, 64). 256 threads, 8x4 micro-tile.
// ---------------------------------------------------------------------------
__global__ __launch_bounds__(256, 2) void gemm_nn_attn(
    const float* __restrict__ Ag, const float* __restrict__ Bg,
    float* __restrict__ Cg)
{
    const int z = blockIdx.z;
    const float* A  = Ag + (size_t)z * kS * kS;
    const float* Bb = Bg + (size_t)z * kS * kH;
    float*       C  = Cg + (size_t)(z >> 4) * kS * kD + (z & 15) * kH;

    __shared__ float As[16][128];
    __shared__ float Bs[16][64];

    const int tid  = threadIdx.x;
    const int tx   = tid & 15;
    const int ty   = tid >> 4;
    const int row0 = blockIdx.y * 128;

    const int ar = tid >> 2, ac = (tid & 3) * 4;   // A loader: rows ar, ar+64
    const int bk = tid >> 4, bc = (tid & 15) * 4;  // B loader

    const float* Ap0 = A  + (size_t)(row0 + ar) * kS + ac;
    const float* Ap1 = Ap0 + (size_t)64 * kS;
    const float* Bp  = Bb + (size_t)bk * kH + bc;

    float acc[8][4];
#pragma unroll
    for (int i = 0; i < 8; i++)
#pragma unroll
        for (int j = 0; j < 4; j++) acc[i][j] = 0.f;

    float4 a0 = *(const float4*)Ap0;
    float4 a1 = *(const float4*)Ap1;
    float4 b0 = *(const float4*)Bp;

    for (int k0 = 0; k0 < kS; k0 += 16) {
        As[ac + 0][ar]      = a0.x; As[ac + 1][ar]      = a0.y;
        As[ac + 2][ar]      = a0.z; As[ac + 3][ar]      = a0.w;
        As[ac + 0][ar + 64] = a1.x; As[ac + 1][ar + 64] = a1.y;
        As[ac + 2][ar + 64] = a1.z; As[ac + 3][ar + 64] = a1.w;
        *(float4*)&Bs[bk][bc] = b0;
        __syncthreads();
        if (k0 + 16 < kS) {
            a0 = *(const float4*)(Ap0 + k0 + 16);
            a1 = *(const float4*)(Ap1 + k0 + 16);
            b0 = *(const float4*)(Bp + (size_t)(k0 + 16) * kH);
        }
#pragma unroll
        for (int kk = 0; kk < 16; kk++) {
            float a[8], b[4];
            *(float4*)&a[0] = *(const float4*)&As[kk][ty * 8];
            *(float4*)&a[4] = *(const float4*)&As[kk][ty * 8 + 4];
            *(float4*)&b[0] = *(const float4*)&Bs[kk][tx * 4];
#pragma unroll
            for (int i = 0; i < 8; i++)
#pragma unroll
                for (int j = 0; j < 4; j++)
                    acc[i][j] += a[i] * b[j];
        }
        __syncthreads();
    }

#pragma unroll
    for (int i = 0; i < 8; i++) {
        const int r = row0 + ty * 8 + i;
        float4 o;
        o.x = acc[i][0]; o.y = acc[i][1]; o.z = acc[i][2]; o.w = acc[i][3];
        *(float4*)(C + (size_t)r * kD + tx * 4) = o;
    }
}

// ---------------------------------------------------------------------------
extern "C" void kernel_launch(void* const* d_in, const int* in_sizes, int n_in,
                              void* d_out, int out_size)
{
    (void)in_sizes; (void)n_in; (void)out_size;
    const float* x      = (const float*)d_in[0];
    const float* attn_w = (const float*)d_in[1];
    const float* w_in   = (const float*)d_in[2];
    const float* b_in   = (const float*)d_in[3];
    const float* w_out  = (const float*)d_in[4];
    const float* b_out  = (const float*)d_in[5];
    float* out = (float*)d_out;

    float *ph, *pp, *pxs, *pt, *psc, *pao;
    cudaGetSymbolAddress((void**)&ph,  g_h);
    cudaGetSymbolAddress((void**)&pp,  g_p);
    cudaGetSymbolAddress((void**)&pxs, g_xsum);
    cudaGetSymbolAddress((void**)&pt,  g_t);
    cudaGetSymbolAddress((void**)&psc, g_scores);
    cudaGetSymbolAddress((void**)&pao, g_ao);

    // 1) h = x @ w_in^T + b_in              [4096 x 1024]
    gemm_nt_128<<<dim3(kD / 128, (kB * kS) / 128, 1), 256>>>(
        x, w_in, b_in, ph, kD, kD, kD, kD, 0, 0, 0, 1.f);

    // 2) zero xsum, then softmax over head_dim + xsum accumulation
    zero_xsum<<<16, 256>>>(pxs);
    softmax_hd<<<dim3(kBN, kS / 64), 256>>>(ph, pp, pxs);

    // 3) t[bn][o][e] = sum_h W[o,n,e,h] * xsum[bn][h]
    compute_t<<<(kS * kN * kH) / 8, 256>>>(attn_w, pxs, pt);

    // 4) scores[bn][s][o] = (1/2048) * p[bn][s][:] . t[bn][o][:]
    gemm_nt_128<<<dim3(kS / 128, kS / 128, kBN), 256>>>(
        pp, pt, nullptr, psc, kH, kH, kH, kS,
        (long long)kS * kH, (long long)kS * kH, (long long)kS * kS,
        1.f / 2048.f);

    // 5) softmax over o (row length 1024)
    softmax_row<<<kBN * kS, 256>>>(psc);

    // 6) out_attn[bn][s][h] = attn @ p  -> g_ao in [b*s][d] layout
    gemm_nn_attn<<<dim3(1, kS / 128, kBN), 256>>>(psc, pp, pao);

    // 7) final = g_ao @ w_out^T + b_out
    gemm_nt_128<<<dim3(kD / 128, (kB * kS) / 128, 1), 256>>>(
        pao, w_out, b_out, out, kD, kD, kD, kD, 0, 0, 0, 1.f);
}

// round 2
// speedup vs baseline: 1.8707x; 1.8707x over previous
#include <cuda_runtime.h>
#include <math.h>

// Problem constants
#define kB 4
#define kS 1024
#define kD 1024
#define kN 16
#define kH 64
#define kBN 64  // kB * kN

// Scratch (device globals: allocation-free rule)
__device__ float g_h[(size_t)kB * kS * kD];        // 16 MB
__device__ float g_p[(size_t)kBN * kS * kH];       // 16 MB
__device__ float g_xsum[kBN * kH];                 // 16 KB
__device__ float g_t[(size_t)kBN * kS * kH];       // 16 MB
__device__ float g_scores[(size_t)kBN * kS * kS];  // 256 MB
__device__ float g_ao[(size_t)kB * kS * kD];       // 16 MB

// ---------------------------------------------------------------------------
// tf32 helpers
// ---------------------------------------------------------------------------
__device__ __forceinline__ unsigned f2tf(float f) {
    unsigned u;
    asm("cvt.rna.tf32.f32 %0, %1;" : "=r"(u) : "f"(f));
    return u;
}

#define MMA_TF32(ac, a0, a1, a2, a3, b0, b1)                                   \
    asm volatile(                                                              \
        "mma.sync.aligned.m16n8k8.row.col.f32.tf32.tf32.f32 "                  \
        "{%0,%1,%2,%3}, {%4,%5,%6,%7}, {%8,%9}, {%0,%1,%2,%3};"                \
        : "+f"((ac)[0]), "+f"((ac)[1]), "+f"((ac)[2]), "+f"((ac)[3])           \
        : "r"(a0), "r"(a1), "r"(a2), "r"(a3), "r"(b0), "r"(b1))

// ---------------------------------------------------------------------------
// TF32 NT GEMM: C[M,N] = alpha * A[M,K] @ B[N,K]^T (+ bias[N])
// 128x128x16 tiles, 8 warps of 32x64 each, m16n8k8 tf32 MMA.
// Grid: (N/128, M/128, batch). 256 threads.
// ---------------------------------------------------------------------------
__global__ __launch_bounds__(256) void gemm_tf32_nt(
    const float* __restrict__ Ag, const float* __restrict__ Bg,
    const float* __restrict__ bias, float* __restrict__ Cg,
    int K, int lda, int ldb, int ldc,
    long long sA, long long sB, long long sC, float alpha)
{
    const float* A = Ag + (size_t)blockIdx.z * sA;
    const float* B = Bg + (size_t)blockIdx.z * sB;
    float*       C = Cg + (size_t)blockIdx.z * sC;

    __shared__ unsigned As[16][136];
    __shared__ unsigned Bs[16][136];

    const int tid  = threadIdx.x;
    const int lane = tid & 31, wid = tid >> 5;
    const int warpRow = wid & 3, warpCol = wid >> 2;
    const int gid = lane >> 2, tig = lane & 3;
    const int row0 = blockIdx.y * 128, col0 = blockIdx.x * 128;

    // Global loaders: 2 float4 from A, 2 from B per thread.
    const int lr = tid >> 2;          // 0..63
    const int lc = (tid & 3) * 4;     // 0,4,8,12
    const float* Ap0 = A + (size_t)(row0 + lr)      * lda + lc;
    const float* Ap1 = A + (size_t)(row0 + lr + 64) * lda + lc;
    const float* Bp0 = B + (size_t)(col0 + lr)      * ldb + lc;
    const float* Bp1 = B + (size_t)(col0 + lr + 64) * ldb + lc;

    float acc[2][8][4];
#pragma unroll
    for (int i = 0; i < 2; i++)
#pragma unroll
        for (int j = 0; j < 8; j++)
#pragma unroll
            for (int k = 0; k < 4; k++) acc[i][j][k] = 0.f;

    float4 a0v = *(const float4*)Ap0;
    float4 a1v = *(const float4*)Ap1;
    float4 b0v = *(const float4*)Bp0;
    float4 b1v = *(const float4*)Bp1;

    for (int k0 = 0; k0 < K; k0 += 16) {
        As[lc + 0][lr]      = f2tf(a0v.x); As[lc + 1][lr]      = f2tf(a0v.y);
        As[lc + 2][lr]      = f2tf(a0v.z); As[lc + 3][lr]      = f2tf(a0v.w);
        As[lc + 0][lr + 64] = f2tf(a1v.x); As[lc + 1][lr + 64] = f2tf(a1v.y);
        As[lc + 2][lr + 64] = f2tf(a1v.z); As[lc + 3][lr + 64] = f2tf(a1v.w);
        Bs[lc + 0][lr]      = f2tf(b0v.x); Bs[lc + 1][lr]      = f2tf(b0v.y);
        Bs[lc + 2][lr]      = f2tf(b0v.z); Bs[lc + 3][lr]      = f2tf(b0v.w);
        Bs[lc + 0][lr + 64] = f2tf(b1v.x); Bs[lc + 1][lr + 64] = f2tf(b1v.y);
        Bs[lc + 2][lr + 64] = f2tf(b1v.z); Bs[lc + 3][lr + 64] = f2tf(b1v.w);
        __syncthreads();
        if (k0 + 16 < K) {
            a0v = *(const float4*)(Ap0 + k0 + 16);
            a1v = *(const float4*)(Ap1 + k0 + 16);
            b0v = *(const float4*)(Bp0 + k0 + 16);
            b1v = *(const float4*)(Bp1 + k0 + 16);
        }
#pragma unroll
        for (int ks = 0; ks < 16; ks += 8) {
            unsigned af[2][4], bf[8][2];
#pragma unroll
            for (int mt = 0; mt < 2; mt++) {
                const int m = warpRow * 32 + mt * 16 + gid;
                af[mt][0] = As[ks + tig][m];
                af[mt][1] = As[ks + tig][m + 8];
                af[mt][2] = As[ks + tig + 4][m];
                af[mt][3] = As[ks + tig + 4][m + 8];
            }
#pragma unroll
            for (int nt = 0; nt < 8; nt++) {
                const int n = warpCol * 64 + nt * 8 + gid;
                bf[nt][0] = Bs[ks + tig][n];
                bf[nt][1] = Bs[ks + tig + 4][n];
            }
#pragma unroll
            for (int mt = 0; mt < 2; mt++)
#pragma unroll
                for (int nt = 0; nt < 8; nt++)
                    MMA_TF32(acc[mt][nt], af[mt][0], af[mt][1], af[mt][2],
                             af[mt][3], bf[nt][0], bf[nt][1]);
        }
        __syncthreads();
    }

#pragma unroll
    for (int mt = 0; mt < 2; mt++) {
#pragma unroll
        for (int nt = 0; nt < 8; nt++) {
            const int row = row0 + warpRow * 32 + mt * 16 + gid;
            const int col = col0 + warpCol * 64 + nt * 8 + 2 * tig;
            float bb0 = 0.f, bb1 = 0.f;
            if (bias) { bb0 = bias[col]; bb1 = bias[col + 1]; }
            float2 v0, v1;
            v0.x = acc[mt][nt][0] * alpha + bb0;
            v0.y = acc[mt][nt][1] * alpha + bb1;
            v1.x = acc[mt][nt][2] * alpha + bb0;
            v1.y = acc[mt][nt][3] * alpha + bb1;
            *(float2*)(C + (size_t)row * ldc + col)       = v0;
            *(float2*)(C + (size_t)(row + 8) * ldc + col) = v1;
        }
    }
}

// ---------------------------------------------------------------------------
// TF32 NN batched GEMM for attn @ p:
// out[bn][s][h] = sum_o attn[bn][s][o] * p[bn][o][h], written to [b*S+s][n*64+h]
// BM=128, BN=64, BK=16. 8 warps of 16x64. Grid: (1, 8, 64).
// ---------------------------------------------------------------------------
__global__ __launch_bounds__(256) void gemm_tf32_nn_attn(
    const float* __restrict__ Ag, const float* __restrict__ Bg,
    float* __restrict__ Cg)
{
    const int z = blockIdx.z;
    const float* A = Ag + (size_t)z * kS * kS;
    const float* B = Bg + (size_t)z * kS * kH;
    float*       C = Cg + (size_t)(z >> 4) * kS * kD + (z & 15) * kH;

    __shared__ unsigned As[16][136];
    __shared__ unsigned Bs[16][72];

    const int tid  = threadIdx.x;
    const int lane = tid & 31, wid = tid >> 5;
    const int gid = lane >> 2, tig = lane & 3;
    const int row0 = blockIdx.y * 128;

    const int lr = tid >> 2;          // A loader rows (0..63)
    const int lc = (tid & 3) * 4;
    const int gk = tid >> 4;          // B loader k (0..15)
    const int gn = (tid & 15) * 4;    // B loader n

    const float* Ap0 = A + (size_t)(row0 + lr)      * kS + lc;
    const float* Ap1 = A + (size_t)(row0 + lr + 64) * kS + lc;
    const float* Bp  = B + (size_t)gk * kH + gn;

    float acc[8][4];
#pragma unroll
    for (int j = 0; j < 8; j++)
#pragma unroll
        for (int k = 0; k < 4; k++) acc[j][k] = 0.f;

    float4 a0v = *(const float4*)Ap0;
    float4 a1v = *(const float4*)Ap1;
    float4 b0v = *(const float4*)Bp;

    for (int k0 = 0; k0 < kS; k0 += 16) {
        As[lc + 0][lr]      = f2tf(a0v.x); As[lc + 1][lr]      = f2tf(a0v.y);
        As[lc + 2][lr]      = f2tf(a0v.z); As[lc + 3][lr]      = f2tf(a0v.w);
        As[lc + 0][lr + 64] = f2tf(a1v.x); As[lc + 1][lr + 64] = f2tf(a1v.y);
        As[lc + 2][lr + 64] = f2tf(a1v.z); As[lc + 3][lr + 64] = f2tf(a1v.w);
        Bs[gk][gn + 0] = f2tf(b0v.x); Bs[gk][gn + 1] = f2tf(b0v.y);
        Bs[gk][gn + 2] = f2tf(b0v.z); Bs[gk][gn + 3] = f2tf(b0v.w);
        __syncthreads();
        if (k0 + 16 < kS) {
            a0v = *(const float4*)(Ap0 + k0 + 16);
            a1v = *(const float4*)(Ap1 + k0 + 16);
            b0v = *(const float4*)(Bp + (size_t)(k0 + 16) * kH);
        }
#pragma unroll
        for (int ks = 0; ks < 16; ks += 8) {
            unsigned af[4], bf[8][2];
            const int m = wid * 16 + gid;
            af[0] = As[ks + tig][m];
            af[1] = As[ks + tig][m + 8];
            af[2] = As[ks + tig + 4][m];
            af[3] = As[ks + tig + 4][m + 8];
#pragma unroll
            for (int nt = 0; nt < 8; nt++) {
                const int n = nt * 8 + gid;
                bf[nt][0] = Bs[ks + tig][n];
                bf[nt][1] = Bs[ks + tig + 4][n];
            }
#pragma unroll
            for (int nt = 0; nt < 8; nt++)
                MMA_TF32(acc[nt], af[0], af[1], af[2], af[3], bf[nt][0], bf[nt][1]);
        }
        __syncthreads();
    }

#pragma unroll
    for (int nt = 0; nt < 8; nt++) {
        const int row = row0 + wid * 16 + gid;
        const int col = nt * 8 + 2 * tig;
        float2 v0, v1;
        v0.x = acc[nt][0]; v0.y = acc[nt][1];
        v1.x = acc[nt][2]; v1.y = acc[nt][3];
        *(float2*)(C + (size_t)row * kD + col)       = v0;
        *(float2*)(C + (size_t)(row + 8) * kD + col) = v1;
    }
}

// ---------------------------------------------------------------------------
// Per-(b,s,n) softmax over head_dim=64, writes p, accumulates xsum.
// ---------------------------------------------------------------------------
__global__ __launch_bounds__(256) void softmax_hd(const float* __restrict__ h,
                                                  float* __restrict__ p,
                                                  float* __restrict__ xsum)
{
    const int bn = blockIdx.x;
    const int b = bn >> 4, n = bn & 15;
    const int warp = threadIdx.x >> 5, lane = threadIdx.x & 31;
    __shared__ float sxs[64];
    if (threadIdx.x < 64) sxs[threadIdx.x] = 0.f;
    __syncthreads();
    float acc0 = 0.f, acc1 = 0.f;
#pragma unroll
    for (int i = 0; i < 8; i++) {
        const int s = blockIdx.y * 64 + warp * 8 + i;
        const float* row = h + (size_t)(b * kS + s) * kD + n * kH;
        float v0 = row[lane], v1 = row[lane + 32];
        float m = fmaxf(v0, v1);
#pragma unroll
        for (int off = 16; off; off >>= 1)
            m = fmaxf(m, __shfl_xor_sync(0xffffffffu, m, off));
        float e0 = __expf(v0 - m), e1 = __expf(v1 - m);
        float ssum = e0 + e1;
#pragma unroll
        for (int off = 16; off; off >>= 1)
            ssum += __shfl_xor_sync(0xffffffffu, ssum, off);
        const float inv = 1.f / ssum;
        e0 *= inv; e1 *= inv;
        float* prow = p + ((size_t)bn * kS + s) * kH;
        prow[lane] = e0; prow[lane + 32] = e1;
        acc0 += e0; acc1 += e1;
    }
    atomicAdd(&sxs[lane], acc0);
    atomicAdd(&sxs[lane + 32], acc1);
    __syncthreads();
    if (threadIdx.x < 64) atomicAdd(&xsum[bn * 64 + threadIdx.x], sxs[threadIdx.x]);
}

__global__ void zero_xsum(float* __restrict__ xsum)
{
    const int i = blockIdx.x * blockDim.x + threadIdx.x;
    if (i < kBN * kH) xsum[i] = 0.f;
}

// ---------------------------------------------------------------------------
// compute_t: t[bn][o][e] = sum_h W[o][n][e][h] * xsum[bn][h]
// Block per (o,n): 256 threads, each handles one (e, 16-h chunk), coalesced
// 64B-per-thread reads, 2-shuffle reduction across 4 lanes, 4 batches.
// Grid: 16384.
// ---------------------------------------------------------------------------
__global__ __launch_bounds__(256) void compute_t2(const float* __restrict__ W,
                                                  const float* __restrict__ xsum,
                                                  float* __restrict__ t)
{
    const int on = blockIdx.x;
    const int n = on & 15, o = on >> 4;
    __shared__ float xs[4][64];
    {
        const int b = threadIdx.x >> 6, h = threadIdx.x & 63;
        xs[b][h] = xsum[(b * 16 + n) * 64 + h];
    }
    __syncthreads();
    const int e = threadIdx.x >> 2, part = threadIdx.x & 3;
    const float4* w =
        (const float4*)(W + (((size_t)o * 16 + n) * 64 + e) * 64 + part * 16);
    const float4 w0 = w[0], w1 = w[1], w2 = w[2], w3 = w[3];
    float r[4];
#pragma unroll
    for (int b = 0; b < 4; b++) {
        const float* x = &xs[b][part * 16];
        r[b] = w0.x * x[0]  + w0.y * x[1]  + w0.z * x[2]  + w0.w * x[3]
             + w1.x * x[4]  + w1.y * x[5]  + w1.z * x[6]  + w1.w * x[7]
             + w2.x * x[8]  + w2.y * x[9]  + w2.z * x[10] + w2.w * x[11]
             + w3.x * x[12] + w3.y * x[13] + w3.z * x[14] + w3.w * x[15];
    }
#pragma unroll
    for (int b = 0; b < 4; b++) {
        r[b] += __shfl_xor_sync(0xffffffffu, r[b], 1);
        r[b] += __shfl_xor_sync(0xffffffffu, r[b], 2);
    }
    // lane `part` owns batch b == part (all lanes hold full sums now)
    t[(((size_t)(part * 16 + n)) * kS + o) * kH + e] = r[part];
}

// ---------------------------------------------------------------------------
// Row softmax over 1024 elements, in place. One block (256 thr) per row.
// ---------------------------------------------------------------------------
__global__ __launch_bounds__(256) void softmax_row(float* __restrict__ S)
{
    float* r = S + (size_t)blockIdx.x * kS;
    float4 v = ((float4*)r)[threadIdx.x];
    __shared__ float sred[8];
    const int warp = threadIdx.x >> 5, lane = threadIdx.x & 31;

    float m = fmaxf(fmaxf(v.x, v.y), fmaxf(v.z, v.w));
#pragma unroll
    for (int off = 16; off; off >>= 1)
        m = fmaxf(m, __shfl_xor_sync(0xffffffffu, m, off));
    if (lane == 0) sred[warp] = m;
    __syncthreads();
    float bm = sred[0];
#pragma unroll
    for (int i = 1; i < 8; i++) bm = fmaxf(bm, sred[i]);
    __syncthreads();

    v.x = __expf(v.x - bm); v.y = __expf(v.y - bm);
    v.z = __expf(v.z - bm); v.w = __expf(v.w - bm);
    float s = v.x + v.y + v.z + v.w;
#pragma unroll
    for (int off = 16; off; off >>= 1)
        s += __shfl_xor_sync(0xffffffffu, s, off);
    if (lane == 0) sred[warp] = s;
    __syncthreads();
    float bs = sred[0];
#pragma unroll
    for (int i = 1; i < 8; i++) bs += sred[i];
    const float inv = 1.f / bs;
    v.x *= inv; v.y *= inv; v.z *= inv; v.w *= inv;
    ((float4*)r)[threadIdx.x] = v;
}

// ---------------------------------------------------------------------------
extern "C" void kernel_launch(void* const* d_in, const int* in_sizes, int n_in,
                              void* d_out, int out_size)
{
    (void)in_sizes; (void)n_in; (void)out_size;
    const float* x      = (const float*)d_in[0];
    const float* attn_w = (const float*)d_in[1];
    const float* w_in   = (const float*)d_in[2];
    const float* b_in   = (const float*)d_in[3];
    const float* w_out  = (const float*)d_in[4];
    const float* b_out  = (const float*)d_in[5];
    float* out = (float*)d_out;

    float *ph, *pp, *pxs, *pt, *psc, *pao;
    cudaGetSymbolAddress((void**)&ph,  g_h);
    cudaGetSymbolAddress((void**)&pp,  g_p);
    cudaGetSymbolAddress((void**)&pxs, g_xsum);
    cudaGetSymbolAddress((void**)&pt,  g_t);
    cudaGetSymbolAddress((void**)&psc, g_scores);
    cudaGetSymbolAddress((void**)&pao, g_ao);

    // 1) h = x @ w_in^T + b_in              [4096 x 1024]
    gemm_tf32_nt<<<dim3(kD / 128, (kB * kS) / 128, 1), 256>>>(
        x, w_in, b_in, ph, kD, kD, kD, kD, 0, 0, 0, 1.f);

    // 2) zero xsum, softmax over head_dim + xsum accumulation
    zero_xsum<<<16, 256>>>(pxs);
    softmax_hd<<<dim3(kBN, kS / 64), 256>>>(ph, pp, pxs);

    // 3) t[bn][o][e] = sum_h W[o,n,e,h] * xsum[bn][h]
    compute_t2<<<kS * kN, 256>>>(attn_w, pxs, pt);

    // 4) scores[bn][s][o] = (1/2048) * p[bn][s][:] . t[bn][o][:]
    gemm_tf32_nt<<<dim3(kS / 128, kS / 128, kBN), 256>>>(
        pp, pt, nullptr, psc, kH, kH, kH, kS,
        (long long)kS * kH, (long long)kS * kH, (long long)kS * kS,
        1.f / 2048.f);

    // 5) softmax over o (row length 1024)
    softmax_row<<<kBN * kS, 256>>>(psc);

    // 6) out_attn = attn @ p  -> g_ao in [b*s][d] layout
    gemm_tf32_nn_attn<<<dim3(1, kS / 128, kBN), 256>>>(psc, pp, pao);

    // 7) final = g_ao @ w_out^T + b_out
    gemm_tf32_nt<<<dim3(kD / 128, (kB * kS) / 128, 1), 256>>>(
        pao, w_out, b_out, out, kD, kD, kD, kD, 0, 0, 0, 1.f);
}

// round 3
// speedup vs baseline: 2.5916x; 1.3853x over previous
#include <cuda_runtime.h>
#include <math.h>

// Problem constants
#define kB 4
#define kS 1024
#define kD 1024
#define kN 16
#define kH 64
#define kBN 64  // kB * kN

// Scratch (device globals: allocation-free rule)
__device__ float g_h[(size_t)kB * kS * kD];        // 16 MB
__device__ float g_p[(size_t)kBN * kS * kH];       // 16 MB
__device__ float g_xsum[kBN * kH];                 // 16 KB
__device__ float g_t[(size_t)kBN * kS * kH];       // 16 MB
__device__ float g_ao[(size_t)kB * kS * kD];       // 16 MB

// ---------------------------------------------------------------------------
// tf32 helpers
// ---------------------------------------------------------------------------
__device__ __forceinline__ unsigned f2tf(float f) {
    unsigned u;
    asm("cvt.rna.tf32.f32 %0, %1;" : "=r"(u) : "f"(f));
    return u;
}

#define MMA_TF32(ac, a0, a1, a2, a3, b0, b1)                                   \
    asm volatile(                                                              \
        "mma.sync.aligned.m16n8k8.row.col.f32.tf32.tf32.f32 "                  \
        "{%0,%1,%2,%3}, {%4,%5,%6,%7}, {%8,%9}, {%0,%1,%2,%3};"                \
        : "+f"((ac)[0]), "+f"((ac)[1]), "+f"((ac)[2]), "+f"((ac)[3])           \
        : "r"(a0), "r"(a1), "r"(a2), "r"(a3), "r"(b0), "r"(b1))

// ---------------------------------------------------------------------------
// TF32 NT GEMM: C[M,N] = alpha * A[M,K] @ B[N,K]^T (+ bias[N])
// 128x128x16 tiles, 8 warps of 32x64 each, m16n8k8 tf32 MMA.
// ---------------------------------------------------------------------------
__global__ __launch_bounds__(256) void gemm_tf32_nt(
    const float* __restrict__ Ag, const float* __restrict__ Bg,
    const float* __restrict__ bias, float* __restrict__ Cg,
    int K, int lda, int ldb, int ldc, float alpha)
{
    const float* A = Ag;
    const float* B = Bg;
    float*       C = Cg;

    __shared__ unsigned As[16][136];
    __shared__ unsigned Bs[16][136];

    const int tid  = threadIdx.x;
    const int lane = tid & 31, wid = tid >> 5;
    const int warpRow = wid & 3, warpCol = wid >> 2;
    const int gid = lane >> 2, tig = lane & 3;
    const int row0 = blockIdx.y * 128, col0 = blockIdx.x * 128;

    const int lr = tid >> 2;
    const int lc = (tid & 3) * 4;
    const float* Ap0 = A + (size_t)(row0 + lr)      * lda + lc;
    const float* Ap1 = A + (size_t)(row0 + lr + 64) * lda + lc;
    const float* Bp0 = B + (size_t)(col0 + lr)      * ldb + lc;
    const float* Bp1 = B + (size_t)(col0 + lr + 64) * ldb + lc;

    float acc[2][8][4];
#pragma unroll
    for (int i = 0; i < 2; i++)
#pragma unroll
        for (int j = 0; j < 8; j++)
#pragma unroll
            for (int k = 0; k < 4; k++) acc[i][j][k] = 0.f;

    float4 a0v = *(const float4*)Ap0;
    float4 a1v = *(const float4*)Ap1;
    float4 b0v = *(const float4*)Bp0;
    float4 b1v = *(const float4*)Bp1;

    for (int k0 = 0; k0 < K; k0 += 16) {
        As[lc + 0][lr]      = f2tf(a0v.x); As[lc + 1][lr]      = f2tf(a0v.y);
        As[lc + 2][lr]      = f2tf(a0v.z); As[lc + 3][lr]      = f2tf(a0v.w);
        As[lc + 0][lr + 64] = f2tf(a1v.x); As[lc + 1][lr + 64] = f2tf(a1v.y);
        As[lc + 2][lr + 64] = f2tf(a1v.z); As[lc + 3][lr + 64] = f2tf(a1v.w);
        Bs[lc + 0][lr]      = f2tf(b0v.x); Bs[lc + 1][lr]      = f2tf(b0v.y);
        Bs[lc + 2][lr]      = f2tf(b0v.z); Bs[lc + 3][lr]      = f2tf(b0v.w);
        Bs[lc + 0][lr + 64] = f2tf(b1v.x); Bs[lc + 1][lr + 64] = f2tf(b1v.y);
        Bs[lc + 2][lr + 64] = f2tf(b1v.z); Bs[lc + 3][lr + 64] = f2tf(b1v.w);
        __syncthreads();
        if (k0 + 16 < K) {
            a0v = *(const float4*)(Ap0 + k0 + 16);
            a1v = *(const float4*)(Ap1 + k0 + 16);
            b0v = *(const float4*)(Bp0 + k0 + 16);
            b1v = *(const float4*)(Bp1 + k0 + 16);
        }
#pragma unroll
        for (int ks = 0; ks < 16; ks += 8) {
            unsigned af[2][4], bf[8][2];
#pragma unroll
            for (int mt = 0; mt < 2; mt++) {
                const int m = warpRow * 32 + mt * 16 + gid;
                af[mt][0] = As[ks + tig][m];
                af[mt][1] = As[ks + tig][m + 8];
                af[mt][2] = As[ks + tig + 4][m];
                af[mt][3] = As[ks + tig + 4][m + 8];
            }
#pragma unroll
            for (int nt = 0; nt < 8; nt++) {
                const int n = warpCol * 64 + nt * 8 + gid;
                bf[nt][0] = Bs[ks + tig][n];
                bf[nt][1] = Bs[ks + tig + 4][n];
            }
#pragma unroll
            for (int mt = 0; mt < 2; mt++)
#pragma unroll
                for (int nt = 0; nt < 8; nt++)
                    MMA_TF32(acc[mt][nt], af[mt][0], af[mt][1], af[mt][2],
                             af[mt][3], bf[nt][0], bf[nt][1]);
        }
        __syncthreads();
    }

#pragma unroll
    for (int mt = 0; mt < 2; mt++) {
#pragma unroll
        for (int nt = 0; nt < 8; nt++) {
            const int row = row0 + warpRow * 32 + mt * 16 + gid;
            const int col = col0 + warpCol * 64 + nt * 8 + 2 * tig;
            float bb0 = 0.f, bb1 = 0.f;
            if (bias) { bb0 = bias[col]; bb1 = bias[col + 1]; }
            float2 v0, v1;
            v0.x = acc[mt][nt][0] * alpha + bb0;
            v0.y = acc[mt][nt][1] * alpha + bb1;
            v1.x = acc[mt][nt][2] * alpha + bb0;
            v1.y = acc[mt][nt][3] * alpha + bb1;
            *(float2*)(C + (size_t)row * ldc + col)       = v0;
            *(float2*)(C + (size_t)(row + 8) * ldc + col) = v1;
        }
    }
}

// ---------------------------------------------------------------------------
// Fused flash attention over o-dim:
//   scores[s][o] = p[bn][s][:] . t[bn][o][:] / 2048
//   attn = softmax_o(scores);  out = attn @ p[bn]
// Q=p tile (128x64), K=t, V=p, streamed in 64-o tiles. Online softmax.
// Grid: (kS/128, kBN). 256 threads = 8 warps x 16 rows.
// ---------------------------------------------------------------------------
#define FL_SMEM_WORDS (128 * 68 + 64 * 68 + 64 * 72 + 128 * 68)
__global__ __launch_bounds__(256, 2) void flash_attn(
    const float* __restrict__ Pg, const float* __restrict__ Tg,
    float* __restrict__ AOg)
{
    extern __shared__ unsigned sm[];
    unsigned* Qs = sm;                      // [128][68]
    unsigned* Ks = Qs + 128 * 68;           // [64][68]
    unsigned* Vs = Ks + 64 * 68;            // [64][72]
    unsigned* Ps = Vs + 64 * 72;            // [128][68]

    const int bn = blockIdx.y;
    const int s0 = blockIdx.x * 128;
    const float* Pp = Pg + (size_t)bn * kS * kH;
    const float* Tp = Tg + (size_t)bn * kS * kH;

    const int tid = threadIdx.x, lane = tid & 31, wid = tid >> 5;
    const int gid = lane >> 2, tig = lane & 3;
    const int mrow = wid * 16 + gid;

    // Load Q tile (stays resident)
    for (int i = tid; i < 128 * 16; i += 256) {
        const int r = i >> 4, c = (i & 15) * 4;
        float4 v = *(const float4*)(Pp + (size_t)(s0 + r) * kH + c);
        Qs[r * 68 + c]     = f2tf(v.x);
        Qs[r * 68 + c + 1] = f2tf(v.y);
        Qs[r * 68 + c + 2] = f2tf(v.z);
        Qs[r * 68 + c + 3] = f2tf(v.w);
    }

    float m0 = -1e30f, m1 = -1e30f, l0 = 0.f, l1 = 0.f;
    float acc_o[8][4];
#pragma unroll
    for (int j = 0; j < 8; j++)
#pragma unroll
        for (int k = 0; k < 4; k++) acc_o[j][k] = 0.f;

    const float scale = 1.f / 2048.f;

    for (int o0 = 0; o0 < kS; o0 += 64) {
        __syncthreads();
        // Load K (=t) and V (=p) tiles
        for (int i = tid; i < 64 * 16; i += 256) {
            const int r = i >> 4, c = (i & 15) * 4;
            float4 kv = *(const float4*)(Tp + (size_t)(o0 + r) * kH + c);
            float4 vv = *(const float4*)(Pp + (size_t)(o0 + r) * kH + c);
            Ks[r * 68 + c]     = f2tf(kv.x);
            Ks[r * 68 + c + 1] = f2tf(kv.y);
            Ks[r * 68 + c + 2] = f2tf(kv.z);
            Ks[r * 68 + c + 3] = f2tf(kv.w);
            Vs[r * 72 + c]     = f2tf(vv.x);
            Vs[r * 72 + c + 1] = f2tf(vv.y);
            Vs[r * 72 + c + 2] = f2tf(vv.z);
            Vs[r * 72 + c + 3] = f2tf(vv.w);
        }
        __syncthreads();

        // S = Q @ K^T
        float acc_s[8][4];
#pragma unroll
        for (int j = 0; j < 8; j++)
#pragma unroll
            for (int k = 0; k < 4; k++) acc_s[j][k] = 0.f;

#pragma unroll
        for (int ks = 0; ks < 64; ks += 8) {
            unsigned a0 = Qs[mrow * 68 + ks + tig];
            unsigned a1 = Qs[(mrow + 8) * 68 + ks + tig];
            unsigned a2 = Qs[mrow * 68 + ks + tig + 4];
            unsigned a3 = Qs[(mrow + 8) * 68 + ks + tig + 4];
#pragma unroll
            for (int nt = 0; nt < 8; nt++) {
                unsigned b0 = Ks[(nt * 8 + gid) * 68 + ks + tig];
                unsigned b1 = Ks[(nt * 8 + gid) * 68 + ks + tig + 4];
                MMA_TF32(acc_s[nt], a0, a1, a2, a3, b0, b1);
            }
        }

        // Row stats (rows mrow, mrow+8), online softmax update
        float tm0 = -1e30f, tm1 = -1e30f;
#pragma unroll
        for (int nt = 0; nt < 8; nt++) {
            tm0 = fmaxf(tm0, fmaxf(acc_s[nt][0], acc_s[nt][1]));
            tm1 = fmaxf(tm1, fmaxf(acc_s[nt][2], acc_s[nt][3]));
        }
        tm0 *= scale; tm1 *= scale;
        tm0 = fmaxf(tm0, __shfl_xor_sync(0xffffffffu, tm0, 1));
        tm0 = fmaxf(tm0, __shfl_xor_sync(0xffffffffu, tm0, 2));
        tm1 = fmaxf(tm1, __shfl_xor_sync(0xffffffffu, tm1, 1));
        tm1 = fmaxf(tm1, __shfl_xor_sync(0xffffffffu, tm1, 2));
        const float mn0 = fmaxf(m0, tm0), mn1 = fmaxf(m1, tm1);
        const float f0 = __expf(m0 - mn0), f1 = __expf(m1 - mn1);

        float sum0 = 0.f, sum1 = 0.f;
#pragma unroll
        for (int nt = 0; nt < 8; nt++) {
            float e00 = __expf(acc_s[nt][0] * scale - mn0);
            float e01 = __expf(acc_s[nt][1] * scale - mn0);
            float e10 = __expf(acc_s[nt][2] * scale - mn1);
            float e11 = __expf(acc_s[nt][3] * scale - mn1);
            sum0 += e00 + e01;
            sum1 += e10 + e11;
            Ps[mrow * 68 + nt * 8 + 2 * tig]           = f2tf(e00);
            Ps[mrow * 68 + nt * 8 + 2 * tig + 1]       = f2tf(e01);
            Ps[(mrow + 8) * 68 + nt * 8 + 2 * tig]     = f2tf(e10);
            Ps[(mrow + 8) * 68 + nt * 8 + 2 * tig + 1] = f2tf(e11);
        }
        sum0 += __shfl_xor_sync(0xffffffffu, sum0, 1);
        sum0 += __shfl_xor_sync(0xffffffffu, sum0, 2);
        sum1 += __shfl_xor_sync(0xffffffffu, sum1, 1);
        sum1 += __shfl_xor_sync(0xffffffffu, sum1, 2);
        l0 = l0 * f0 + sum0;
        l1 = l1 * f1 + sum1;
        m0 = mn0; m1 = mn1;
#pragma unroll
        for (int nt = 0; nt < 8; nt++) {
            acc_o[nt][0] *= f0; acc_o[nt][1] *= f0;
            acc_o[nt][2] *= f1; acc_o[nt][3] *= f1;
        }
        __syncwarp();

        // O += P @ V
#pragma unroll
        for (int ks = 0; ks < 64; ks += 8) {
            unsigned a0 = Ps[mrow * 68 + ks + tig];
            unsigned a1 = Ps[(mrow + 8) * 68 + ks + tig];
            unsigned a2 = Ps[mrow * 68 + ks + tig + 4];
            unsigned a3 = Ps[(mrow + 8) * 68 + ks + tig + 4];
#pragma unroll
            for (int nt = 0; nt < 8; nt++) {
                unsigned b0 = Vs[(ks + tig) * 72 + nt * 8 + gid];
                unsigned b1 = Vs[(ks + tig + 4) * 72 + nt * 8 + gid];
                MMA_TF32(acc_o[nt], a0, a1, a2, a3, b0, b1);
            }
        }
    }

    // Epilogue: normalize and write to g_ao[(b*S + s)][n*64 + h]
    const int b = bn >> 4, n = bn & 15;
    const float inv0 = 1.f / l0, inv1 = 1.f / l1;
    float* C = AOg + ((size_t)(b * kS + s0 + mrow)) * kD + n * 64;
#pragma unroll
    for (int nt = 0; nt < 8; nt++) {
        float2 v0, v1;
        v0.x = acc_o[nt][0] * inv0; v0.y = acc_o[nt][1] * inv0;
        v1.x = acc_o[nt][2] * inv1; v1.y = acc_o[nt][3] * inv1;
        *(float2*)(C + nt * 8 + 2 * tig)            = v0;
        *(float2*)(C + (size_t)8 * kD + nt * 8 + 2 * tig) = v1;
    }
}

// ---------------------------------------------------------------------------
// Per-(b,s,n) softmax over head_dim=64, writes p, accumulates xsum.
// ---------------------------------------------------------------------------
__global__ __launch_bounds__(256) void softmax_hd(const float* __restrict__ h,
                                                  float* __restrict__ p,
                                                  float* __restrict__ xsum)
{
    const int bn = blockIdx.x;
    const int b = bn >> 4, n = bn & 15;
    const int warp = threadIdx.x >> 5, lane = threadIdx.x & 31;
    __shared__ float sxs[64];
    if (threadIdx.x < 64) sxs[threadIdx.x] = 0.f;
    __syncthreads();
    float acc0 = 0.f, acc1 = 0.f;
#pragma unroll
    for (int i = 0; i < 8; i++) {
        const int s = blockIdx.y * 64 + warp * 8 + i;
        const float* row = h + (size_t)(b * kS + s) * kD + n * kH;
        float v0 = row[lane], v1 = row[lane + 32];
        float m = fmaxf(v0, v1);
#pragma unroll
        for (int off = 16; off; off >>= 1)
            m = fmaxf(m, __shfl_xor_sync(0xffffffffu, m, off));
        float e0 = __expf(v0 - m), e1 = __expf(v1 - m);
        float ssum = e0 + e1;
#pragma unroll
        for (int off = 16; off; off >>= 1)
            ssum += __shfl_xor_sync(0xffffffffu, ssum, off);
        const float inv = 1.f / ssum;
        e0 *= inv; e1 *= inv;
        float* prow = p + ((size_t)bn * kS + s) * kH;
        prow[lane] = e0; prow[lane + 32] = e1;
        acc0 += e0; acc1 += e1;
    }
    atomicAdd(&sxs[lane], acc0);
    atomicAdd(&sxs[lane + 32], acc1);
    __syncthreads();
    if (threadIdx.x < 64) atomicAdd(&xsum[bn * 64 + threadIdx.x], sxs[threadIdx.x]);
}

__global__ void zero_xsum(float* __restrict__ xsum)
{
    const int i = blockIdx.x * blockDim.x + threadIdx.x;
    if (i < kBN * kH) xsum[i] = 0.f;
}

// ---------------------------------------------------------------------------
// compute_t: t[bn][o][e] = sum_h W[o][n][e][h] * xsum[bn][h]
// Block per (n, 16 o's). xsum held in registers; pure streaming reads of W.
// Grid: 1024 blocks x 256 threads.
// ---------------------------------------------------------------------------
__global__ __launch_bounds__(256, 2) void compute_t3(const float* __restrict__ W,
                                                     const float* __restrict__ xsum,
                                                     float* __restrict__ t)
{
    const int n = blockIdx.x & 15, oc = blockIdx.x >> 4;
    __shared__ float xs[4][64];
    {
        const int bb = threadIdx.x >> 6, hh = threadIdx.x & 63;
        xs[bb][hh] = xsum[(bb * 16 + n) * 64 + hh];
    }
    __syncthreads();
    const int e = threadIdx.x >> 2, part = threadIdx.x & 3;
    float4 xr[4][4];
#pragma unroll
    for (int bb = 0; bb < 4; bb++)
#pragma unroll
        for (int j = 0; j < 4; j++)
            xr[bb][j] = *(const float4*)&xs[bb][part * 16 + j * 4];

#pragma unroll 4
    for (int oi = 0; oi < 16; oi++) {
        const int o = oc * 16 + oi;
        const float4* w =
            (const float4*)(W + (((size_t)o * 16 + n) * 64 + e) * 64 + part * 16);
        const float4 w0 = w[0], w1 = w[1], w2 = w[2], w3 = w[3];
        float r[4];
#pragma unroll
        for (int bb = 0; bb < 4; bb++) {
            r[bb] = w0.x * xr[bb][0].x + w0.y * xr[bb][0].y
                  + w0.z * xr[bb][0].z + w0.w * xr[bb][0].w
                  + w1.x * xr[bb][1].x + w1.y * xr[bb][1].y
                  + w1.z * xr[bb][1].z + w1.w * xr[bb][1].w
                  + w2.x * xr[bb][2].x + w2.y * xr[bb][2].y
                  + w2.z * xr[bb][2].z + w2.w * xr[bb][2].w
                  + w3.x * xr[bb][3].x + w3.y * xr[bb][3].y
                  + w3.z * xr[bb][3].z + w3.w * xr[bb][3].w;
        }
#pragma unroll
        for (int bb = 0; bb < 4; bb++) {
            r[bb] += __shfl_xor_sync(0xffffffffu, r[bb], 1);
            r[bb] += __shfl_xor_sync(0xffffffffu, r[bb], 2);
        }
        t[(((size_t)(part * 16 + n)) * kS + o) * kH + e] = r[part];
    }
}

// ---------------------------------------------------------------------------
extern "C" void kernel_launch(void* const* d_in, const int* in_sizes, int n_in,
                              void* d_out, int out_size)
{
    (void)in_sizes; (void)n_in; (void)out_size;
    const float* x      = (const float*)d_in[0];
    const float* attn_w = (const float*)d_in[1];
    const float* w_in   = (const float*)d_in[2];
    const float* b_in   = (const float*)d_in[3];
    const float* w_out  = (const float*)d_in[4];
    const float* b_out  = (const float*)d_in[5];
    float* out = (float*)d_out;

    float *ph, *pp, *pxs, *pt, *pao;
    cudaGetSymbolAddress((void**)&ph,  g_h);
    cudaGetSymbolAddress((void**)&pp,  g_p);
    cudaGetSymbolAddress((void**)&pxs, g_xsum);
    cudaGetSymbolAddress((void**)&pt,  g_t);
    cudaGetSymbolAddress((void**)&pao, g_ao);

    cudaFuncSetAttribute(flash_attn, cudaFuncAttributeMaxDynamicSharedMemorySize,
                         FL_SMEM_WORDS * 4);

    // 1) h = x @ w_in^T + b_in              [4096 x 1024]
    gemm_tf32_nt<<<dim3(kD / 128, (kB * kS) / 128), 256>>>(
        x, w_in, b_in, ph, kD, kD, kD, kD, 1.f);

    // 2) zero xsum, softmax over head_dim + xsum accumulation
    zero_xsum<<<16, 256>>>(pxs);
    softmax_hd<<<dim3(kBN, kS / 64), 256>>>(ph, pp, pxs);

    // 3) t[bn][o][e] = sum_h W[o,n,e,h] * xsum[bn][h]
    compute_t3<<<1024, 256>>>(attn_w, pxs, pt);

    // 4-6) fused flash attention -> g_ao in [b*s][d] layout
    flash_attn<<<dim3(kS / 128, kBN), 256, FL_SMEM_WORDS * 4>>>(pp, pt, pao);

    // 7) final = g_ao @ w_out^T + b_out
    gemm_tf32_nt<<<dim3(kD / 128, (kB * kS) / 128), 256>>>(
        pao, w_out, b_out, out, kD, kD, kD, kD, 1.f);
}

// round 4
// speedup vs baseline: 2.8402x; 1.0959x over previous
#include <cuda_runtime.h>
#include <math.h>

// Problem constants
#define kB 4
#define kS 1024
#define kD 1024
#define kN 16
#define kH 64
#define kBN 64  // kB * kN

// Scratch (device globals: allocation-free rule)
__device__ float g_p[(size_t)kBN * kS * kH];       // 16 MB
__device__ float g_xsum[kBN * kH];                 // 16 KB
__device__ float g_t[(size_t)kBN * kS * kH];       // 16 MB
__device__ float g_ao[(size_t)kB * kS * kD];       // 16 MB

// ---------------------------------------------------------------------------
// MMA: raw fp32 bits fed as tf32 (HW truncates mantissa; no cvt needed)
// ---------------------------------------------------------------------------
#define MMA_TF32(ac, a0, a1, a2, a3, b0, b1)                                   \
    asm volatile(                                                              \
        "mma.sync.aligned.m16n8k8.row.col.f32.tf32.tf32.f32 "                  \
        "{%0,%1,%2,%3}, {%4,%5,%6,%7}, {%8,%9}, {%0,%1,%2,%3};"                \
        : "+f"((ac)[0]), "+f"((ac)[1]), "+f"((ac)[2]), "+f"((ac)[3])           \
        : "r"(a0), "r"(a1), "r"(a2), "r"(a3), "r"(b0), "r"(b1))

__device__ __forceinline__ unsigned fbits(float f) { return __float_as_uint(f); }

__device__ __forceinline__ void cp16(unsigned saddr, const void* gaddr) {
    asm volatile("cp.async.cg.shared.global [%0], [%1], 16;"
                 :: "r"(saddr), "l"(gaddr));
}
#define CP_COMMIT() asm volatile("cp.async.commit_group;")
#define CP_WAIT(n)  asm volatile("cp.async.wait_group %0;" :: "n"(n))

// ---------------------------------------------------------------------------
// Double-buffered TF32 NT GEMM: C[M,N] = alpha * A[M,K] @ B[N,K]^T (+ bias)
// 128x128x32 tiles, cp.async 2-stage. If FUSE: epilogue does per-head
// softmax over 64-col chunks, writes p[bn][s][h], accumulates xsum.
// Grid: (N/128, M/128). 256 threads, 8 warps of 32x64.
// Dynamic smem: 2*128*36*2 floats (+128 for sxs).
// ---------------------------------------------------------------------------
#define G2_STAGE (128 * 36)
#define G2_SMEM_WORDS (4 * G2_STAGE + 128)

template <bool FUSE>
__global__ __launch_bounds__(256, 2) void gemm2(
    const float* __restrict__ A, const float* __restrict__ B,
    const float* __restrict__ bias, float* __restrict__ C,
    int K, int lda, int ldb, int ldc, float alpha, float* __restrict__ xsum)
{
    extern __shared__ float smx[];
    float* sA  = smx;                    // [2][128][36]
    float* sB  = smx + 2 * G2_STAGE;     // [2][128][36]
    float* sxs = smx + 4 * G2_STAGE;     // [2][64] (FUSE only)

    const int tid  = threadIdx.x;
    const int lane = tid & 31, wid = tid >> 5;
    const int warpRow = wid & 3, warpCol = wid >> 2;
    const int gid = lane >> 2, tig = lane & 3;
    const int row0 = blockIdx.y * 128, col0 = blockIdx.x * 128;

    if (FUSE && tid < 128) sxs[tid] = 0.f;

    // Loader: each thread copies 4 x 16B for A and for B per stage.
    const int lrow  = tid >> 1;
    const int lhalf = (tid & 1) * 16;  // float offset within 32-float row
    const float* Asrc = A + (size_t)(row0 + lrow) * lda + lhalf;
    const float* Bsrc = B + (size_t)(col0 + lrow) * ldb + lhalf;
    const unsigned aBase =
        (unsigned)__cvta_generic_to_shared(&sA[lrow * 36 + lhalf]);
    const unsigned bBase =
        (unsigned)__cvta_generic_to_shared(&sB[lrow * 36 + lhalf]);

    float acc[2][8][4];
#pragma unroll
    for (int i = 0; i < 2; i++)
#pragma unroll
        for (int j = 0; j < 8; j++)
#pragma unroll
            for (int k = 0; k < 4; k++) acc[i][j][k] = 0.f;

    const int nIter = K / 32;

    // Prologue: stage 0
#pragma unroll
    for (int j = 0; j < 4; j++) {
        cp16(aBase + j * 16, Asrc + j * 4);
        cp16(bBase + j * 16, Bsrc + j * 4);
    }
    CP_COMMIT();

    for (int it = 0; it < nIter; it++) {
        const int buf = it & 1;
        if (it + 1 < nIter) {
            const unsigned off = (buf ^ 1) * (G2_STAGE * 4);
            const int k0 = (it + 1) * 32;
#pragma unroll
            for (int j = 0; j < 4; j++) {
                cp16(aBase + off + j * 16, Asrc + k0 + j * 4);
                cp16(bBase + off + j * 16, Bsrc + k0 + j * 4);
            }
            CP_COMMIT();
            CP_WAIT(1);
        } else {
            CP_WAIT(0);
        }
        __syncthreads();

        const float* Ab = sA + buf * G2_STAGE;
        const float* Bb = sB + buf * G2_STAGE;
#pragma unroll
        for (int ks = 0; ks < 32; ks += 8) {
            unsigned af[2][4], bf[8][2];
#pragma unroll
            for (int mt = 0; mt < 2; mt++) {
                const int m = warpRow * 32 + mt * 16 + gid;
                af[mt][0] = fbits(Ab[m * 36 + ks + tig]);
                af[mt][1] = fbits(Ab[(m + 8) * 36 + ks + tig]);
                af[mt][2] = fbits(Ab[m * 36 + ks + tig + 4]);
                af[mt][3] = fbits(Ab[(m + 8) * 36 + ks + tig + 4]);
            }
#pragma unroll
            for (int nt = 0; nt < 8; nt++) {
                const int n = warpCol * 64 + nt * 8 + gid;
                bf[nt][0] = fbits(Bb[n * 36 + ks + tig]);
                bf[nt][1] = fbits(Bb[n * 36 + ks + tig + 4]);
            }
#pragma unroll
            for (int mt = 0; mt < 2; mt++)
#pragma unroll
                for (int nt = 0; nt < 8; nt++)
                    MMA_TF32(acc[mt][nt], af[mt][0], af[mt][1], af[mt][2],
                             af[mt][3], bf[nt][0], bf[nt][1]);
        }
        __syncthreads();
    }

    if (!FUSE) {
#pragma unroll
        for (int mt = 0; mt < 2; mt++) {
#pragma unroll
            for (int nt = 0; nt < 8; nt++) {
                const int row = row0 + warpRow * 32 + mt * 16 + gid;
                const int col = col0 + warpCol * 64 + nt * 8 + 2 * tig;
                float bb0 = 0.f, bb1 = 0.f;
                if (bias) { bb0 = bias[col]; bb1 = bias[col + 1]; }
                float2 v0, v1;
                v0.x = acc[mt][nt][0] * alpha + bb0;
                v0.y = acc[mt][nt][1] * alpha + bb1;
                v1.x = acc[mt][nt][2] * alpha + bb0;
                v1.y = acc[mt][nt][3] * alpha + bb1;
                *(float2*)(C + (size_t)row * ldc + col)       = v0;
                *(float2*)(C + (size_t)(row + 8) * ldc + col) = v1;
            }
        }
    } else {
        // Softmax over the 64-wide head chunk owned by this warp's quad.
        const int head = blockIdx.x * 2 + warpCol;
        const int b    = blockIdx.y >> 3;  // 8 row-blocks per batch
        const int bn   = b * 16 + head;
        // add bias in place
#pragma unroll
        for (int mt = 0; mt < 2; mt++)
#pragma unroll
            for (int nt = 0; nt < 8; nt++) {
                const int col = col0 + warpCol * 64 + nt * 8 + 2 * tig;
                acc[mt][nt][0] += bias[col];
                acc[mt][nt][1] += bias[col + 1];
                acc[mt][nt][2] += bias[col];
                acc[mt][nt][3] += bias[col + 1];
            }
        float xacc[8][2];
#pragma unroll
        for (int nt = 0; nt < 8; nt++) { xacc[nt][0] = 0.f; xacc[nt][1] = 0.f; }

#pragma unroll
        for (int mt = 0; mt < 2; mt++) {
#pragma unroll
            for (int half = 0; half < 2; half++) {
                // row = row0 + warpRow*32 + mt*16 + gid + half*8
                float mx = -1e30f;
#pragma unroll
                for (int nt = 0; nt < 8; nt++)
                    mx = fmaxf(mx, fmaxf(acc[mt][nt][half * 2],
                                         acc[mt][nt][half * 2 + 1]));
                mx = fmaxf(mx, __shfl_xor_sync(0xffffffffu, mx, 1));
                mx = fmaxf(mx, __shfl_xor_sync(0xffffffffu, mx, 2));
                float sum = 0.f;
#pragma unroll
                for (int nt = 0; nt < 8; nt++) {
                    float e0 = __expf(acc[mt][nt][half * 2]     - mx);
                    float e1 = __expf(acc[mt][nt][half * 2 + 1] - mx);
                    acc[mt][nt][half * 2]     = e0;
                    acc[mt][nt][half * 2 + 1] = e1;
                    sum += e0 + e1;
                }
                sum += __shfl_xor_sync(0xffffffffu, sum, 1);
                sum += __shfl_xor_sync(0xffffffffu, sum, 2);
                const float inv = 1.f / sum;
                const int s = (row0 & 1023) + warpRow * 32 + mt * 16 + gid + half * 8;
                float* prow = C + ((size_t)bn * kS + s) * kH;
#pragma unroll
                for (int nt = 0; nt < 8; nt++) {
                    float p0 = acc[mt][nt][half * 2]     * inv;
                    float p1 = acc[mt][nt][half * 2 + 1] * inv;
                    float2 v; v.x = p0; v.y = p1;
                    *(float2*)(prow + nt * 8 + 2 * tig) = v;
                    xacc[nt][0] += p0;
                    xacc[nt][1] += p1;
                }
            }
        }
        // Accumulate xsum: smem then one global atomic per entry.
#pragma unroll
        for (int nt = 0; nt < 8; nt++) {
            atomicAdd(&sxs[warpCol * 64 + nt * 8 + 2 * tig],     xacc[nt][0]);
            atomicAdd(&sxs[warpCol * 64 + nt * 8 + 2 * tig + 1], xacc[nt][1]);
        }
        __syncthreads();
        if (tid < 128) {
            const int hh = tid & 63, hd = tid >> 6;
            atomicAdd(&xsum[(b * 16 + blockIdx.x * 2 + hd) * 64 + hh], sxs[tid]);
        }
    }
}

// ---------------------------------------------------------------------------
// Fused flash attention over o-dim (Q=p, K=t, V=p), raw-bits tf32 MMA.
// Grid: (kS/128, kBN). 256 threads = 8 warps x 16 rows.
// ---------------------------------------------------------------------------
#define FL_SMEM_WORDS (128 * 68 + 64 * 68 + 64 * 72 + 128 * 68)
__global__ __launch_bounds__(256, 2) void flash_attn(
    const float* __restrict__ Pg, const float* __restrict__ Tg,
    float* __restrict__ AOg)
{
    extern __shared__ float sm[];
    float* Qs = sm;                      // [128][68]
    float* Ks = Qs + 128 * 68;           // [64][68]
    float* Vs = Ks + 64 * 68;            // [64][72]
    float* Ps = Vs + 64 * 72;            // [128][68]

    const int bn = blockIdx.y;
    const int s0 = blockIdx.x * 128;
    const float* Pp = Pg + (size_t)bn * kS * kH;
    const float* Tp = Tg + (size_t)bn * kS * kH;

    const int tid = threadIdx.x, lane = tid & 31, wid = tid >> 5;
    const int gid = lane >> 2, tig = lane & 3;
    const int mrow = wid * 16 + gid;

    // Load Q tile (resident)
    for (int i = tid; i < 128 * 16; i += 256) {
        const int r = i >> 4, c = (i & 15) * 4;
        float4 v = *(const float4*)(Pp + (size_t)(s0 + r) * kH + c);
        *(float4*)(Qs + r * 68 + c) = v;
    }

    float m0 = -1e30f, m1 = -1e30f, l0 = 0.f, l1 = 0.f;
    float acc_o[8][4];
#pragma unroll
    for (int j = 0; j < 8; j++)
#pragma unroll
        for (int k = 0; k < 4; k++) acc_o[j][k] = 0.f;

    const float scale = 1.f / 2048.f;

    for (int o0 = 0; o0 < kS; o0 += 64) {
        __syncthreads();
        for (int i = tid; i < 64 * 16; i += 256) {
            const int r = i >> 4, c = (i & 15) * 4;
            float4 kv = *(const float4*)(Tp + (size_t)(o0 + r) * kH + c);
            float4 vv = *(const float4*)(Pp + (size_t)(o0 + r) * kH + c);
            *(float4*)(Ks + r * 68 + c) = kv;
            *(float4*)(Vs + r * 72 + c) = vv;
        }
        __syncthreads();

        // S = Q @ K^T
        float acc_s[8][4];
#pragma unroll
        for (int j = 0; j < 8; j++)
#pragma unroll
            for (int k = 0; k < 4; k++) acc_s[j][k] = 0.f;

#pragma unroll
        for (int ks = 0; ks < 64; ks += 8) {
            unsigned a0 = fbits(Qs[mrow * 68 + ks + tig]);
            unsigned a1 = fbits(Qs[(mrow + 8) * 68 + ks + tig]);
            unsigned a2 = fbits(Qs[mrow * 68 + ks + tig + 4]);
            unsigned a3 = fbits(Qs[(mrow + 8) * 68 + ks + tig + 4]);
#pragma unroll
            for (int nt = 0; nt < 8; nt++) {
                unsigned b0 = fbits(Ks[(nt * 8 + gid) * 68 + ks + tig]);
                unsigned b1 = fbits(Ks[(nt * 8 + gid) * 68 + ks + tig + 4]);
                MMA_TF32(acc_s[nt], a0, a1, a2, a3, b0, b1);
            }
        }

        // Online softmax
        float tm0 = -1e30f, tm1 = -1e30f;
#pragma unroll
        for (int nt = 0; nt < 8; nt++) {
            tm0 = fmaxf(tm0, fmaxf(acc_s[nt][0], acc_s[nt][1]));
            tm1 = fmaxf(tm1, fmaxf(acc_s[nt][2], acc_s[nt][3]));
        }
        tm0 *= scale; tm1 *= scale;
        tm0 = fmaxf(tm0, __shfl_xor_sync(0xffffffffu, tm0, 1));
        tm0 = fmaxf(tm0, __shfl_xor_sync(0xffffffffu, tm0, 2));
        tm1 = fmaxf(tm1, __shfl_xor_sync(0xffffffffu, tm1, 1));
        tm1 = fmaxf(tm1, __shfl_xor_sync(0xffffffffu, tm1, 2));
        const float mn0 = fmaxf(m0, tm0), mn1 = fmaxf(m1, tm1);
        const float f0 = __expf(m0 - mn0), f1 = __expf(m1 - mn1);

        float sum0 = 0.f, sum1 = 0.f;
#pragma unroll
        for (int nt = 0; nt < 8; nt++) {
            float e00 = __expf(acc_s[nt][0] * scale - mn0);
            float e01 = __expf(acc_s[nt][1] * scale - mn0);
            float e10 = __expf(acc_s[nt][2] * scale - mn1);
            float e11 = __expf(acc_s[nt][3] * scale - mn1);
            sum0 += e00 + e01;
            sum1 += e10 + e11;
            Ps[mrow * 68 + nt * 8 + 2 * tig]           = e00;
            Ps[mrow * 68 + nt * 8 + 2 * tig + 1]       = e01;
            Ps[(mrow + 8) * 68 + nt * 8 + 2 * tig]     = e10;
            Ps[(mrow + 8) * 68 + nt * 8 + 2 * tig + 1] = e11;
        }
        sum0 += __shfl_xor_sync(0xffffffffu, sum0, 1);
        sum0 += __shfl_xor_sync(0xffffffffu, sum0, 2);
        sum1 += __shfl_xor_sync(0xffffffffu, sum1, 1);
        sum1 += __shfl_xor_sync(0xffffffffu, sum1, 2);
        l0 = l0 * f0 + sum0;
        l1 = l1 * f1 + sum1;
        m0 = mn0; m1 = mn1;
#pragma unroll
        for (int nt = 0; nt < 8; nt++) {
            acc_o[nt][0] *= f0; acc_o[nt][1] *= f0;
            acc_o[nt][2] *= f1; acc_o[nt][3] *= f1;
        }
        __syncwarp();

        // O += P @ V
#pragma unroll
        for (int ks = 0; ks < 64; ks += 8) {
            unsigned a0 = fbits(Ps[mrow * 68 + ks + tig]);
            unsigned a1 = fbits(Ps[(mrow + 8) * 68 + ks + tig]);
            unsigned a2 = fbits(Ps[mrow * 68 + ks + tig + 4]);
            unsigned a3 = fbits(Ps[(mrow + 8) * 68 + ks + tig + 4]);
#pragma unroll
            for (int nt = 0; nt < 8; nt++) {
                unsigned b0 = fbits(Vs[(ks + tig) * 72 + nt * 8 + gid]);
                unsigned b1 = fbits(Vs[(ks + tig + 4) * 72 + nt * 8 + gid]);
                MMA_TF32(acc_o[nt], a0, a1, a2, a3, b0, b1);
            }
        }
    }

    // Epilogue
    const int b = bn >> 4, n = bn & 15;
    const float inv0 = 1.f / l0, inv1 = 1.f / l1;
    float* C = AOg + ((size_t)(b * kS + s0 + mrow)) * kD + n * 64;
#pragma unroll
    for (int nt = 0; nt < 8; nt++) {
        float2 v0, v1;
        v0.x = acc_o[nt][0] * inv0; v0.y = acc_o[nt][1] * inv0;
        v1.x = acc_o[nt][2] * inv1; v1.y = acc_o[nt][3] * inv1;
        *(float2*)(C + nt * 8 + 2 * tig)                  = v0;
        *(float2*)(C + (size_t)8 * kD + nt * 8 + 2 * tig) = v1;
    }
}

__global__ void zero_xsum(float* __restrict__ xsum)
{
    const int i = blockIdx.x * blockDim.x + threadIdx.x;
    if (i < kBN * kH) xsum[i] = 0.f;
}

// ---------------------------------------------------------------------------
// compute_t: t[bn][o][e] = sum_h W[o][n][e][h] * xsum[bn][h]
// Block per (n, 8 o's). xsum in registers; streaming W reads. Grid: 2048.
// ---------------------------------------------------------------------------
__global__ __launch_bounds__(256, 2) void compute_t4(const float* __restrict__ W,
                                                     const float* __restrict__ xsum,
                                                     float* __restrict__ t)
{
    const int n = blockIdx.x & 15, oc = blockIdx.x >> 4;
    __shared__ float xs[4][64];
    {
        const int bb = threadIdx.x >> 6, hh = threadIdx.x & 63;
        xs[bb][hh] = xsum[(bb * 16 + n) * 64 + hh];
    }
    __syncthreads();
    const int e = threadIdx.x >> 2, part = threadIdx.x & 3;
    float4 xr[4][4];
#pragma unroll
    for (int bb = 0; bb < 4; bb++)
#pragma unroll
        for (int j = 0; j < 4; j++)
            xr[bb][j] = *(const float4*)&xs[bb][part * 16 + j * 4];

#pragma unroll
    for (int oi = 0; oi < 8; oi++) {
        const int o = oc * 8 + oi;
        const float4* w =
            (const float4*)(W + (((size_t)o * 16 + n) * 64 + e) * 64 + part * 16);
        const float4 w0 = w[0], w1 = w[1], w2 = w[2], w3 = w[3];
        float r[4];
#pragma unroll
        for (int bb = 0; bb < 4; bb++) {
            r[bb] = w0.x * xr[bb][0].x + w0.y * xr[bb][0].y
                  + w0.z * xr[bb][0].z + w0.w * xr[bb][0].w
                  + w1.x * xr[bb][1].x + w1.y * xr[bb][1].y
                  + w1.z * xr[bb][1].z + w1.w * xr[bb][1].w
                  + w2.x * xr[bb][2].x + w2.y * xr[bb][2].y
                  + w2.z * xr[bb][2].z + w2.w * xr[bb][2].w
                  + w3.x * xr[bb][3].x + w3.y * xr[bb][3].y
                  + w3.z * xr[bb][3].z + w3.w * xr[bb][3].w;
        }
#pragma unroll
        for (int bb = 0; bb < 4; bb++) {
            r[bb] += __shfl_xor_sync(0xffffffffu, r[bb], 1);
            r[bb] += __shfl_xor_sync(0xffffffffu, r[bb], 2);
        }
        t[(((size_t)(part * 16 + n)) * kS + o) * kH + e] = r[part];
    }
}

// ---------------------------------------------------------------------------
extern "C" void kernel_launch(void* const* d_in, const int* in_sizes, int n_in,
                              void* d_out, int out_size)
{
    (void)in_sizes; (void)n_in; (void)out_size;
    const float* x      = (const float*)d_in[0];
    const float* attn_w = (const float*)d_in[1];
    const float* w_in   = (const float*)d_in[2];
    const float* b_in   = (const float*)d_in[3];
    const float* w_out  = (const float*)d_in[4];
    const float* b_out  = (const float*)d_in[5];
    float* out = (float*)d_out;

    float *pp, *pxs, *pt, *pao;
    cudaGetSymbolAddress((void**)&pp,  g_p);
    cudaGetSymbolAddress((void**)&pxs, g_xsum);
    cudaGetSymbolAddress((void**)&pt,  g_t);
    cudaGetSymbolAddress((void**)&pao, g_ao);

    cudaFuncSetAttribute(gemm2<true>,  cudaFuncAttributeMaxDynamicSharedMemorySize,
                         G2_SMEM_WORDS * 4);
    cudaFuncSetAttribute(gemm2<false>, cudaFuncAttributeMaxDynamicSharedMemorySize,
                         G2_SMEM_WORDS * 4);
    cudaFuncSetAttribute(flash_attn, cudaFuncAttributeMaxDynamicSharedMemorySize,
                         FL_SMEM_WORDS * 4);

    // 0) zero xsum
    zero_xsum<<<16, 256>>>(pxs);

    // 1+2) h = x @ w_in^T + b_in, fused per-head softmax -> p, xsum
    gemm2<true><<<dim3(kD / 128, (kB * kS) / 128), 256, G2_SMEM_WORDS * 4>>>(
        x, w_in, b_in, pp, kD, kD, kD, kD, 1.f, pxs);

    // 3) t[bn][o][e] = sum_h W[o,n,e,h] * xsum[bn][h]
    compute_t4<<<2048, 256>>>(attn_w, pxs, pt);

    // 4-6) fused flash attention -> g_ao in [b*s][d] layout
    flash_attn<<<dim3(kS / 128, kBN), 256, FL_SMEM_WORDS * 4>>>(pp, pt, pao);

    // 7) final = g_ao @ w_out^T + b_out
    gemm2<false><<<dim3(kD / 128, (kB * kS) / 128), 256, G2_SMEM_WORDS * 4>>>(
        pao, w_out, b_out, out, kD, kD, kD, kD, 1.f, nullptr);
}

// round 5
// speedup vs baseline: 2.8831x; 1.0151x over previous
#include <cuda_runtime.h>
#include <math.h>

// Problem constants
#define kB 4
#define kS 1024
#define kD 1024
#define kN 16
#define kH 64
#define kBN 64  // kB * kN

// Scratch (device globals: allocation-free rule)
__device__ float g_p[(size_t)kBN * kS * kH];       // 16 MB
__device__ float g_xsum[kBN * kH];                 // 16 KB
__device__ float g_t[(size_t)kBN * kS * kH];       // 16 MB
__device__ float g_ao[(size_t)kB * kS * kD];       // 16 MB

// ---------------------------------------------------------------------------
// MMA: raw fp32 bits fed as tf32 (HW truncates mantissa; no cvt needed)
// ---------------------------------------------------------------------------
#define MMA_TF32(ac, a0, a1, a2, a3, b0, b1)                                   \
    asm volatile(                                                              \
        "mma.sync.aligned.m16n8k8.row.col.f32.tf32.tf32.f32 "                  \
        "{%0,%1,%2,%3}, {%4,%5,%6,%7}, {%8,%9}, {%0,%1,%2,%3};"                \
        : "+f"((ac)[0]), "+f"((ac)[1]), "+f"((ac)[2]), "+f"((ac)[3])           \
        : "r"(a0), "r"(a1), "r"(a2), "r"(a3), "r"(b0), "r"(b1))

__device__ __forceinline__ unsigned fbits(float f) { return __float_as_uint(f); }

__device__ __forceinline__ void cp16(unsigned saddr, const void* gaddr) {
    asm volatile("cp.async.cg.shared.global [%0], [%1], 16;"
                 :: "r"(saddr), "l"(gaddr));
}
#define CP_COMMIT() asm volatile("cp.async.commit_group;")
#define CP_WAIT(n)  asm volatile("cp.async.wait_group %0;" :: "n"(n))

// ---------------------------------------------------------------------------
// Double-buffered TF32 NT GEMM: C[M,N] = alpha * A[M,K] @ B[N,K]^T (+ bias)
// 128x128x32 tiles, cp.async 2-stage. If FUSE: epilogue does per-head
// softmax over 64-col chunks, writes p[bn][s][h], accumulates xsum.
// ---------------------------------------------------------------------------
#define G2_STAGE (128 * 36)
#define G2_SMEM_WORDS (4 * G2_STAGE + 128)

template <bool FUSE>
__global__ __launch_bounds__(256, 2) void gemm2(
    const float* __restrict__ A, const float* __restrict__ B,
    const float* __restrict__ bias, float* __restrict__ C,
    int K, int lda, int ldb, int ldc, float alpha, float* __restrict__ xsum)
{
    extern __shared__ float smx[];
    float* sA  = smx;                    // [2][128][36]
    float* sB  = smx + 2 * G2_STAGE;     // [2][128][36]
    float* sxs = smx + 4 * G2_STAGE;     // [128] (FUSE only)

    const int tid  = threadIdx.x;
    const int lane = tid & 31, wid = tid >> 5;
    const int warpRow = wid & 3, warpCol = wid >> 2;
    const int gid = lane >> 2, tig = lane & 3;
    const int row0 = blockIdx.y * 128, col0 = blockIdx.x * 128;

    if (FUSE && tid < 128) sxs[tid] = 0.f;

    const int lrow  = tid >> 1;
    const int lhalf = (tid & 1) * 16;
    const float* Asrc = A + (size_t)(row0 + lrow) * lda + lhalf;
    const float* Bsrc = B + (size_t)(col0 + lrow) * ldb + lhalf;
    const unsigned aBase =
        (unsigned)__cvta_generic_to_shared(&sA[lrow * 36 + lhalf]);
    const unsigned bBase =
        (unsigned)__cvta_generic_to_shared(&sB[lrow * 36 + lhalf]);

    float acc[2][8][4];
#pragma unroll
    for (int i = 0; i < 2; i++)
#pragma unroll
        for (int j = 0; j < 8; j++)
#pragma unroll
            for (int k = 0; k < 4; k++) acc[i][j][k] = 0.f;

    const int nIter = K / 32;

#pragma unroll
    for (int j = 0; j < 4; j++) {
        cp16(aBase + j * 16, Asrc + j * 4);
        cp16(bBase + j * 16, Bsrc + j * 4);
    }
    CP_COMMIT();

    for (int it = 0; it < nIter; it++) {
        const int buf = it & 1;
        if (it + 1 < nIter) {
            const unsigned off = (buf ^ 1) * (G2_STAGE * 4);
            const int k0 = (it + 1) * 32;
#pragma unroll
            for (int j = 0; j < 4; j++) {
                cp16(aBase + off + j * 16, Asrc + k0 + j * 4);
                cp16(bBase + off + j * 16, Bsrc + k0 + j * 4);
            }
            CP_COMMIT();
            CP_WAIT(1);
        } else {
            CP_WAIT(0);
        }
        __syncthreads();

        const float* Ab = sA + buf * G2_STAGE;
        const float* Bb = sB + buf * G2_STAGE;
#pragma unroll
        for (int ks = 0; ks < 32; ks += 8) {
            unsigned af[2][4], bf[8][2];
#pragma unroll
            for (int mt = 0; mt < 2; mt++) {
                const int m = warpRow * 32 + mt * 16 + gid;
                af[mt][0] = fbits(Ab[m * 36 + ks + tig]);
                af[mt][1] = fbits(Ab[(m + 8) * 36 + ks + tig]);
                af[mt][2] = fbits(Ab[m * 36 + ks + tig + 4]);
                af[mt][3] = fbits(Ab[(m + 8) * 36 + ks + tig + 4]);
            }
#pragma unroll
            for (int nt = 0; nt < 8; nt++) {
                const int n = warpCol * 64 + nt * 8 + gid;
                bf[nt][0] = fbits(Bb[n * 36 + ks + tig]);
                bf[nt][1] = fbits(Bb[n * 36 + ks + tig + 4]);
            }
#pragma unroll
            for (int mt = 0; mt < 2; mt++)
#pragma unroll
                for (int nt = 0; nt < 8; nt++)
                    MMA_TF32(acc[mt][nt], af[mt][0], af[mt][1], af[mt][2],
                             af[mt][3], bf[nt][0], bf[nt][1]);
        }
        __syncthreads();
    }

    if (!FUSE) {
#pragma unroll
        for (int mt = 0; mt < 2; mt++) {
#pragma unroll
            for (int nt = 0; nt < 8; nt++) {
                const int row = row0 + warpRow * 32 + mt * 16 + gid;
                const int col = col0 + warpCol * 64 + nt * 8 + 2 * tig;
                float bb0 = 0.f, bb1 = 0.f;
                if (bias) { bb0 = bias[col]; bb1 = bias[col + 1]; }
                float2 v0, v1;
                v0.x = acc[mt][nt][0] * alpha + bb0;
                v0.y = acc[mt][nt][1] * alpha + bb1;
                v1.x = acc[mt][nt][2] * alpha + bb0;
                v1.y = acc[mt][nt][3] * alpha + bb1;
                *(float2*)(C + (size_t)row * ldc + col)       = v0;
                *(float2*)(C + (size_t)(row + 8) * ldc + col) = v1;
            }
        }
    } else {
        const int head = blockIdx.x * 2 + warpCol;
        const int b    = blockIdx.y >> 3;
        const int bn   = b * 16 + head;
#pragma unroll
        for (int mt = 0; mt < 2; mt++)
#pragma unroll
            for (int nt = 0; nt < 8; nt++) {
                const int col = col0 + warpCol * 64 + nt * 8 + 2 * tig;
                acc[mt][nt][0] += bias[col];
                acc[mt][nt][1] += bias[col + 1];
                acc[mt][nt][2] += bias[col];
                acc[mt][nt][3] += bias[col + 1];
            }
        float xacc[8][2];
#pragma unroll
        for (int nt = 0; nt < 8; nt++) { xacc[nt][0] = 0.f; xacc[nt][1] = 0.f; }

#pragma unroll
        for (int mt = 0; mt < 2; mt++) {
#pragma unroll
            for (int half = 0; half < 2; half++) {
                float mx = -1e30f;
#pragma unroll
                for (int nt = 0; nt < 8; nt++)
                    mx = fmaxf(mx, fmaxf(acc[mt][nt][half * 2],
                                         acc[mt][nt][half * 2 + 1]));
                mx = fmaxf(mx, __shfl_xor_sync(0xffffffffu, mx, 1));
                mx = fmaxf(mx, __shfl_xor_sync(0xffffffffu, mx, 2));
                float sum = 0.f;
#pragma unroll
                for (int nt = 0; nt < 8; nt++) {
                    float e0 = __expf(acc[mt][nt][half * 2]     - mx);
                    float e1 = __expf(acc[mt][nt][half * 2 + 1] - mx);
                    acc[mt][nt][half * 2]     = e0;
                    acc[mt][nt][half * 2 + 1] = e1;
                    sum += e0 + e1;
                }
                sum += __shfl_xor_sync(0xffffffffu, sum, 1);
                sum += __shfl_xor_sync(0xffffffffu, sum, 2);
                const float inv = 1.f / sum;
                const int s = (row0 & 1023) + warpRow * 32 + mt * 16 + gid + half * 8;
                float* prow = C + ((size_t)bn * kS + s) * kH;
#pragma unroll
                for (int nt = 0; nt < 8; nt++) {
                    float p0 = acc[mt][nt][half * 2]     * inv;
                    float p1 = acc[mt][nt][half * 2 + 1] * inv;
                    float2 v; v.x = p0; v.y = p1;
                    *(float2*)(prow + nt * 8 + 2 * tig) = v;
                    xacc[nt][0] += p0;
                    xacc[nt][1] += p1;
                }
            }
        }
#pragma unroll
        for (int nt = 0; nt < 8; nt++) {
            atomicAdd(&sxs[warpCol * 64 + nt * 8 + 2 * tig],     xacc[nt][0]);
            atomicAdd(&sxs[warpCol * 64 + nt * 8 + 2 * tig + 1], xacc[nt][1]);
        }
        __syncthreads();
        if (tid < 128) {
            const int hh = tid & 63, hd = tid >> 6;
            atomicAdd(&xsum[(b * 16 + blockIdx.x * 2 + hd) * 64 + hh], sxs[tid]);
        }
    }
}

// ---------------------------------------------------------------------------
// Fused flash attention over o-dim (Q=p, K=t, V=p).
// Structural bound: |scores| = |p.t|/2048 <= max|t|/2048 <= 0.005, so:
//   - no max subtraction needed (exp never overflows)
//   - expm1 via 3-term Taylor (exact to ~4e-9 at this magnitude)
//   - PV MMA runs on (e-1) [tiny values -> full tf32 relative precision];
//     the mean term sum_o V = xsum[bn] is added back exactly in fp32.
//   - l = 1024 + sum(e-1), reduced once in the epilogue.
// Grid: (kS/128, kBN). 256 threads = 8 warps x 16 rows.
// ---------------------------------------------------------------------------
#define FL_SMEM_WORDS (128 * 68 + 64 * 68 + 64 * 72 + 128 * 68)
__global__ __launch_bounds__(256, 2) void flash_attn(
    const float* __restrict__ Pg, const float* __restrict__ Tg,
    const float* __restrict__ Xs, float* __restrict__ AOg)
{
    extern __shared__ float sm[];
    float* Qs = sm;                      // [128][68]
    float* Ks = Qs + 128 * 68;           // [64][68]
    float* Vs = Ks + 64 * 68;            // [64][72]
    float* Ps = Vs + 64 * 72;            // [128][68]

    const int bn = blockIdx.y;
    const int s0 = blockIdx.x * 128;
    const float* Pp = Pg + (size_t)bn * kS * kH;
    const float* Tp = Tg + (size_t)bn * kS * kH;

    const int tid = threadIdx.x, lane = tid & 31, wid = tid >> 5;
    const int gid = lane >> 2, tig = lane & 3;
    const int mrow = wid * 16 + gid;

    // Load Q tile (resident)
    for (int i = tid; i < 128 * 16; i += 256) {
        const int r = i >> 4, c = (i & 15) * 4;
        float4 v = *(const float4*)(Pp + (size_t)(s0 + r) * kH + c);
        *(float4*)(Qs + r * 68 + c) = v;
    }

    float lsum0 = 0.f, lsum1 = 0.f;
    float acc_o[8][4];
#pragma unroll
    for (int j = 0; j < 8; j++)
#pragma unroll
        for (int k = 0; k < 4; k++) acc_o[j][k] = 0.f;

    const float scale = 1.f / 2048.f;
    const float c2 = 0.5f, c3 = 1.f / 6.f;

    for (int o0 = 0; o0 < kS; o0 += 64) {
        __syncthreads();
        for (int i = tid; i < 64 * 16; i += 256) {
            const int r = i >> 4, c = (i & 15) * 4;
            float4 kv = *(const float4*)(Tp + (size_t)(o0 + r) * kH + c);
            float4 vv = *(const float4*)(Pp + (size_t)(o0 + r) * kH + c);
            *(float4*)(Ks + r * 68 + c) = kv;
            *(float4*)(Vs + r * 72 + c) = vv;
        }
        __syncthreads();

        // S = Q @ K^T
        float acc_s[8][4];
#pragma unroll
        for (int j = 0; j < 8; j++)
#pragma unroll
            for (int k = 0; k < 4; k++) acc_s[j][k] = 0.f;

#pragma unroll
        for (int ks = 0; ks < 64; ks += 8) {
            unsigned a0 = fbits(Qs[mrow * 68 + ks + tig]);
            unsigned a1 = fbits(Qs[(mrow + 8) * 68 + ks + tig]);
            unsigned a2 = fbits(Qs[mrow * 68 + ks + tig + 4]);
            unsigned a3 = fbits(Qs[(mrow + 8) * 68 + ks + tig + 4]);
#pragma unroll
            for (int nt = 0; nt < 8; nt++) {
                unsigned b0 = fbits(Ks[(nt * 8 + gid) * 68 + ks + tig]);
                unsigned b1 = fbits(Ks[(nt * 8 + gid) * 68 + ks + tig + 4]);
                MMA_TF32(acc_s[nt], a0, a1, a2, a3, b0, b1);
            }
        }

        // e-1 = x + x^2*(1/2 + x/6), x = s/2048  (|x| <= ~0.005)
#pragma unroll
        for (int nt = 0; nt < 8; nt++) {
            float x00 = acc_s[nt][0] * scale;
            float x01 = acc_s[nt][1] * scale;
            float x10 = acc_s[nt][2] * scale;
            float x11 = acc_s[nt][3] * scale;
            float e00 = fmaf(x00 * x00, fmaf(x00, c3, c2), x00);
            float e01 = fmaf(x01 * x01, fmaf(x01, c3, c2), x01);
            float e10 = fmaf(x10 * x10, fmaf(x10, c3, c2), x10);
            float e11 = fmaf(x11 * x11, fmaf(x11, c3, c2), x11);
            lsum0 += e00 + e01;
            lsum1 += e10 + e11;
            Ps[mrow * 68 + nt * 8 + 2 * tig]           = e00;
            Ps[mrow * 68 + nt * 8 + 2 * tig + 1]       = e01;
            Ps[(mrow + 8) * 68 + nt * 8 + 2 * tig]     = e10;
            Ps[(mrow + 8) * 68 + nt * 8 + 2 * tig + 1] = e11;
        }
        __syncwarp();

        // O += (e-1) @ V
#pragma unroll
        for (int ks = 0; ks < 64; ks += 8) {
            unsigned a0 = fbits(Ps[mrow * 68 + ks + tig]);
            unsigned a1 = fbits(Ps[(mrow + 8) * 68 + ks + tig]);
            unsigned a2 = fbits(Ps[mrow * 68 + ks + tig + 4]);
            unsigned a3 = fbits(Ps[(mrow + 8) * 68 + ks + tig + 4]);
#pragma unroll
            for (int nt = 0; nt < 8; nt++) {
                unsigned b0 = fbits(Vs[(ks + tig) * 72 + nt * 8 + gid]);
                unsigned b1 = fbits(Vs[(ks + tig + 4) * 72 + nt * 8 + gid]);
                MMA_TF32(acc_o[nt], a0, a1, a2, a3, b0, b1);
            }
        }
    }

    // Epilogue: l = 1024 + sum(e-1); out = (acc_o + xsum) / l
    lsum0 += __shfl_xor_sync(0xffffffffu, lsum0, 1);
    lsum0 += __shfl_xor_sync(0xffffffffu, lsum0, 2);
    lsum1 += __shfl_xor_sync(0xffffffffu, lsum1, 1);
    lsum1 += __shfl_xor_sync(0xffffffffu, lsum1, 2);
    const float inv0 = 1.f / (1024.f + lsum0);
    const float inv1 = 1.f / (1024.f + lsum1);

    const int b = bn >> 4, n = bn & 15;
    const float* xv = Xs + bn * kH;
    float* C = AOg + ((size_t)(b * kS + s0 + mrow)) * kD + n * 64;
#pragma unroll
    for (int nt = 0; nt < 8; nt++) {
        const int col = nt * 8 + 2 * tig;
        const float x0 = xv[col], x1 = xv[col + 1];
        float2 v0, v1;
        v0.x = (acc_o[nt][0] + x0) * inv0; v0.y = (acc_o[nt][1] + x1) * inv0;
        v1.x = (acc_o[nt][2] + x0) * inv1; v1.y = (acc_o[nt][3] + x1) * inv1;
        *(float2*)(C + col)                  = v0;
        *(float2*)(C + (size_t)8 * kD + col) = v1;
    }
}

__global__ void zero_xsum(float* __restrict__ xsum)
{
    const int i = blockIdx.x * blockDim.x + threadIdx.x;
    if (i < kBN * kH) xsum[i] = 0.f;
}

// ---------------------------------------------------------------------------
// compute_t: t[bn][o][e] = sum_h W[o][n][e][h] * xsum[bn][h]
// Block per (n, 8 o's). xsum in registers; streaming W reads. Grid: 2048.
// ---------------------------------------------------------------------------
__global__ __launch_bounds__(256, 2) void compute_t4(const float* __restrict__ W,
                                                     const float* __restrict__ xsum,
                                                     float* __restrict__ t)
{
    const int n = blockIdx.x & 15, oc = blockIdx.x >> 4;
    __shared__ float xs[4][64];
    {
        const int bb = threadIdx.x >> 6, hh = threadIdx.x & 63;
        xs[bb][hh] = xsum[(bb * 16 + n) * 64 + hh];
    }
    __syncthreads();
    const int e = threadIdx.x >> 2, part = threadIdx.x & 3;
    float4 xr[4][4];
#pragma unroll
    for (int bb = 0; bb < 4; bb++)
#pragma unroll
        for (int j = 0; j < 4; j++)
            xr[bb][j] = *(const float4*)&xs[bb][part * 16 + j * 4];

#pragma unroll
    for (int oi = 0; oi < 8; oi++) {
        const int o = oc * 8 + oi;
        const float4* w =
            (const float4*)(W + (((size_t)o * 16 + n) * 64 + e) * 64 + part * 16);
        const float4 w0 = w[0], w1 = w[1], w2 = w[2], w3 = w[3];
        float r[4];
#pragma unroll
        for (int bb = 0; bb < 4; bb++) {
            r[bb] = w0.x * xr[bb][0].x + w0.y * xr[bb][0].y
                  + w0.z * xr[bb][0].z + w0.w * xr[bb][0].w
                  + w1.x * xr[bb][1].x + w1.y * xr[bb][1].y
                  + w1.z * xr[bb][1].z + w1.w * xr[bb][1].w
                  + w2.x * xr[bb][2].x + w2.y * xr[bb][2].y
                  + w2.z * xr[bb][2].z + w2.w * xr[bb][2].w
                  + w3.x * xr[bb][3].x + w3.y * xr[bb][3].y
                  + w3.z * xr[bb][3].z + w3.w * xr[bb][3].w;
        }
#pragma unroll
        for (int bb = 0; bb < 4; bb++) {
            r[bb] += __shfl_xor_sync(0xffffffffu, r[bb], 1);
            r[bb] += __shfl_xor_sync(0xffffffffu, r[bb], 2);
        }
        t[(((size_t)(part * 16 + n)) * kS + o) * kH + e] = r[part];
    }
}

// ---------------------------------------------------------------------------
extern "C" void kernel_launch(void* const* d_in, const int* in_sizes, int n_in,
                              void* d_out, int out_size)
{
    (void)in_sizes; (void)n_in; (void)out_size;
    const float* x      = (const float*)d_in[0];
    const float* attn_w = (const float*)d_in[1];
    const float* w_in   = (const float*)d_in[2];
    const float* b_in   = (const float*)d_in[3];
    const float* w_out  = (const float*)d_in[4];
    const float* b_out  = (const float*)d_in[5];
    float* out = (float*)d_out;

    float *pp, *pxs, *pt, *pao;
    cudaGetSymbolAddress((void**)&pp,  g_p);
    cudaGetSymbolAddress((void**)&pxs, g_xsum);
    cudaGetSymbolAddress((void**)&pt,  g_t);
    cudaGetSymbolAddress((void**)&pao, g_ao);

    cudaFuncSetAttribute(gemm2<true>,  cudaFuncAttributeMaxDynamicSharedMemorySize,
                         G2_SMEM_WORDS * 4);
    cudaFuncSetAttribute(gemm2<false>, cudaFuncAttributeMaxDynamicSharedMemorySize,
                         G2_SMEM_WORDS * 4);
    cudaFuncSetAttribute(flash_attn, cudaFuncAttributeMaxDynamicSharedMemorySize,
                         FL_SMEM_WORDS * 4);

    // 0) zero xsum
    zero_xsum<<<16, 256>>>(pxs);

    // 1+2) h = x @ w_in^T + b_in, fused per-head softmax -> p, xsum
    gemm2<true><<<dim3(kD / 128, (kB * kS) / 128), 256, G2_SMEM_WORDS * 4>>>(
        x, w_in, b_in, pp, kD, kD, kD, kD, 1.f, pxs);

    // 3) t[bn][o][e] = sum_h W[o,n,e,h] * xsum[bn][h]
    compute_t4<<<2048, 256>>>(attn_w, pxs, pt);

    // 4-6) fused flash attention -> g_ao in [b*s][d] layout
    flash_attn<<<dim3(kS / 128, kBN), 256, FL_SMEM_WORDS * 4>>>(pp, pt, pxs, pao);

    // 7) final = g_ao @ w_out^T + b_out
    gemm2<false><<<dim3(kD / 128, (kB * kS) / 128), 256, G2_SMEM_WORDS * 4>>>(
        pao, w_out, b_out, out, kD, kD, kD, kD, 1.f, nullptr);
}

// round 7
// speedup vs baseline: 3.2824x; 1.1385x over previous
#include <cuda_runtime.h>
#include <cuda_bf16.h>
#include <math.h>

// Problem constants
#define kB 4
#define kS 1024
#define kD 1024
#define kN 16
#define kH 64
#define kBN 64  // kB * kN

// Scratch (device globals: allocation-free rule)
__device__ float g_p[(size_t)kBN * kS * kH];       // 16 MB
__device__ float g_xsum[kBN * kH];                 // 16 KB
__device__ float g_t[(size_t)kBN * kS * kH];       // 16 MB
__device__ float g_ao[(size_t)kB * kS * kD];       // 16 MB

// ---------------------------------------------------------------------------
// MMA helpers
// ---------------------------------------------------------------------------
#define MMA_TF32(ac, a0, a1, a2, a3, b0, b1)                                   \
    asm volatile(                                                              \
        "mma.sync.aligned.m16n8k8.row.col.f32.tf32.tf32.f32 "                  \
        "{%0,%1,%2,%3}, {%4,%5,%6,%7}, {%8,%9}, {%0,%1,%2,%3};"                \
        : "+f"((ac)[0]), "+f"((ac)[1]), "+f"((ac)[2]), "+f"((ac)[3])           \
        : "r"(a0), "r"(a1), "r"(a2), "r"(a3), "r"(b0), "r"(b1))

#define MMA_BF16(ac, a0, a1, a2, a3, b0, b1)                                   \
    asm volatile(                                                              \
        "mma.sync.aligned.m16n8k16.row.col.f32.bf16.bf16.f32 "                 \
        "{%0,%1,%2,%3}, {%4,%5,%6,%7}, {%8,%9}, {%0,%1,%2,%3};"                \
        : "+f"((ac)[0]), "+f"((ac)[1]), "+f"((ac)[2]), "+f"((ac)[3])           \
        : "r"(a0), "r"(a1), "r"(a2), "r"(a3), "r"(b0), "r"(b1))

__device__ __forceinline__ unsigned fbits(float f) { return __float_as_uint(f); }

// pack two f32 -> bf16x2 (lo = first arg)
__device__ __forceinline__ unsigned pk(float lo, float hi) {
    unsigned r;
    asm("cvt.rn.bf16x2.f32 %0, %1, %2;" : "=r"(r) : "f"(hi), "f"(lo));
    return r;
}

__device__ __forceinline__ void cp16(unsigned saddr, const void* gaddr) {
    asm volatile("cp.async.cg.shared.global [%0], [%1], 16;"
                 :: "r"(saddr), "l"(gaddr));
}
#define CP_COMMIT() asm volatile("cp.async.commit_group;")
#define CP_WAIT(n)  asm volatile("cp.async.wait_group %0;" :: "n"(n))

// ---------------------------------------------------------------------------
// Double-buffered TF32 NT GEMM: C[M,N] = alpha * A[M,K] @ B[N,K]^T (+ bias)
// 128x128x32 tiles, cp.async 2-stage. If FUSE: epilogue does per-head
// softmax over 64-col chunks, writes p[bn][s][h], accumulates xsum.
// ---------------------------------------------------------------------------
#define G2_STAGE (128 * 36)
#define G2_SMEM_WORDS (4 * G2_STAGE + 128)

template <bool FUSE>
__global__ __launch_bounds__(256, 2) void gemm2(
    const float* __restrict__ A, const float* __restrict__ B,
    const float* __restrict__ bias, float* __restrict__ C,
    int K, int lda, int ldb, int ldc, float alpha, float* __restrict__ xsum)
{
    extern __shared__ float smx[];
    float* sA  = smx;                    // [2][128][36]
    float* sB  = smx + 2 * G2_STAGE;     // [2][128][36]
    float* sxs = smx + 4 * G2_STAGE;     // [128] (FUSE only)

    const int tid  = threadIdx.x;
    const int lane = tid & 31, wid = tid >> 5;
    const int warpRow = wid & 3, warpCol = wid >> 2;
    const int gid = lane >> 2, tig = lane & 3;
    const int row0 = blockIdx.y * 128, col0 = blockIdx.x * 128;

    if (FUSE && tid < 128) sxs[tid] = 0.f;

    const int lrow  = tid >> 1;
    const int lhalf = (tid & 1) * 16;
    const float* Asrc = A + (size_t)(row0 + lrow) * lda + lhalf;
    const float* Bsrc = B + (size_t)(col0 + lrow) * ldb + lhalf;
    const unsigned aBase =
        (unsigned)__cvta_generic_to_shared(&sA[lrow * 36 + lhalf]);
    const unsigned bBase =
        (unsigned)__cvta_generic_to_shared(&sB[lrow * 36 + lhalf]);

    float acc[2][8][4];
#pragma unroll
    for (int i = 0; i < 2; i++)
#pragma unroll
        for (int j = 0; j < 8; j++)
#pragma unroll
            for (int k = 0; k < 4; k++) acc[i][j][k] = 0.f;

    const int nIter = K / 32;

#pragma unroll
    for (int j = 0; j < 4; j++) {
        cp16(aBase + j * 16, Asrc + j * 4);
        cp16(bBase + j * 16, Bsrc + j * 4);
    }
    CP_COMMIT();

    for (int it = 0; it < nIter; it++) {
        const int buf = it & 1;
        if (it + 1 < nIter) {
            const unsigned off = (buf ^ 1) * (G2_STAGE * 4);
            const int k0 = (it + 1) * 32;
#pragma unroll
            for (int j = 0; j < 4; j++) {
                cp16(aBase + off + j * 16, Asrc + k0 + j * 4);
                cp16(bBase + off + j * 16, Bsrc + k0 + j * 4);
            }
            CP_COMMIT();
            CP_WAIT(1);
        } else {
            CP_WAIT(0);
        }
        __syncthreads();

        const float* Ab = sA + buf * G2_STAGE;
        const float* Bb = sB + buf * G2_STAGE;
#pragma unroll
        for (int ks = 0; ks < 32; ks += 8) {
            unsigned af[2][4], bf[8][2];
#pragma unroll
            for (int mt = 0; mt < 2; mt++) {
                const int m = warpRow * 32 + mt * 16 + gid;
                af[mt][0] = fbits(Ab[m * 36 + ks + tig]);
                af[mt][1] = fbits(Ab[(m + 8) * 36 + ks + tig]);
                af[mt][2] = fbits(Ab[m * 36 + ks + tig + 4]);
                af[mt][3] = fbits(Ab[(m + 8) * 36 + ks + tig + 4]);
            }
#pragma unroll
            for (int nt = 0; nt < 8; nt++) {
                const int n = warpCol * 64 + nt * 8 + gid;
                bf[nt][0] = fbits(Bb[n * 36 + ks + tig]);
                bf[nt][1] = fbits(Bb[n * 36 + ks + tig + 4]);
            }
#pragma unroll
            for (int mt = 0; mt < 2; mt++)
#pragma unroll
                for (int nt = 0; nt < 8; nt++)
                    MMA_TF32(acc[mt][nt], af[mt][0], af[mt][1], af[mt][2],
                             af[mt][3], bf[nt][0], bf[nt][1]);
        }
        __syncthreads();
    }

    if (!FUSE) {
#pragma unroll
        for (int mt = 0; mt < 2; mt++) {
#pragma unroll
            for (int nt = 0; nt < 8; nt++) {
                const int row = row0 + warpRow * 32 + mt * 16 + gid;
                const int col = col0 + warpCol * 64 + nt * 8 + 2 * tig;
                float bb0 = 0.f, bb1 = 0.f;
                if (bias) { bb0 = bias[col]; bb1 = bias[col + 1]; }
                float2 v0, v1;
                v0.x = acc[mt][nt][0] * alpha + bb0;
                v0.y = acc[mt][nt][1] * alpha + bb1;
                v1.x = acc[mt][nt][2] * alpha + bb0;
                v1.y = acc[mt][nt][3] * alpha + bb1;
                *(float2*)(C + (size_t)row * ldc + col)       = v0;
                *(float2*)(C + (size_t)(row + 8) * ldc + col) = v1;
            }
        }
    } else {
        const int head = blockIdx.x * 2 + warpCol;
        const int b    = blockIdx.y >> 3;
        const int bn   = b * 16 + head;
#pragma unroll
        for (int mt = 0; mt < 2; mt++)
#pragma unroll
            for (int nt = 0; nt < 8; nt++) {
                const int col = col0 + warpCol * 64 + nt * 8 + 2 * tig;
                acc[mt][nt][0] += bias[col];
                acc[mt][nt][1] += bias[col + 1];
                acc[mt][nt][2] += bias[col];
                acc[mt][nt][3] += bias[col + 1];
            }
        float xacc[8][2];
#pragma unroll
        for (int nt = 0; nt < 8; nt++) { xacc[nt][0] = 0.f; xacc[nt][1] = 0.f; }

#pragma unroll
        for (int mt = 0; mt < 2; mt++) {
#pragma unroll
            for (int half = 0; half < 2; half++) {
                float mx = -1e30f;
#pragma unroll
                for (int nt = 0; nt < 8; nt++)
                    mx = fmaxf(mx, fmaxf(acc[mt][nt][half * 2],
                                         acc[mt][nt][half * 2 + 1]));
                mx = fmaxf(mx, __shfl_xor_sync(0xffffffffu, mx, 1));
                mx = fmaxf(mx, __shfl_xor_sync(0xffffffffu, mx, 2));
                float sum = 0.f;
#pragma unroll
                for (int nt = 0; nt < 8; nt++) {
                    float e0 = __expf(acc[mt][nt][half * 2]     - mx);
                    float e1 = __expf(acc[mt][nt][half * 2 + 1] - mx);
                    acc[mt][nt][half * 2]     = e0;
                    acc[mt][nt][half * 2 + 1] = e1;
                    sum += e0 + e1;
                }
                sum += __shfl_xor_sync(0xffffffffu, sum, 1);
                sum += __shfl_xor_sync(0xffffffffu, sum, 2);
                const float inv = 1.f / sum;
                const int s = (row0 & 1023) + warpRow * 32 + mt * 16 + gid + half * 8;
                float* prow = C + ((size_t)bn * kS + s) * kH;
#pragma unroll
                for (int nt = 0; nt < 8; nt++) {
                    float p0 = acc[mt][nt][half * 2]     * inv;
                    float p1 = acc[mt][nt][half * 2 + 1] * inv;
                    float2 v; v.x = p0; v.y = p1;
                    *(float2*)(prow + nt * 8 + 2 * tig) = v;
                    xacc[nt][0] += p0;
                    xacc[nt][1] += p1;
                }
            }
        }
#pragma unroll
        for (int nt = 0; nt < 8; nt++) {
            atomicAdd(&sxs[warpCol * 64 + nt * 8 + 2 * tig],     xacc[nt][0]);
            atomicAdd(&sxs[warpCol * 64 + nt * 8 + 2 * tig + 1], xacc[nt][1]);
        }
        __syncthreads();
        if (tid < 128) {
            const int hh = tid & 63, hd = tid >> 6;
            atomicAdd(&xsum[(b * 16 + blockIdx.x * 2 + hd) * 64 + hh], sxs[tid]);
        }
    }
}

// ---------------------------------------------------------------------------
// Fused flash attention over o-dim (Q=p/2048, K=t, V=p), bf16 m16n8k16.
// |scores| <= 0.005 structurally -> no max subtraction; e-1 via Taylor;
// PV runs on (e-1) held ENTIRELY in registers (S-accum layout == A-frag
// layout); mean term added back exactly via fp32 xsum. l = 1024 + sum(e-1).
// Smem (static 36KB): Qs[128][72]h, Ks[64][72]h, VsT[64][72]h (stride 36 b32
// words -> bank-conflict-free fragment access: bank = 4*gid + tig).
// Grid: (kS/128, kBN). 256 threads = 8 warps x 16 rows.
// ---------------------------------------------------------------------------
__global__ __launch_bounds__(256, 2) void flash_attn(
    const float* __restrict__ Pg, const float* __restrict__ Tg,
    const float* __restrict__ Xs, float* __restrict__ AOg)
{
    __shared__ unsigned QsW[128 * 36];
    __shared__ unsigned KsW[64 * 36];
    __shared__ unsigned VsW[64 * 36];

    const int bn = blockIdx.y;
    const int s0 = blockIdx.x * 128;
    const float* Pp = Pg + (size_t)bn * kS * kH;
    const float* Tp = Tg + (size_t)bn * kS * kH;

    const int tid = threadIdx.x, lane = tid & 31, wid = tid >> 5;
    const int gid = lane >> 2, tig = lane & 3;
    const int mrow = wid * 16 + gid;

    const float qscale = 1.f / 2048.f;

    // Load Q tile (resident, bf16, pre-scaled by 1/2048)
    {
        const int r0 = tid >> 2, cb = (tid & 3) * 16;
#pragma unroll
        for (int half = 0; half < 2; half++) {
            const int r = r0 + half * 64;
            const float* src = Pp + (size_t)(s0 + r) * kH + cb;
#pragma unroll
            for (int q = 0; q < 4; q++) {
                float4 v = *(const float4*)(src + q * 4);
                QsW[r * 36 + cb / 2 + q * 2]     = pk(v.x * qscale, v.y * qscale);
                QsW[r * 36 + cb / 2 + q * 2 + 1] = pk(v.z * qscale, v.w * qscale);
            }
        }
    }

    float lsum0 = 0.f, lsum1 = 0.f;
    float acc_o[8][4];
#pragma unroll
    for (int j = 0; j < 8; j++)
#pragma unroll
        for (int k = 0; k < 4; k++) acc_o[j][k] = 0.f;

    const float c2 = 0.5f, c3 = 1.f / 6.f;

    for (int o0 = 0; o0 < kS; o0 += 64) {
        __syncthreads();
        // K tile: t rows, bf16
        {
            const int r = tid >> 2, cb = (tid & 3) * 16;
            const float* src = Tp + (size_t)(o0 + r) * kH + cb;
#pragma unroll
            for (int q = 0; q < 4; q++) {
                float4 v = *(const float4*)(src + q * 4);
                KsW[r * 36 + cb / 2 + q * 2]     = pk(v.x, v.y);
                KsW[r * 36 + cb / 2 + q * 2 + 1] = pk(v.z, v.w);
            }
        }
        // V^T tile: p rows transposed into [h][o], bf16, o-pairs packed
        {
            const int op = tid & 31, cb = (tid >> 5) * 8;
            const float* r0p = Pp + (size_t)(o0 + 2 * op) * kH + cb;
            const float* r1p = r0p + kH;
            float4 u0 = *(const float4*)(r0p);
            float4 u1 = *(const float4*)(r0p + 4);
            float4 w0 = *(const float4*)(r1p);
            float4 w1 = *(const float4*)(r1p + 4);
            VsW[(cb + 0) * 36 + op] = pk(u0.x, w0.x);
            VsW[(cb + 1) * 36 + op] = pk(u0.y, w0.y);
            VsW[(cb + 2) * 36 + op] = pk(u0.z, w0.z);
            VsW[(cb + 3) * 36 + op] = pk(u0.w, w0.w);
            VsW[(cb + 4) * 36 + op] = pk(u1.x, w1.x);
            VsW[(cb + 5) * 36 + op] = pk(u1.y, w1.y);
            VsW[(cb + 6) * 36 + op] = pk(u1.z, w1.z);
            VsW[(cb + 7) * 36 + op] = pk(u1.w, w1.w);
        }
        __syncthreads();

        // S = Q @ K^T  (x = scores/2048 directly, scale folded into Q)
        float acc_s[8][4];
#pragma unroll
        for (int j = 0; j < 8; j++)
#pragma unroll
            for (int k = 0; k < 4; k++) acc_s[j][k] = 0.f;

#pragma unroll
        for (int j = 0; j < 4; j++) {
            unsigned a0 = QsW[mrow * 36 + 8 * j + tig];
            unsigned a1 = QsW[(mrow + 8) * 36 + 8 * j + tig];
            unsigned a2 = QsW[mrow * 36 + 8 * j + tig + 4];
            unsigned a3 = QsW[(mrow + 8) * 36 + 8 * j + tig + 4];
#pragma unroll
            for (int nt = 0; nt < 8; nt++) {
                unsigned b0 = KsW[(nt * 8 + gid) * 36 + 8 * j + tig];
                unsigned b1 = KsW[(nt * 8 + gid) * 36 + 8 * j + tig + 4];
                MMA_BF16(acc_s[nt], a0, a1, a2, a3, b0, b1);
            }
        }

        // e-1 = x + x^2*(1/2 + x/6), then pack to bf16 A-fragments in regs
#pragma unroll
        for (int nt = 0; nt < 8; nt++) {
            float e0 = fmaf(acc_s[nt][0] * acc_s[nt][0],
                            fmaf(acc_s[nt][0], c3, c2), acc_s[nt][0]);
            float e1 = fmaf(acc_s[nt][1] * acc_s[nt][1],
                            fmaf(acc_s[nt][1], c3, c2), acc_s[nt][1]);
            float e2 = fmaf(acc_s[nt][2] * acc_s[nt][2],
                            fmaf(acc_s[nt][2], c3, c2), acc_s[nt][2]);
            float e3 = fmaf(acc_s[nt][3] * acc_s[nt][3],
                            fmaf(acc_s[nt][3], c3, c2), acc_s[nt][3]);
            lsum0 += e0 + e1;
            lsum1 += e2 + e3;
            acc_s[nt][0] = e0; acc_s[nt][1] = e1;
            acc_s[nt][2] = e2; acc_s[nt][3] = e3;
        }

        // O += (e-1) @ V : A-frags directly from acc_s register layout
#pragma unroll
        for (int j = 0; j < 4; j++) {
            unsigned pa0 = pk(acc_s[2 * j][0],     acc_s[2 * j][1]);
            unsigned pa1 = pk(acc_s[2 * j][2],     acc_s[2 * j][3]);
            unsigned pa2 = pk(acc_s[2 * j + 1][0], acc_s[2 * j + 1][1]);
            unsigned pa3 = pk(acc_s[2 * j + 1][2], acc_s[2 * j + 1][3]);
#pragma unroll
            for (int ht = 0; ht < 8; ht++) {
                unsigned b0 = VsW[(ht * 8 + gid) * 36 + 8 * j + tig];
                unsigned b1 = VsW[(ht * 8 + gid) * 36 + 8 * j + tig + 4];
                MMA_BF16(acc_o[ht], pa0, pa1, pa2, pa3, b0, b1);
            }
        }
    }

    // Epilogue: l = 1024 + sum(e-1); out = (acc_o + xsum) / l
    lsum0 += __shfl_xor_sync(0xffffffffu, lsum0, 1);
    lsum0 += __shfl_xor_sync(0xffffffffu, lsum0, 2);
    lsum1 += __shfl_xor_sync(0xffffffffu, lsum1, 1);
    lsum1 += __shfl_xor_sync(0xffffffffu, lsum1, 2);
    const float inv0 = 1.f / (1024.f + lsum0);
    const float inv1 = 1.f / (1024.f + lsum1);

    const int b = bn >> 4, n = bn & 15;
    const float* xv = Xs + bn * kH;
    float* C = AOg + ((size_t)(b * kS + s0 + mrow)) * kD + n * 64;
#pragma unroll
    for (int nt = 0; nt < 8; nt++) {
        const int col = nt * 8 + 2 * tig;
        const float x0 = xv[col], x1 = xv[col + 1];
        float2 v0, v1;
        v0.x = (acc_o[nt][0] + x0) * inv0; v0.y = (acc_o[nt][1] + x1) * inv0;
        v1.x = (acc_o[nt][2] + x0) * inv1; v1.y = (acc_o[nt][3] + x1) * inv1;
        *(float2*)(C + col)                  = v0;
        *(float2*)(C + (size_t)8 * kD + col) = v1;
    }
}

__global__ void zero_xsum(float* __restrict__ xsum)
{
    const int i = blockIdx.x * blockDim.x + threadIdx.x;
    if (i < kBN * kH) xsum[i] = 0.f;
}

// ---------------------------------------------------------------------------
// compute_t: t[bn][o][e] = sum_h W[o][n][e][h] * xsum[bn][h]
// Block per (n, 8 o's). xsum in registers; streaming W reads. Grid: 2048.
// ---------------------------------------------------------------------------
__global__ __launch_bounds__(256, 2) void compute_t4(const float* __restrict__ W,
                                                     const float* __restrict__ xsum,
                                                     float* __restrict__ t)
{
    const int n = blockIdx.x & 15, oc = blockIdx.x >> 4;
    __shared__ float xs[4][64];
    {
        const int bb = threadIdx.x >> 6, hh = threadIdx.x & 63;
        xs[bb][hh] = xsum[(bb * 16 + n) * 64 + hh];
    }
    __syncthreads();
    const int e = threadIdx.x >> 2, part = threadIdx.x & 3;
    float4 xr[4][4];
#pragma unroll
    for (int bb = 0; bb < 4; bb++)
#pragma unroll
        for (int j = 0; j < 4; j++)
            xr[bb][j] = *(const float4*)&xs[bb][part * 16 + j * 4];

#pragma unroll
    for (int oi = 0; oi < 8; oi++) {
        const int o = oc * 8 + oi;
        const float4* w =
            (const float4*)(W + (((size_t)o * 16 + n) * 64 + e) * 64 + part * 16);
        const float4 w0 = w[0], w1 = w[1], w2 = w[2], w3 = w[3];
        float r[4];
#pragma unroll
        for (int bb = 0; bb < 4; bb++) {
            r[bb] = w0.x * xr[bb][0].x + w0.y * xr[bb][0].y
                  + w0.z * xr[bb][0].z + w0.w * xr[bb][0].w
                  + w1.x * xr[bb][1].x + w1.y * xr[bb][1].y
                  + w1.z * xr[bb][1].z + w1.w * xr[bb][1].w
                  + w2.x * xr[bb][2].x + w2.y * xr[bb][2].y
                  + w2.z * xr[bb][2].z + w2.w * xr[bb][2].w
                  + w3.x * xr[bb][3].x + w3.y * xr[bb][3].y
                  + w3.z * xr[bb][3].z + w3.w * xr[bb][3].w;
        }
#pragma unroll
        for (int bb = 0; bb < 4; bb++) {
            r[bb] += __shfl_xor_sync(0xffffffffu, r[bb], 1);
            r[bb] += __shfl_xor_sync(0xffffffffu, r[bb], 2);
        }
        t[(((size_t)(part * 16 + n)) * kS + o) * kH + e] = r[part];
    }
}

// ---------------------------------------------------------------------------
extern "C" void kernel_launch(void* const* d_in, const int* in_sizes, int n_in,
                              void* d_out, int out_size)
{
    (void)in_sizes; (void)n_in; (void)out_size;
    const float* x      = (const float*)d_in[0];
    const float* attn_w = (const float*)d_in[1];
    const float* w_in   = (const float*)d_in[2];
    const float* b_in   = (const float*)d_in[3];
    const float* w_out  = (const float*)d_in[4];
    const float* b_out  = (const float*)d_in[5];
    float* out = (float*)d_out;

    float *pp, *pxs, *pt, *pao;
    cudaGetSymbolAddress((void**)&pp,  g_p);
    cudaGetSymbolAddress((void**)&pxs, g_xsum);
    cudaGetSymbolAddress((void**)&pt,  g_t);
    cudaGetSymbolAddress((void**)&pao, g_ao);

    cudaFuncSetAttribute(gemm2<true>,  cudaFuncAttributeMaxDynamicSharedMemorySize,
                         G2_SMEM_WORDS * 4);
    cudaFuncSetAttribute(gemm2<false>, cudaFuncAttributeMaxDynamicSharedMemorySize,
                         G2_SMEM_WORDS * 4);

    // 0) zero xsum
    zero_xsum<<<16, 256>>>(pxs);

    // 1+2) h = x @ w_in^T + b_in, fused per-head softmax -> p, xsum
    gemm2<true><<<dim3(kD / 128, (kB * kS) / 128), 256, G2_SMEM_WORDS * 4>>>(
        x, w_in, b_in, pp, kD, kD, kD, kD, 1.f, pxs);

    // 3) t[bn][o][e] = sum_h W[o,n,e,h] * xsum[bn][h]
    compute_t4<<<2048, 256>>>(attn_w, pxs, pt);

    // 4-6) fused flash attention -> g_ao in [b*s][d] layout
    flash_attn<<<dim3(kS / 128, kBN), 256>>>(pp, pt, pxs, pao);

    // 7) final = g_ao @ w_out^T + b_out
    gemm2<false><<<dim3(kD / 128, (kB * kS) / 128), 256, G2_SMEM_WORDS * 4>>>(
        pao, w_out, b_out, out, kD, kD, kD, kD, 1.f, nullptr);
}

// round 8
// speedup vs baseline: 3.9692x; 1.2092x over previous
#include <cuda_runtime.h>
#include <cuda_bf16.h>
#include <math.h>

// Problem constants
#define kB 4
#define kS 1024
#define kD 1024
#define kN 16
#define kH 64
#define kBN 64  // kB * kN

// Scratch (device globals: allocation-free rule)
__device__ float g_p[(size_t)kBN * kS * kH];       // 16 MB  p[bn][s][h]
__device__ float g_xsum[kBN * kH];                 // 16 KB
__device__ float g_t[(size_t)kBN * kS * kH];       // 16 MB  t[bn][o][e]
__device__ float g_ao[(size_t)kB * kS * kD];       // 16 MB
__device__ unsigned g_m[(size_t)kBN * 72 * 36];    // Ms[bn][72 rows][72 halves]
                                                   // row h<64: M[e][h]/2048 (bf16)
                                                   // row 64: tau[e]/2048; 65-71: 0

// ---------------------------------------------------------------------------
// MMA helpers
// ---------------------------------------------------------------------------
#define MMA_TF32(ac, a0, a1, a2, a3, b0, b1)                                   \
    asm volatile(                                                              \
        "mma.sync.aligned.m16n8k8.row.col.f32.tf32.tf32.f32 "                  \
        "{%0,%1,%2,%3}, {%4,%5,%6,%7}, {%8,%9}, {%0,%1,%2,%3};"                \
        : "+f"((ac)[0]), "+f"((ac)[1]), "+f"((ac)[2]), "+f"((ac)[3])           \
        : "r"(a0), "r"(a1), "r"(a2), "r"(a3), "r"(b0), "r"(b1))

#define MMA_BF16(ac, a0, a1, a2, a3, b0, b1)                                   \
    asm volatile(                                                              \
        "mma.sync.aligned.m16n8k16.row.col.f32.bf16.bf16.f32 "                 \
        "{%0,%1,%2,%3}, {%4,%5,%6,%7}, {%8,%9}, {%0,%1,%2,%3};"                \
        : "+f"((ac)[0]), "+f"((ac)[1]), "+f"((ac)[2]), "+f"((ac)[3])           \
        : "r"(a0), "r"(a1), "r"(a2), "r"(a3), "r"(b0), "r"(b1))

__device__ __forceinline__ unsigned fbits(float f) { return __float_as_uint(f); }

// pack two f32 -> bf16x2 (lo = first arg)
__device__ __forceinline__ unsigned pk(float lo, float hi) {
    unsigned r;
    asm("cvt.rn.bf16x2.f32 %0, %1, %2;" : "=r"(r) : "f"(hi), "f"(lo));
    return r;
}

__device__ __forceinline__ void cp16(unsigned saddr, const void* gaddr) {
    asm volatile("cp.async.cg.shared.global [%0], [%1], 16;"
                 :: "r"(saddr), "l"(gaddr));
}
#define CP_COMMIT() asm volatile("cp.async.commit_group;")
#define CP_WAIT(n)  asm volatile("cp.async.wait_group %0;" :: "n"(n))

// ---------------------------------------------------------------------------
// Double-buffered TF32 NT GEMM: C[M,N] = alpha * A[M,K] @ B[N,K]^T (+ bias)
// 128x128x32 tiles, cp.async 2-stage. If FUSE: epilogue does per-head
// softmax over 64-col chunks, writes p[bn][s][h], accumulates xsum.
// ---------------------------------------------------------------------------
#define G2_STAGE (128 * 36)
#define G2_SMEM_WORDS (4 * G2_STAGE + 128)

template <bool FUSE>
__global__ __launch_bounds__(256, 2) void gemm2(
    const float* __restrict__ A, const float* __restrict__ B,
    const float* __restrict__ bias, float* __restrict__ C,
    int K, int lda, int ldb, int ldc, float alpha, float* __restrict__ xsum)
{
    extern __shared__ float smx[];
    float* sA  = smx;                    // [2][128][36]
    float* sB  = smx + 2 * G2_STAGE;     // [2][128][36]
    float* sxs = smx + 4 * G2_STAGE;     // [128] (FUSE only)

    const int tid  = threadIdx.x;
    const int lane = tid & 31, wid = tid >> 5;
    const int warpRow = wid & 3, warpCol = wid >> 2;
    const int gid = lane >> 2, tig = lane & 3;
    const int row0 = blockIdx.y * 128, col0 = blockIdx.x * 128;

    if (FUSE && tid < 128) sxs[tid] = 0.f;

    const int lrow  = tid >> 1;
    const int lhalf = (tid & 1) * 16;
    const float* Asrc = A + (size_t)(row0 + lrow) * lda + lhalf;
    const float* Bsrc = B + (size_t)(col0 + lrow) * ldb + lhalf;
    const unsigned aBase =
        (unsigned)__cvta_generic_to_shared(&sA[lrow * 36 + lhalf]);
    const unsigned bBase =
        (unsigned)__cvta_generic_to_shared(&sB[lrow * 36 + lhalf]);

    float acc[2][8][4];
#pragma unroll
    for (int i = 0; i < 2; i++)
#pragma unroll
        for (int j = 0; j < 8; j++)
#pragma unroll
            for (int k = 0; k < 4; k++) acc[i][j][k] = 0.f;

    const int nIter = K / 32;

#pragma unroll
    for (int j = 0; j < 4; j++) {
        cp16(aBase + j * 16, Asrc + j * 4);
        cp16(bBase + j * 16, Bsrc + j * 4);
    }
    CP_COMMIT();

    for (int it = 0; it < nIter; it++) {
        const int buf = it & 1;
        if (it + 1 < nIter) {
            const unsigned off = (buf ^ 1) * (G2_STAGE * 4);
            const int k0 = (it + 1) * 32;
#pragma unroll
            for (int j = 0; j < 4; j++) {
                cp16(aBase + off + j * 16, Asrc + k0 + j * 4);
                cp16(bBase + off + j * 16, Bsrc + k0 + j * 4);
            }
            CP_COMMIT();
            CP_WAIT(1);
        } else {
            CP_WAIT(0);
        }
        __syncthreads();

        const float* Ab = sA + buf * G2_STAGE;
        const float* Bb = sB + buf * G2_STAGE;
#pragma unroll
        for (int ks = 0; ks < 32; ks += 8) {
            unsigned af[2][4], bf[8][2];
#pragma unroll
            for (int mt = 0; mt < 2; mt++) {
                const int m = warpRow * 32 + mt * 16 + gid;
                af[mt][0] = fbits(Ab[m * 36 + ks + tig]);
                af[mt][1] = fbits(Ab[(m + 8) * 36 + ks + tig]);
                af[mt][2] = fbits(Ab[m * 36 + ks + tig + 4]);
                af[mt][3] = fbits(Ab[(m + 8) * 36 + ks + tig + 4]);
            }
#pragma unroll
            for (int nt = 0; nt < 8; nt++) {
                const int n = warpCol * 64 + nt * 8 + gid;
                bf[nt][0] = fbits(Bb[n * 36 + ks + tig]);
                bf[nt][1] = fbits(Bb[n * 36 + ks + tig + 4]);
            }
#pragma unroll
            for (int mt = 0; mt < 2; mt++)
#pragma unroll
                for (int nt = 0; nt < 8; nt++)
                    MMA_TF32(acc[mt][nt], af[mt][0], af[mt][1], af[mt][2],
                             af[mt][3], bf[nt][0], bf[nt][1]);
        }
        __syncthreads();
    }

    if (!FUSE) {
#pragma unroll
        for (int mt = 0; mt < 2; mt++) {
#pragma unroll
            for (int nt = 0; nt < 8; nt++) {
                const int row = row0 + warpRow * 32 + mt * 16 + gid;
                const int col = col0 + warpCol * 64 + nt * 8 + 2 * tig;
                float bb0 = 0.f, bb1 = 0.f;
                if (bias) { bb0 = bias[col]; bb1 = bias[col + 1]; }
                float2 v0, v1;
                v0.x = acc[mt][nt][0] * alpha + bb0;
                v0.y = acc[mt][nt][1] * alpha + bb1;
                v1.x = acc[mt][nt][2] * alpha + bb0;
                v1.y = acc[mt][nt][3] * alpha + bb1;
                *(float2*)(C + (size_t)row * ldc + col)       = v0;
                *(float2*)(C + (size_t)(row + 8) * ldc + col) = v1;
            }
        }
    } else {
        const int head = blockIdx.x * 2 + warpCol;
        const int b    = blockIdx.y >> 3;
        const int bn   = b * 16 + head;
#pragma unroll
        for (int mt = 0; mt < 2; mt++)
#pragma unroll
            for (int nt = 0; nt < 8; nt++) {
                const int col = col0 + warpCol * 64 + nt * 8 + 2 * tig;
                acc[mt][nt][0] += bias[col];
                acc[mt][nt][1] += bias[col + 1];
                acc[mt][nt][2] += bias[col];
                acc[mt][nt][3] += bias[col + 1];
            }
        float xacc[8][2];
#pragma unroll
        for (int nt = 0; nt < 8; nt++) { xacc[nt][0] = 0.f; xacc[nt][1] = 0.f; }

#pragma unroll
        for (int mt = 0; mt < 2; mt++) {
#pragma unroll
            for (int half = 0; half < 2; half++) {
                float mx = -1e30f;
#pragma unroll
                for (int nt = 0; nt < 8; nt++)
                    mx = fmaxf(mx, fmaxf(acc[mt][nt][half * 2],
                                         acc[mt][nt][half * 2 + 1]));
                mx = fmaxf(mx, __shfl_xor_sync(0xffffffffu, mx, 1));
                mx = fmaxf(mx, __shfl_xor_sync(0xffffffffu, mx, 2));
                float sum = 0.f;
#pragma unroll
                for (int nt = 0; nt < 8; nt++) {
                    float e0 = __expf(acc[mt][nt][half * 2]     - mx);
                    float e1 = __expf(acc[mt][nt][half * 2 + 1] - mx);
                    acc[mt][nt][half * 2]     = e0;
                    acc[mt][nt][half * 2 + 1] = e1;
                    sum += e0 + e1;
                }
                sum += __shfl_xor_sync(0xffffffffu, sum, 1);
                sum += __shfl_xor_sync(0xffffffffu, sum, 2);
                const float inv = 1.f / sum;
                const int s = (row0 & 1023) + warpRow * 32 + mt * 16 + gid + half * 8;
                float* prow = C + ((size_t)bn * kS + s) * kH;
#pragma unroll
                for (int nt = 0; nt < 8; nt++) {
                    float p0 = acc[mt][nt][half * 2]     * inv;
                    float p1 = acc[mt][nt][half * 2 + 1] * inv;
                    float2 v; v.x = p0; v.y = p1;
                    *(float2*)(prow + nt * 8 + 2 * tig) = v;
                    xacc[nt][0] += p0;
                    xacc[nt][1] += p1;
                }
            }
        }
#pragma unroll
        for (int nt = 0; nt < 8; nt++) {
            atomicAdd(&sxs[warpCol * 64 + nt * 8 + 2 * tig],     xacc[nt][0]);
            atomicAdd(&sxs[warpCol * 64 + nt * 8 + 2 * tig + 1], xacc[nt][1]);
        }
        __syncthreads();
        if (tid < 128) {
            const int hh = tid & 63, hd = tid >> 6;
            atomicAdd(&xsum[(b * 16 + blockIdx.x * 2 + hd) * 64 + hh], sxs[tid]);
        }
    }
}

__global__ void zero_xsum(float* __restrict__ xsum)
{
    const int i = blockIdx.x * blockDim.x + threadIdx.x;
    if (i < kBN * kH) xsum[i] = 0.f;
}

// ---------------------------------------------------------------------------
// compute_t: t[bn][o][e] = sum_h W[o][n][e][h] * xsum[bn][h]
// Block per (n, 8 o's). xsum in registers; streaming W reads. Grid: 2048.
// ---------------------------------------------------------------------------
__global__ __launch_bounds__(256, 2) void compute_t4(const float* __restrict__ W,
                                                     const float* __restrict__ xsum,
                                                     float* __restrict__ t)
{
    const int n = blockIdx.x & 15, oc = blockIdx.x >> 4;
    __shared__ float xs[4][64];
    {
        const int bb = threadIdx.x >> 6, hh = threadIdx.x & 63;
        xs[bb][hh] = xsum[(bb * 16 + n) * 64 + hh];
    }
    __syncthreads();
    const int e = threadIdx.x >> 2, part = threadIdx.x & 3;
    float4 xr[4][4];
#pragma unroll
    for (int bb = 0; bb < 4; bb++)
#pragma unroll
        for (int j = 0; j < 4; j++)
            xr[bb][j] = *(const float4*)&xs[bb][part * 16 + j * 4];

#pragma unroll
    for (int oi = 0; oi < 8; oi++) {
        const int o = oc * 8 + oi;
        const float4* w =
            (const float4*)(W + (((size_t)o * 16 + n) * 64 + e) * 64 + part * 16);
        const float4 w0 = w[0], w1 = w[1], w2 = w[2], w3 = w[3];
        float r[4];
#pragma unroll
        for (int bb = 0; bb < 4; bb++) {
            r[bb] = w0.x * xr[bb][0].x + w0.y * xr[bb][0].y
                  + w0.z * xr[bb][0].z + w0.w * xr[bb][0].w
                  + w1.x * xr[bb][1].x + w1.y * xr[bb][1].y
                  + w1.z * xr[bb][1].z + w1.w * xr[bb][1].w
                  + w2.x * xr[bb][2].x + w2.y * xr[bb][2].y
                  + w2.z * xr[bb][2].z + w2.w * xr[bb][2].w
                  + w3.x * xr[bb][3].x + w3.y * xr[bb][3].y
                  + w3.z * xr[bb][3].z + w3.w * xr[bb][3].w;
        }
#pragma unroll
        for (int bb = 0; bb < 4; bb++) {
            r[bb] += __shfl_xor_sync(0xffffffffu, r[bb], 1);
            r[bb] += __shfl_xor_sync(0xffffffffu, r[bb], 2);
        }
        t[(((size_t)(part * 16 + n)) * kS + o) * kH + e] = r[part];
    }
}

// ---------------------------------------------------------------------------
// gemm_m: per bn, M[e][h] = sum_o t[bn][o][e] * p[bn][o][h]  (K = 1024),
// plus tau[e] = sum_o t[bn][o][e] via an appended ones-column (n = 64..71).
// Writes Ms[bn][h'][e] = M[e][h']/2048 bf16 (h'=64 row = tau/2048).
// Grid: 64 blocks (bn), 128 threads (4 warps, each 16 e-rows x 72 n).
// ---------------------------------------------------------------------------
__global__ __launch_bounds__(128) void gemm_m(
    const float* __restrict__ Tg, const float* __restrict__ Pg,
    unsigned* __restrict__ Mout)
{
    __shared__ unsigned As[64 * 36];  // t^T: [e][o-halves], stride 36 words
    __shared__ unsigned Bs[72 * 36];  // p^T rows 0-63; row 64 = ones; 65-71 = 0

    const int bn = blockIdx.x;
    const int tid = threadIdx.x, lane = tid & 31, wid = tid >> 5;
    const int gid = lane >> 2, tig = lane & 3;
    const float* Tp = Tg + (size_t)bn * kS * kH;
    const float* Pp = Pg + (size_t)bn * kS * kH;

    // constant rows 64-71 of Bs (ones row + zeros), written once
    for (int i = tid; i < 8 * 36; i += 128) {
        const int r = 64 + i / 36, w = i % 36;
        Bs[r * 36 + w] = (r == 64 && w < 32) ? 0x3F803F80u : 0u;
    }

    float acc[9][4];
#pragma unroll
    for (int j = 0; j < 9; j++)
#pragma unroll
        for (int k = 0; k < 4; k++) acc[j][k] = 0.f;

    const int op = tid & 31;            // o-pair 0..31 (rows 2op, 2op+1)
    const int cb = (tid >> 5) * 16;     // col base 0,16,32,48

    for (int o0 = 0; o0 < kS; o0 += 64) {
        __syncthreads();
        // t^T into As
        {
            const float* r0p = Tp + (size_t)(o0 + 2 * op) * kH + cb;
            const float* r1p = r0p + kH;
#pragma unroll
            for (int q = 0; q < 4; q++) {
                float4 u = *(const float4*)(r0p + q * 4);
                float4 w = *(const float4*)(r1p + q * 4);
                As[(cb + q * 4 + 0) * 36 + op] = pk(u.x, w.x);
                As[(cb + q * 4 + 1) * 36 + op] = pk(u.y, w.y);
                As[(cb + q * 4 + 2) * 36 + op] = pk(u.z, w.z);
                As[(cb + q * 4 + 3) * 36 + op] = pk(u.w, w.w);
            }
        }
        // p^T into Bs rows 0-63
        {
            const float* r0p = Pp + (size_t)(o0 + 2 * op) * kH + cb;
            const float* r1p = r0p + kH;
#pragma unroll
            for (int q = 0; q < 4; q++) {
                float4 u = *(const float4*)(r0p + q * 4);
                float4 w = *(const float4*)(r1p + q * 4);
                Bs[(cb + q * 4 + 0) * 36 + op] = pk(u.x, w.x);
                Bs[(cb + q * 4 + 1) * 36 + op] = pk(u.y, w.y);
                Bs[(cb + q * 4 + 2) * 36 + op] = pk(u.z, w.z);
                Bs[(cb + q * 4 + 3) * 36 + op] = pk(u.w, w.w);
            }
        }
        __syncthreads();

        const int mrow = wid * 16 + gid;
#pragma unroll
        for (int j = 0; j < 4; j++) {
            unsigned a0 = As[mrow * 36 + 8 * j + tig];
            unsigned a1 = As[(mrow + 8) * 36 + 8 * j + tig];
            unsigned a2 = As[mrow * 36 + 8 * j + tig + 4];
            unsigned a3 = As[(mrow + 8) * 36 + 8 * j + tig + 4];
#pragma unroll
            for (int nt = 0; nt < 9; nt++) {
                unsigned b0 = Bs[(nt * 8 + gid) * 36 + 8 * j + tig];
                unsigned b1 = Bs[(nt * 8 + gid) * 36 + 8 * j + tig + 4];
                MMA_BF16(acc[nt], a0, a1, a2, a3, b0, b1);
            }
        }
    }

    // Write transposed bf16: Ms[bn][col][e], scaled by 1/2048
    __nv_bfloat16* pm = (__nv_bfloat16*)(Mout + (size_t)bn * 72 * 36);
    const float s = 1.f / 2048.f;
    const int mrow = wid * 16 + gid;
#pragma unroll
    for (int nt = 0; nt < 9; nt++) {
        const int col = nt * 8 + 2 * tig;
        pm[(col)     * 72 + mrow]     = __float2bfloat16(acc[nt][0] * s);
        pm[(col + 1) * 72 + mrow]     = __float2bfloat16(acc[nt][1] * s);
        pm[(col)     * 72 + mrow + 8] = __float2bfloat16(acc[nt][2] * s);
        pm[(col + 1) * 72 + mrow + 8] = __float2bfloat16(acc[nt][3] * s);
    }
}

// ---------------------------------------------------------------------------
// gemm_apply: out[bn][s][h] = (xsum[bn][h] + (p_s @ M')[h]) /
//                             (1024 + (p_s @ tau')),  written to g_ao layout.
// A = p tile [128 s][64 e] bf16; B = Ms[bn] [72 n][64 e] bf16 (n=64 -> tau).
// Grid: (kS/128, kBN). 256 threads = 8 warps x 16 s-rows.
// ---------------------------------------------------------------------------
__global__ __launch_bounds__(256) void gemm_apply(
    const float* __restrict__ Pg, const unsigned* __restrict__ Mg,
    const float* __restrict__ Xs, float* __restrict__ AOg)
{
    __shared__ unsigned Ps[128 * 36];
    __shared__ unsigned Bs[72 * 36];

    const int bn = blockIdx.y;
    const int s0 = blockIdx.x * 128;
    const float* Pp = Pg + (size_t)bn * kS * kH;
    const unsigned* Mp = Mg + (size_t)bn * 72 * 36;

    const int tid = threadIdx.x, lane = tid & 31, wid = tid >> 5;
    const int gid = lane >> 2, tig = lane & 3;
    const int mrow = wid * 16 + gid;

    // Load Ms (word copy, coalesced)
    for (int i = tid; i < 72 * 36; i += 256) Bs[i] = Mp[i];

    // Load p tile -> bf16, conflict-free uint2 stores
    {
        const int r0 = tid >> 4, c = (tid & 15) * 4;
#pragma unroll
        for (int pass = 0; pass < 8; pass++) {
            const int r = r0 + pass * 16;
            float4 v = *(const float4*)(Pp + (size_t)(s0 + r) * kH + c);
            uint2 w;
            w.x = pk(v.x, v.y);
            w.y = pk(v.z, v.w);
            *(uint2*)&Ps[r * 36 + c / 2] = w;
        }
    }
    __syncthreads();

    float acc[9][4];
#pragma unroll
    for (int j = 0; j < 9; j++)
#pragma unroll
        for (int k = 0; k < 4; k++) acc[j][k] = 0.f;

#pragma unroll
    for (int j = 0; j < 4; j++) {
        unsigned a0 = Ps[mrow * 36 + 8 * j + tig];
        unsigned a1 = Ps[(mrow + 8) * 36 + 8 * j + tig];
        unsigned a2 = Ps[mrow * 36 + 8 * j + tig + 4];
        unsigned a3 = Ps[(mrow + 8) * 36 + 8 * j + tig + 4];
#pragma unroll
        for (int nt = 0; nt < 9; nt++) {
            unsigned b0 = Bs[(nt * 8 + gid) * 36 + 8 * j + tig];
            unsigned b1 = Bs[(nt * 8 + gid) * 36 + 8 * j + tig + 4];
            MMA_BF16(acc[nt], a0, a1, a2, a3, b0, b1);
        }
    }

    // Denominators: col 64 lives in acc[8][0]/acc[8][2] of quad-leader lanes
    const float tau0 = __shfl_sync(0xffffffffu, acc[8][0], lane & 28);
    const float tau1 = __shfl_sync(0xffffffffu, acc[8][2], lane & 28);
    const float inv0 = 1.f / (1024.f + tau0);
    const float inv1 = 1.f / (1024.f + tau1);

    const int b = bn >> 4, n = bn & 15;
    const float* xv = Xs + bn * kH;
    float* C = AOg + ((size_t)(b * kS + s0 + mrow)) * kD + n * 64;
#pragma unroll
    for (int nt = 0; nt < 8; nt++) {
        const int col = nt * 8 + 2 * tig;
        const float x0 = xv[col], x1 = xv[col + 1];
        float2 v0, v1;
        v0.x = (acc[nt][0] + x0) * inv0; v0.y = (acc[nt][1] + x1) * inv0;
        v1.x = (acc[nt][2] + x0) * inv1; v1.y = (acc[nt][3] + x1) * inv1;
        *(float2*)(C + col)                  = v0;
        *(float2*)(C + (size_t)8 * kD + col) = v1;
    }
}

// ---------------------------------------------------------------------------
extern "C" void kernel_launch(void* const* d_in, const int* in_sizes, int n_in,
                              void* d_out, int out_size)
{
    (void)in_sizes; (void)n_in; (void)out_size;
    const float* x      = (const float*)d_in[0];
    const float* attn_w = (const float*)d_in[1];
    const float* w_in   = (const float*)d_in[2];
    const float* b_in   = (const float*)d_in[3];
    const float* w_out  = (const float*)d_in[4];
    const float* b_out  = (const float*)d_in[5];
    float* out = (float*)d_out;

    float *pp, *pxs, *pt, *pao;
    unsigned* pm;
    cudaGetSymbolAddress((void**)&pp,  g_p);
    cudaGetSymbolAddress((void**)&pxs, g_xsum);
    cudaGetSymbolAddress((void**)&pt,  g_t);
    cudaGetSymbolAddress((void**)&pao, g_ao);
    cudaGetSymbolAddress((void**)&pm,  g_m);

    cudaFuncSetAttribute(gemm2<true>,  cudaFuncAttributeMaxDynamicSharedMemorySize,
                         G2_SMEM_WORDS * 4);
    cudaFuncSetAttribute(gemm2<false>, cudaFuncAttributeMaxDynamicSharedMemorySize,
                         G2_SMEM_WORDS * 4);

    // 0) zero xsum
    zero_xsum<<<16, 256>>>(pxs);

    // 1+2) h = x @ w_in^T + b_in, fused per-head softmax -> p, xsum
    gemm2<true><<<dim3(kD / 128, (kB * kS) / 128), 256, G2_SMEM_WORDS * 4>>>(
        x, w_in, b_in, pp, kD, kD, kD, kD, 1.f, pxs);

    // 3) t[bn][o][e] = sum_h W[o,n,e,h] * xsum[bn][h]
    compute_t4<<<2048, 256>>>(attn_w, pxs, pt);

    // 4) M = t^T @ p (+tau), scaled 1/2048, bf16 transposed
    gemm_m<<<kBN, 128>>>(pt, pp, pm);

    // 5) linearized attention apply -> g_ao in [b*s][d] layout
    gemm_apply<<<dim3(kS / 128, kBN), 256>>>(pp, pm, pxs, pao);

    // 6) final = g_ao @ w_out^T + b_out
    gemm2<false><<<dim3(kD / 128, (kB * kS) / 128), 256, G2_SMEM_WORDS * 4>>>(
        pao, w_out, b_out, out, kD, kD, kD, kD, 1.f, nullptr);
}

// round 9
// speedup vs baseline: 4.3468x; 1.0951x over previous
#include <cuda_runtime.h>
#include <cuda_bf16.h>
#include <math.h>

// Problem constants
#define kB 4
#define kS 1024
#define kD 1024
#define kN 16
#define kH 64
#define kBN 64  // kB * kN

// Scratch (device globals: allocation-free rule)
__device__ float g_p[(size_t)kBN * kS * kH];       // 16 MB  p[bn][s][h]
__device__ float g_xsum[kBN * kH];                 // 16 KB
__device__ float g_t[(size_t)kBN * kS * kH];       // 16 MB  t[bn][o][e]
__device__ float g_ao[(size_t)kB * kS * kD];       // 16 MB
__device__ float g_mf[(size_t)kBN * 72 * 64];      // fp32 M[bn][col(h/tau)][e]

// ---------------------------------------------------------------------------
// MMA helpers
// ---------------------------------------------------------------------------
#define MMA_TF32(ac, a0, a1, a2, a3, b0, b1)                                   \
    asm volatile(                                                              \
        "mma.sync.aligned.m16n8k8.row.col.f32.tf32.tf32.f32 "                  \
        "{%0,%1,%2,%3}, {%4,%5,%6,%7}, {%8,%9}, {%0,%1,%2,%3};"                \
        : "+f"((ac)[0]), "+f"((ac)[1]), "+f"((ac)[2]), "+f"((ac)[3])           \
        : "r"(a0), "r"(a1), "r"(a2), "r"(a3), "r"(b0), "r"(b1))

#define MMA_BF16(ac, a0, a1, a2, a3, b0, b1)                                   \
    asm volatile(                                                              \
        "mma.sync.aligned.m16n8k16.row.col.f32.bf16.bf16.f32 "                 \
        "{%0,%1,%2,%3}, {%4,%5,%6,%7}, {%8,%9}, {%0,%1,%2,%3};"                \
        : "+f"((ac)[0]), "+f"((ac)[1]), "+f"((ac)[2]), "+f"((ac)[3])           \
        : "r"(a0), "r"(a1), "r"(a2), "r"(a3), "r"(b0), "r"(b1))

__device__ __forceinline__ unsigned fbits(float f) { return __float_as_uint(f); }

// pack two f32 -> bf16x2 (lo = first arg)
__device__ __forceinline__ unsigned pk(float lo, float hi) {
    unsigned r;
    asm("cvt.rn.bf16x2.f32 %0, %1, %2;" : "=r"(r) : "f"(hi), "f"(lo));
    return r;
}

__device__ __forceinline__ void cp16(unsigned saddr, const void* gaddr) {
    asm volatile("cp.async.cg.shared.global [%0], [%1], 16;"
                 :: "r"(saddr), "l"(gaddr));
}
#define CP_COMMIT() asm volatile("cp.async.commit_group;")
#define CP_WAIT(n)  asm volatile("cp.async.wait_group %0;" :: "n"(n))

// ---------------------------------------------------------------------------
// Double-buffered TF32 NT GEMM: C[M,N] = alpha * A[M,K] @ B[N,K]^T (+ bias)
// 128x128x32 tiles, cp.async 2-stage. If FUSE: epilogue does per-head
// softmax over 64-col chunks, writes p[bn][s][h], accumulates xsum.
// ---------------------------------------------------------------------------
#define G2_STAGE (128 * 36)
#define G2_SMEM_WORDS (4 * G2_STAGE + 128)

template <bool FUSE>
__global__ __launch_bounds__(256, 2) void gemm2(
    const float* __restrict__ A, const float* __restrict__ B,
    const float* __restrict__ bias, float* __restrict__ C,
    int K, int lda, int ldb, int ldc, float alpha, float* __restrict__ xsum)
{
    extern __shared__ float smx[];
    float* sA  = smx;                    // [2][128][36]
    float* sB  = smx + 2 * G2_STAGE;     // [2][128][36]
    float* sxs = smx + 4 * G2_STAGE;     // [128] (FUSE only)

    const int tid  = threadIdx.x;
    const int lane = tid & 31, wid = tid >> 5;
    const int warpRow = wid & 3, warpCol = wid >> 2;
    const int gid = lane >> 2, tig = lane & 3;
    const int row0 = blockIdx.y * 128, col0 = blockIdx.x * 128;

    if (FUSE && tid < 128) sxs[tid] = 0.f;

    const int lrow  = tid >> 1;
    const int lhalf = (tid & 1) * 16;
    const float* Asrc = A + (size_t)(row0 + lrow) * lda + lhalf;
    const float* Bsrc = B + (size_t)(col0 + lrow) * ldb + lhalf;
    const unsigned aBase =
        (unsigned)__cvta_generic_to_shared(&sA[lrow * 36 + lhalf]);
    const unsigned bBase =
        (unsigned)__cvta_generic_to_shared(&sB[lrow * 36 + lhalf]);

    float acc[2][8][4];
#pragma unroll
    for (int i = 0; i < 2; i++)
#pragma unroll
        for (int j = 0; j < 8; j++)
#pragma unroll
            for (int k = 0; k < 4; k++) acc[i][j][k] = 0.f;

    const int nIter = K / 32;

#pragma unroll
    for (int j = 0; j < 4; j++) {
        cp16(aBase + j * 16, Asrc + j * 4);
        cp16(bBase + j * 16, Bsrc + j * 4);
    }
    CP_COMMIT();

    for (int it = 0; it < nIter; it++) {
        const int buf = it & 1;
        if (it + 1 < nIter) {
            const unsigned off = (buf ^ 1) * (G2_STAGE * 4);
            const int k0 = (it + 1) * 32;
#pragma unroll
            for (int j = 0; j < 4; j++) {
                cp16(aBase + off + j * 16, Asrc + k0 + j * 4);
                cp16(bBase + off + j * 16, Bsrc + k0 + j * 4);
            }
            CP_COMMIT();
            CP_WAIT(1);
        } else {
            CP_WAIT(0);
        }
        __syncthreads();

        const float* Ab = sA + buf * G2_STAGE;
        const float* Bb = sB + buf * G2_STAGE;
#pragma unroll
        for (int ks = 0; ks < 32; ks += 8) {
            unsigned af[2][4], bf[8][2];
#pragma unroll
            for (int mt = 0; mt < 2; mt++) {
                const int m = warpRow * 32 + mt * 16 + gid;
                af[mt][0] = fbits(Ab[m * 36 + ks + tig]);
                af[mt][1] = fbits(Ab[(m + 8) * 36 + ks + tig]);
                af[mt][2] = fbits(Ab[m * 36 + ks + tig + 4]);
                af[mt][3] = fbits(Ab[(m + 8) * 36 + ks + tig + 4]);
            }
#pragma unroll
            for (int nt = 0; nt < 8; nt++) {
                const int n = warpCol * 64 + nt * 8 + gid;
                bf[nt][0] = fbits(Bb[n * 36 + ks + tig]);
                bf[nt][1] = fbits(Bb[n * 36 + ks + tig + 4]);
            }
#pragma unroll
            for (int mt = 0; mt < 2; mt++)
#pragma unroll
                for (int nt = 0; nt < 8; nt++)
                    MMA_TF32(acc[mt][nt], af[mt][0], af[mt][1], af[mt][2],
                             af[mt][3], bf[nt][0], bf[nt][1]);
        }
        __syncthreads();
    }

    if (!FUSE) {
#pragma unroll
        for (int mt = 0; mt < 2; mt++) {
#pragma unroll
            for (int nt = 0; nt < 8; nt++) {
                const int row = row0 + warpRow * 32 + mt * 16 + gid;
                const int col = col0 + warpCol * 64 + nt * 8 + 2 * tig;
                float bb0 = 0.f, bb1 = 0.f;
                if (bias) { bb0 = bias[col]; bb1 = bias[col + 1]; }
                float2 v0, v1;
                v0.x = acc[mt][nt][0] * alpha + bb0;
                v0.y = acc[mt][nt][1] * alpha + bb1;
                v1.x = acc[mt][nt][2] * alpha + bb0;
                v1.y = acc[mt][nt][3] * alpha + bb1;
                *(float2*)(C + (size_t)row * ldc + col)       = v0;
                *(float2*)(C + (size_t)(row + 8) * ldc + col) = v1;
            }
        }
    } else {
        const int head = blockIdx.x * 2 + warpCol;
        const int b    = blockIdx.y >> 3;
        const int bn   = b * 16 + head;
#pragma unroll
        for (int mt = 0; mt < 2; mt++)
#pragma unroll
            for (int nt = 0; nt < 8; nt++) {
                const int col = col0 + warpCol * 64 + nt * 8 + 2 * tig;
                acc[mt][nt][0] += bias[col];
                acc[mt][nt][1] += bias[col + 1];
                acc[mt][nt][2] += bias[col];
                acc[mt][nt][3] += bias[col + 1];
            }
        float xacc[8][2];
#pragma unroll
        for (int nt = 0; nt < 8; nt++) { xacc[nt][0] = 0.f; xacc[nt][1] = 0.f; }

#pragma unroll
        for (int mt = 0; mt < 2; mt++) {
#pragma unroll
            for (int half = 0; half < 2; half++) {
                float mx = -1e30f;
#pragma unroll
                for (int nt = 0; nt < 8; nt++)
                    mx = fmaxf(mx, fmaxf(acc[mt][nt][half * 2],
                                         acc[mt][nt][half * 2 + 1]));
                mx = fmaxf(mx, __shfl_xor_sync(0xffffffffu, mx, 1));
                mx = fmaxf(mx, __shfl_xor_sync(0xffffffffu, mx, 2));
                float sum = 0.f;
#pragma unroll
                for (int nt = 0; nt < 8; nt++) {
                    float e0 = __expf(acc[mt][nt][half * 2]     - mx);
                    float e1 = __expf(acc[mt][nt][half * 2 + 1] - mx);
                    acc[mt][nt][half * 2]     = e0;
                    acc[mt][nt][half * 2 + 1] = e1;
                    sum += e0 + e1;
                }
                sum += __shfl_xor_sync(0xffffffffu, sum, 1);
                sum += __shfl_xor_sync(0xffffffffu, sum, 2);
                const float inv = 1.f / sum;
                const int s = (row0 & 1023) + warpRow * 32 + mt * 16 + gid + half * 8;
                float* prow = C + ((size_t)bn * kS + s) * kH;
#pragma unroll
                for (int nt = 0; nt < 8; nt++) {
                    float p0 = acc[mt][nt][half * 2]     * inv;
                    float p1 = acc[mt][nt][half * 2 + 1] * inv;
                    float2 v; v.x = p0; v.y = p1;
                    *(float2*)(prow + nt * 8 + 2 * tig) = v;
                    xacc[nt][0] += p0;
                    xacc[nt][1] += p1;
                }
            }
        }
#pragma unroll
        for (int nt = 0; nt < 8; nt++) {
            atomicAdd(&sxs[warpCol * 64 + nt * 8 + 2 * tig],     xacc[nt][0]);
            atomicAdd(&sxs[warpCol * 64 + nt * 8 + 2 * tig + 1], xacc[nt][1]);
        }
        __syncthreads();
        if (tid < 128) {
            const int hh = tid & 63, hd = tid >> 6;
            atomicAdd(&xsum[(b * 16 + blockIdx.x * 2 + hd) * 64 + hh], sxs[tid]);
        }
    }
}

__global__ void zero_scratch(float* __restrict__ xsum, float* __restrict__ mf)
{
    const int i = blockIdx.x * blockDim.x + threadIdx.x;
    if (i < kBN * kH) xsum[i] = 0.f;
    if (i < kBN * 72 * 64) mf[i] = 0.f;
}

// ---------------------------------------------------------------------------
// compute_t: t[bn][o][e] = sum_h W[o][n][e][h] * xsum[bn][h]
// Block per (n, 8 o's). xsum in registers; streaming W reads. Grid: 2048.
// ---------------------------------------------------------------------------
__global__ __launch_bounds__(256, 2) void compute_t4(const float* __restrict__ W,
                                                     const float* __restrict__ xsum,
                                                     float* __restrict__ t)
{
    const int n = blockIdx.x & 15, oc = blockIdx.x >> 4;
    __shared__ float xs[4][64];
    {
        const int bb = threadIdx.x >> 6, hh = threadIdx.x & 63;
        xs[bb][hh] = xsum[(bb * 16 + n) * 64 + hh];
    }
    __syncthreads();
    const int e = threadIdx.x >> 2, part = threadIdx.x & 3;
    float4 xr[4][4];
#pragma unroll
    for (int bb = 0; bb < 4; bb++)
#pragma unroll
        for (int j = 0; j < 4; j++)
            xr[bb][j] = *(const float4*)&xs[bb][part * 16 + j * 4];

#pragma unroll
    for (int oi = 0; oi < 8; oi++) {
        const int o = oc * 8 + oi;
        const float4* w =
            (const float4*)(W + (((size_t)o * 16 + n) * 64 + e) * 64 + part * 16);
        const float4 w0 = w[0], w1 = w[1], w2 = w[2], w3 = w[3];
        float r[4];
#pragma unroll
        for (int bb = 0; bb < 4; bb++) {
            r[bb] = w0.x * xr[bb][0].x + w0.y * xr[bb][0].y
                  + w0.z * xr[bb][0].z + w0.w * xr[bb][0].w
                  + w1.x * xr[bb][1].x + w1.y * xr[bb][1].y
                  + w1.z * xr[bb][1].z + w1.w * xr[bb][1].w
                  + w2.x * xr[bb][2].x + w2.y * xr[bb][2].y
                  + w2.z * xr[bb][2].z + w2.w * xr[bb][2].w
                  + w3.x * xr[bb][3].x + w3.y * xr[bb][3].y
                  + w3.z * xr[bb][3].z + w3.w * xr[bb][3].w;
        }
#pragma unroll
        for (int bb = 0; bb < 4; bb++) {
            r[bb] += __shfl_xor_sync(0xffffffffu, r[bb], 1);
            r[bb] += __shfl_xor_sync(0xffffffffu, r[bb], 2);
        }
        t[(((size_t)(part * 16 + n)) * kS + o) * kH + e] = r[part];
    }
}

// ---------------------------------------------------------------------------
// gemm_m (split-K): per (ksplit, bn), partial
//   M[e][h] += sum_{o in chunk} t[bn][o][e] * p[bn][o][h]; tau via ones col.
// fp32 atomicAdd into Mf[bn][col][e]. Grid: (kBN, 8). 128 threads.
// ---------------------------------------------------------------------------
__global__ __launch_bounds__(128) void gemm_m(
    const float* __restrict__ Tg, const float* __restrict__ Pg,
    float* __restrict__ Mf)
{
    __shared__ unsigned As[64 * 36];  // t^T: [e][o-halves]
    __shared__ unsigned Bs[72 * 36];  // p^T rows 0-63; row 64 = ones; 65-71 = 0

    const int bn = blockIdx.x;
    const int o_base = blockIdx.y * 128;
    const int tid = threadIdx.x, lane = tid & 31, wid = tid >> 5;
    const int gid = lane >> 2, tig = lane & 3;
    const float* Tp = Tg + (size_t)bn * kS * kH;
    const float* Pp = Pg + (size_t)bn * kS * kH;

    for (int i = tid; i < 8 * 36; i += 128) {
        const int r = 64 + i / 36, w = i % 36;
        Bs[r * 36 + w] = (r == 64 && w < 32) ? 0x3F803F80u : 0u;
    }

    float acc[9][4];
#pragma unroll
    for (int j = 0; j < 9; j++)
#pragma unroll
        for (int k = 0; k < 4; k++) acc[j][k] = 0.f;

    const int op = tid & 31;            // o-pair 0..31
    const int cb = (tid >> 5) * 16;     // col base

#pragma unroll
    for (int oi = 0; oi < 2; oi++) {
        const int o0 = o_base + oi * 64;
        __syncthreads();
        {
            const float* r0p = Tp + (size_t)(o0 + 2 * op) * kH + cb;
            const float* r1p = r0p + kH;
#pragma unroll
            for (int q = 0; q < 4; q++) {
                float4 u = *(const float4*)(r0p + q * 4);
                float4 w = *(const float4*)(r1p + q * 4);
                As[(cb + q * 4 + 0) * 36 + op] = pk(u.x, w.x);
                As[(cb + q * 4 + 1) * 36 + op] = pk(u.y, w.y);
                As[(cb + q * 4 + 2) * 36 + op] = pk(u.z, w.z);
                As[(cb + q * 4 + 3) * 36 + op] = pk(u.w, w.w);
            }
        }
        {
            const float* r0p = Pp + (size_t)(o0 + 2 * op) * kH + cb;
            const float* r1p = r0p + kH;
#pragma unroll
            for (int q = 0; q < 4; q++) {
                float4 u = *(const float4*)(r0p + q * 4);
                float4 w = *(const float4*)(r1p + q * 4);
                Bs[(cb + q * 4 + 0) * 36 + op] = pk(u.x, w.x);
                Bs[(cb + q * 4 + 1) * 36 + op] = pk(u.y, w.y);
                Bs[(cb + q * 4 + 2) * 36 + op] = pk(u.z, w.z);
                Bs[(cb + q * 4 + 3) * 36 + op] = pk(u.w, w.w);
            }
        }
        __syncthreads();

        const int mrow = wid * 16 + gid;
#pragma unroll
        for (int j = 0; j < 4; j++) {
            unsigned a0 = As[mrow * 36 + 8 * j + tig];
            unsigned a1 = As[(mrow + 8) * 36 + 8 * j + tig];
            unsigned a2 = As[mrow * 36 + 8 * j + tig + 4];
            unsigned a3 = As[(mrow + 8) * 36 + 8 * j + tig + 4];
#pragma unroll
            for (int nt = 0; nt < 9; nt++) {
                unsigned b0 = Bs[(nt * 8 + gid) * 36 + 8 * j + tig];
                unsigned b1 = Bs[(nt * 8 + gid) * 36 + 8 * j + tig + 4];
                MMA_BF16(acc[nt], a0, a1, a2, a3, b0, b1);
            }
        }
    }

    // Accumulate partials: Mf[bn][col][e] += acc
    float* mf = Mf + (size_t)bn * 72 * 64;
    const int mrow = wid * 16 + gid;
#pragma unroll
    for (int nt = 0; nt < 9; nt++) {
        const int col = nt * 8 + 2 * tig;
        if (col < 65) {  // cols 65..71 are structurally zero
            atomicAdd(&mf[col * 64 + mrow],           acc[nt][0]);
            atomicAdd(&mf[col * 64 + mrow + 8],       acc[nt][2]);
            if (col + 1 < 65) {
                atomicAdd(&mf[(col + 1) * 64 + mrow],     acc[nt][1]);
                atomicAdd(&mf[(col + 1) * 64 + mrow + 8], acc[nt][3]);
            }
        }
    }
}

// ---------------------------------------------------------------------------
// gemm_apply: out[bn][s][h] = (xsum[bn][h] + (p_s @ M')[h]) /
//                             (1024 + (p_s @ tau')),  written to g_ao layout.
// Converts fp32 Mf -> bf16 smem (scaled 1/2048) at load.
// Grid: (kS/128, kBN). 256 threads = 8 warps x 16 s-rows.
// ---------------------------------------------------------------------------
__global__ __launch_bounds__(256) void gemm_apply(
    const float* __restrict__ Pg, const float* __restrict__ Mf,
    const float* __restrict__ Xs, float* __restrict__ AOg)
{
    __shared__ unsigned Ps[128 * 36];
    __shared__ unsigned Bs[72 * 36];

    const int bn = blockIdx.y;
    const int s0 = blockIdx.x * 128;
    const float* Pp = Pg + (size_t)bn * kS * kH;
    const float* mf = Mf + (size_t)bn * 72 * 64;

    const int tid = threadIdx.x, lane = tid & 31, wid = tid >> 5;
    const int gid = lane >> 2, tig = lane & 3;
    const int mrow = wid * 16 + gid;
    const float ms = 1.f / 2048.f;

    // Load + scale + pack Mf -> Bs (rows 0..71, 32 words each used)
    for (int i = tid; i < 72 * 32; i += 256) {
        const int r = i >> 5, w = i & 31;
        float2 v = *(const float2*)(mf + r * 64 + 2 * w);
        Bs[r * 36 + w] = pk(v.x * ms, v.y * ms);
    }

    // Load p tile -> bf16
    {
        const int r0 = tid >> 4, c = (tid & 15) * 4;
#pragma unroll
        for (int pass = 0; pass < 8; pass++) {
            const int r = r0 + pass * 16;
            float4 v = *(const float4*)(Pp + (size_t)(s0 + r) * kH + c);
            uint2 w;
            w.x = pk(v.x, v.y);
            w.y = pk(v.z, v.w);
            *(uint2*)&Ps[r * 36 + c / 2] = w;
        }
    }
    __syncthreads();

    float acc[9][4];
#pragma unroll
    for (int j = 0; j < 9; j++)
#pragma unroll
        for (int k = 0; k < 4; k++) acc[j][k] = 0.f;

#pragma unroll
    for (int j = 0; j < 4; j++) {
        unsigned a0 = Ps[mrow * 36 + 8 * j + tig];
        unsigned a1 = Ps[(mrow + 8) * 36 + 8 * j + tig];
        unsigned a2 = Ps[mrow * 36 + 8 * j + tig + 4];
        unsigned a3 = Ps[(mrow + 8) * 36 + 8 * j + tig + 4];
#pragma unroll
        for (int nt = 0; nt < 9; nt++) {
            unsigned b0 = Bs[(nt * 8 + gid) * 36 + 8 * j + tig];
            unsigned b1 = Bs[(nt * 8 + gid) * 36 + 8 * j + tig + 4];
            MMA_BF16(acc[nt], a0, a1, a2, a3, b0, b1);
        }
    }

    // Denominators: col 64 in acc[8][0]/acc[8][2] of quad-leader lanes
    const float tau0 = __shfl_sync(0xffffffffu, acc[8][0], lane & 28);
    const float tau1 = __shfl_sync(0xffffffffu, acc[8][2], lane & 28);
    const float inv0 = 1.f / (1024.f + tau0);
    const float inv1 = 1.f / (1024.f + tau1);

    const int b = bn >> 4, n = bn & 15;
    const float* xv = Xs + bn * kH;
    float* C = AOg + ((size_t)(b * kS + s0 + mrow)) * kD + n * 64;
#pragma unroll
    for (int nt = 0; nt < 8; nt++) {
        const int col = nt * 8 + 2 * tig;
        const float x0 = xv[col], x1 = xv[col + 1];
        float2 v0, v1;
        v0.x = (acc[nt][0] + x0) * inv0; v0.y = (acc[nt][1] + x1) * inv0;
        v1.x = (acc[nt][2] + x0) * inv1; v1.y = (acc[nt][3] + x1) * inv1;
        *(float2*)(C + col)                  = v0;
        *(float2*)(C + (size_t)8 * kD + col) = v1;
    }
}

// ---------------------------------------------------------------------------
extern "C" void kernel_launch(void* const* d_in, const int* in_sizes, int n_in,
                              void* d_out, int out_size)
{
    (void)in_sizes; (void)n_in; (void)out_size;
    const float* x      = (const float*)d_in[0];
    const float* attn_w = (const float*)d_in[1];
    const float* w_in   = (const float*)d_in[2];
    const float* b_in   = (const float*)d_in[3];
    const float* w_out  = (const float*)d_in[4];
    const float* b_out  = (const float*)d_in[5];
    float* out = (float*)d_out;

    float *pp, *pxs, *pt, *pao, *pmf;
    cudaGetSymbolAddress((void**)&pp,  g_p);
    cudaGetSymbolAddress((void**)&pxs, g_xsum);
    cudaGetSymbolAddress((void**)&pt,  g_t);
    cudaGetSymbolAddress((void**)&pao, g_ao);
    cudaGetSymbolAddress((void**)&pmf, g_mf);

    cudaFuncSetAttribute(gemm2<true>,  cudaFuncAttributeMaxDynamicSharedMemorySize,
                         G2_SMEM_WORDS * 4);
    cudaFuncSetAttribute(gemm2<false>, cudaFuncAttributeMaxDynamicSharedMemorySize,
                         G2_SMEM_WORDS * 4);

    // 0) zero xsum + M scratch
    zero_scratch<<<(kBN * 72 * 64 + 255) / 256, 256>>>(pxs, pmf);

    // 1+2) h = x @ w_in^T + b_in, fused per-head softmax -> p, xsum
    gemm2<true><<<dim3(kD / 128, (kB * kS) / 128), 256, G2_SMEM_WORDS * 4>>>(
        x, w_in, b_in, pp, kD, kD, kD, kD, 1.f, pxs);

    // 3) t[bn][o][e] = sum_h W[o,n,e,h] * xsum[bn][h]
    compute_t4<<<2048, 256>>>(attn_w, pxs, pt);

    // 4) M = t^T @ p (+tau), split-K over 8 chunks, fp32 atomics
    gemm_m<<<dim3(kBN, 8), 128>>>(pt, pp, pmf);

    // 5) linearized attention apply -> g_ao in [b*s][d] layout
    gemm_apply<<<dim3(kS / 128, kBN), 256>>>(pp, pmf, pxs, pao);

    // 6) final = g_ao @ w_out^T + b_out
    gemm2<false><<<dim3(kD / 128, (kB * kS) / 128), 256, G2_SMEM_WORDS * 4>>>(
        pao, w_out, b_out, out, kD, kD, kD, kD, 1.f, nullptr);
}

// round 11
// speedup vs baseline: 5.3382x; 1.2281x over previous
#include <cuda_runtime.h>
#include <cuda_bf16.h>
#include <math.h>

// Problem constants
#define kB 4
#define kS 1024
#define kD 1024
#define kN 16
#define kH 64
#define kBN 64  // kB * kN

// Scratch (device globals: allocation-free rule)
__device__ float g_p[(size_t)kBN * kS * kH];       // 16 MB  p[bn][s][h]
__device__ float g_xsum[kBN * kH];                 // 16 KB
__device__ float g_t[(size_t)kBN * kS * kH];       // 16 MB  t[bn][o][e]
__device__ float g_mf[(size_t)kBN * 72 * 64];      // fp32 M[bn][col(h/tau)][e]
__device__ unsigned g_xb[(size_t)kB * kS * kD / 2];   // x bf16 (8 MB)
__device__ unsigned g_winb[(size_t)kD * kD / 2];      // w_in bf16 (2 MB)
__device__ unsigned g_woutb[(size_t)kD * kD / 2];     // w_out bf16 (2 MB)
__device__ unsigned g_acb[(size_t)kB * kS * kD / 2];  // a_c bf16 (8 MB)
__device__ float g_inv[(size_t)kB * kS * kN];         // inv[s_glob][n] (256 KB)
__device__ float g_y[kBN * kD];                       // y[bn][d] (256 KB)

// ---------------------------------------------------------------------------
// MMA helpers
// ---------------------------------------------------------------------------
#define MMA_BF16(ac, a0, a1, a2, a3, b0, b1)                                   \
    asm volatile(                                                              \
        "mma.sync.aligned.m16n8k16.row.col.f32.bf16.bf16.f32 "                 \
        "{%0,%1,%2,%3}, {%4,%5,%6,%7}, {%8,%9}, {%0,%1,%2,%3};"                \
        : "+f"((ac)[0]), "+f"((ac)[1]), "+f"((ac)[2]), "+f"((ac)[3])           \
        : "r"(a0), "r"(a1), "r"(a2), "r"(a3), "r"(b0), "r"(b1))

// pack two f32 -> bf16x2 (lo = first arg), round-to-nearest (unbiased)
__device__ __forceinline__ unsigned pk(float lo, float hi) {
    unsigned r;
    asm("cvt.rn.bf16x2.f32 %0, %1, %2;" : "=r"(r) : "f"(hi), "f"(lo));
    return r;
}

__device__ __forceinline__ void cp16(unsigned saddr, const void* gaddr) {
    asm volatile("cp.async.cg.shared.global [%0], [%1], 16;"
                 :: "r"(saddr), "l"(gaddr));
}
#define CP_COMMIT() asm volatile("cp.async.commit_group;")
#define CP_WAIT(n)  asm volatile("cp.async.wait_group %0;" :: "n"(n))

// ---------------------------------------------------------------------------
// f32 -> bf16 conversion (word-pair granularity)
// ---------------------------------------------------------------------------
__global__ void f32_to_bf16(const float* __restrict__ src,
                            unsigned* __restrict__ dst, int nwords)
{
    const int i = blockIdx.x * blockDim.x + threadIdx.x;
    if (i < nwords) {
        float2 v = ((const float2*)src)[i];
        dst[i] = pk(v.x, v.y);
    }
}

// ---------------------------------------------------------------------------
// Double-buffered BF16 NT GEMM: 128x128x64-per-stage, m16n8k16.
// MODE 0 (FUSE): C=p; epilogue = +b_in, per-head softmax, xsum atomics.
// MODE 1 (BASE): C=out; epilogue = + sum_n inv[row][n]*y[bn][col] + b_out,
//                all in fp32 (exact mean path).
// Grid: (kD/128, rows/128). 256 threads, 8 warps of 32x64.
// ---------------------------------------------------------------------------
#define BSTG (128 * 36)  // words per stage per operand
#define GB_SMEM_BYTES ((4 * BSTG + 16 * 132 + 128 * 16) * 4)

template <int MODE>
__global__ __launch_bounds__(256, 2) void gemm2b(
    const unsigned short* __restrict__ A, const unsigned short* __restrict__ B,
    const float* __restrict__ bias, float* __restrict__ C,
    float* __restrict__ xsum, const float* __restrict__ yg,
    const float* __restrict__ invg)
{
    extern __shared__ unsigned smw[];
    unsigned* sA = smw;                         // [2][128][36]
    unsigned* sB = smw + 2 * BSTG;              // [2][128][36]
    float* sxs  = (float*)(smw + 4 * BSTG);     // FUSE: [128]
    float* ys   = (float*)(smw + 4 * BSTG);     // BASE: [16][132]
    float* invs = ys + 16 * 132;                // BASE: [128][16]

    const int tid  = threadIdx.x;
    const int lane = tid & 31, wid = tid >> 5;
    const int warpRow = wid & 3, warpCol = wid >> 2;
    const int gid = lane >> 2, tig = lane & 3;
    const int row0 = blockIdx.y * 128, col0 = blockIdx.x * 128;

    if (MODE == 0) {
        if (tid < 128) sxs[tid] = 0.f;
    } else {
        const int b = row0 >> 10;
        for (int i = tid; i < 16 * 128; i += 256) {
            const int nn = i >> 7, c = i & 127;
            ys[nn * 132 + c] = yg[(b * 16 + nn) * kD + col0 + c];
        }
        for (int i = tid; i < 128 * 16; i += 256)
            invs[i] = invg[(size_t)(row0 + (i >> 4)) * 16 + (i & 15)];
    }

    const int lrow = tid >> 1;
    const int lsel = tid & 1;
    const unsigned short* Asrc = A + (size_t)(row0 + lrow) * kD + lsel * 32;
    const unsigned short* Bsrc = B + (size_t)(col0 + lrow) * kD + lsel * 32;
    const unsigned aB =
        (unsigned)__cvta_generic_to_shared(&sA[lrow * 36 + lsel * 16]);
    const unsigned bB =
        (unsigned)__cvta_generic_to_shared(&sB[lrow * 36 + lsel * 16]);

    float acc[2][8][4];
#pragma unroll
    for (int i = 0; i < 2; i++)
#pragma unroll
        for (int j = 0; j < 8; j++)
#pragma unroll
            for (int k = 0; k < 4; k++) acc[i][j][k] = 0.f;

    // Prologue: stage 0
#pragma unroll
    for (int j = 0; j < 4; j++) {
        cp16(aB + j * 16, Asrc + j * 8);
        cp16(bB + j * 16, Bsrc + j * 8);
    }
    CP_COMMIT();

    const int nIter = kD / 64;  // 16
    for (int it = 0; it < nIter; it++) {
        const int buf = it & 1;
        if (it + 1 < nIter) {
            const unsigned off = (buf ^ 1) * (BSTG * 4);
            const int k0 = (it + 1) * 64;
#pragma unroll
            for (int j = 0; j < 4; j++) {
                cp16(aB + off + j * 16, Asrc + k0 + j * 8);
                cp16(bB + off + j * 16, Bsrc + k0 + j * 8);
            }
            CP_COMMIT();
            CP_WAIT(1);
        } else {
            CP_WAIT(0);
        }
        __syncthreads();

        const unsigned* Ab = sA + buf * BSTG;
        const unsigned* Bb = sB + buf * BSTG;
#pragma unroll
        for (int j = 0; j < 4; j++) {
            unsigned af[2][4], bf2[8][2];
#pragma unroll
            for (int mt = 0; mt < 2; mt++) {
                const int m = warpRow * 32 + mt * 16 + gid;
                af[mt][0] = Ab[m * 36 + 8 * j + tig];
                af[mt][1] = Ab[(m + 8) * 36 + 8 * j + tig];
                af[mt][2] = Ab[m * 36 + 8 * j + tig + 4];
                af[mt][3] = Ab[(m + 8) * 36 + 8 * j + tig + 4];
            }
#pragma unroll
            for (int nt = 0; nt < 8; nt++) {
                const int n = warpCol * 64 + nt * 8 + gid;
                bf2[nt][0] = Bb[n * 36 + 8 * j + tig];
                bf2[nt][1] = Bb[n * 36 + 8 * j + tig + 4];
            }
#pragma unroll
            for (int mt = 0; mt < 2; mt++)
#pragma unroll
                for (int nt = 0; nt < 8; nt++)
                    MMA_BF16(acc[mt][nt], af[mt][0], af[mt][1], af[mt][2],
                             af[mt][3], bf2[nt][0], bf2[nt][1]);
        }
        __syncthreads();
    }

    if (MODE == 1) {
        // BASE epilogue: out = acc + sum_n inv[row][n]*y[n][col] + b_out
        // (cl MUST include warpCol*64 — R10 bug was omitting it)
#pragma unroll
        for (int mt = 0; mt < 2; mt++) {
            const int rl = warpRow * 32 + mt * 16 + gid;
            float ia[16], ib[16];
#pragma unroll
            for (int q = 0; q < 4; q++) {
                *(float4*)&ia[q * 4] = *(float4*)&invs[rl * 16 + q * 4];
                *(float4*)&ib[q * 4] = *(float4*)&invs[(rl + 8) * 16 + q * 4];
            }
#pragma unroll
            for (int nt = 0; nt < 8; nt++) {
                const int cl = warpCol * 64 + nt * 8 + 2 * tig;
                float s00 = 0.f, s01 = 0.f, s10 = 0.f, s11 = 0.f;
#pragma unroll
                for (int n = 0; n < 16; n++) {
                    const float y0 = ys[n * 132 + cl];
                    const float y1 = ys[n * 132 + cl + 1];
                    s00 += ia[n] * y0; s01 += ia[n] * y1;
                    s10 += ib[n] * y0; s11 += ib[n] * y1;
                }
                const float bb0 = bias[col0 + cl], bb1 = bias[col0 + cl + 1];
                float2 v0, v1;
                v0.x = acc[mt][nt][0] + s00 + bb0;
                v0.y = acc[mt][nt][1] + s01 + bb1;
                v1.x = acc[mt][nt][2] + s10 + bb0;
                v1.y = acc[mt][nt][3] + s11 + bb1;
                *(float2*)(C + (size_t)(row0 + rl) * kD + col0 + cl)     = v0;
                *(float2*)(C + (size_t)(row0 + rl + 8) * kD + col0 + cl) = v1;
            }
        }
    } else {
        // FUSE epilogue: bias + per-head softmax + xsum
        const int head = blockIdx.x * 2 + warpCol;
        const int b    = blockIdx.y >> 3;
        const int bn   = b * 16 + head;
#pragma unroll
        for (int mt = 0; mt < 2; mt++)
#pragma unroll
            for (int nt = 0; nt < 8; nt++) {
                const int col = col0 + warpCol * 64 + nt * 8 + 2 * tig;
                acc[mt][nt][0] += bias[col];
                acc[mt][nt][1] += bias[col + 1];
                acc[mt][nt][2] += bias[col];
                acc[mt][nt][3] += bias[col + 1];
            }
        float xacc[8][2];
#pragma unroll
        for (int nt = 0; nt < 8; nt++) { xacc[nt][0] = 0.f; xacc[nt][1] = 0.f; }

#pragma unroll
        for (int mt = 0; mt < 2; mt++) {
#pragma unroll
            for (int half = 0; half < 2; half++) {
                float mx = -1e30f;
#pragma unroll
                for (int nt = 0; nt < 8; nt++)
                    mx = fmaxf(mx, fmaxf(acc[mt][nt][half * 2],
                                         acc[mt][nt][half * 2 + 1]));
                mx = fmaxf(mx, __shfl_xor_sync(0xffffffffu, mx, 1));
                mx = fmaxf(mx, __shfl_xor_sync(0xffffffffu, mx, 2));
                float sum = 0.f;
#pragma unroll
                for (int nt = 0; nt < 8; nt++) {
                    float e0 = __expf(acc[mt][nt][half * 2]     - mx);
                    float e1 = __expf(acc[mt][nt][half * 2 + 1] - mx);
                    acc[mt][nt][half * 2]     = e0;
                    acc[mt][nt][half * 2 + 1] = e1;
                    sum += e0 + e1;
                }
                sum += __shfl_xor_sync(0xffffffffu, sum, 1);
                sum += __shfl_xor_sync(0xffffffffu, sum, 2);
                const float inv = 1.f / sum;
                const int s = (row0 & 1023) + warpRow * 32 + mt * 16 + gid + half * 8;
                float* prow = C + ((size_t)bn * kS + s) * kH;
#pragma unroll
                for (int nt = 0; nt < 8; nt++) {
                    float p0 = acc[mt][nt][half * 2]     * inv;
                    float p1 = acc[mt][nt][half * 2 + 1] * inv;
                    float2 v; v.x = p0; v.y = p1;
                    *(float2*)(prow + nt * 8 + 2 * tig) = v;
                    xacc[nt][0] += p0;
                    xacc[nt][1] += p1;
                }
            }
        }
#pragma unroll
        for (int nt = 0; nt < 8; nt++) {
            atomicAdd(&sxs[warpCol * 64 + nt * 8 + 2 * tig],     xacc[nt][0]);
            atomicAdd(&sxs[warpCol * 64 + nt * 8 + 2 * tig + 1], xacc[nt][1]);
        }
        __syncthreads();
        if (tid < 128) {
            const int hh = tid & 63, hd = tid >> 6;
            atomicAdd(&xsum[(b * 16 + blockIdx.x * 2 + hd) * 64 + hh], sxs[tid]);
        }
    }
}

__global__ void zero_scratch(float* __restrict__ xsum, float* __restrict__ mf)
{
    const int i = blockIdx.x * blockDim.x + threadIdx.x;
    if (i < kBN * kH) xsum[i] = 0.f;
    if (i < kBN * 72 * 64) mf[i] = 0.f;
}

// ---------------------------------------------------------------------------
// compute_t: t[bn][o][e] = sum_h W[o][n][e][h] * xsum[bn][h]. Grid: 2048.
// ---------------------------------------------------------------------------
__global__ __launch_bounds__(256, 2) void compute_t4(const float* __restrict__ W,
                                                     const float* __restrict__ xsum,
                                                     float* __restrict__ t)
{
    const int n = blockIdx.x & 15, oc = blockIdx.x >> 4;
    __shared__ float xs[4][64];
    {
        const int bb = threadIdx.x >> 6, hh = threadIdx.x & 63;
        xs[bb][hh] = xsum[(bb * 16 + n) * 64 + hh];
    }
    __syncthreads();
    const int e = threadIdx.x >> 2, part = threadIdx.x & 3;
    float4 xr[4][4];
#pragma unroll
    for (int bb = 0; bb < 4; bb++)
#pragma unroll
        for (int j = 0; j < 4; j++)
            xr[bb][j] = *(const float4*)&xs[bb][part * 16 + j * 4];

#pragma unroll
    for (int oi = 0; oi < 8; oi++) {
        const int o = oc * 8 + oi;
        const float4* w =
            (const float4*)(W + (((size_t)o * 16 + n) * 64 + e) * 64 + part * 16);
        const float4 w0 = w[0], w1 = w[1], w2 = w[2], w3 = w[3];
        float r[4];
#pragma unroll
        for (int bb = 0; bb < 4; bb++) {
            r[bb] = w0.x * xr[bb][0].x + w0.y * xr[bb][0].y
                  + w0.z * xr[bb][0].z + w0.w * xr[bb][0].w
                  + w1.x * xr[bb][1].x + w1.y * xr[bb][1].y
                  + w1.z * xr[bb][1].z + w1.w * xr[bb][1].w
                  + w2.x * xr[bb][2].x + w2.y * xr[bb][2].y
                  + w2.z * xr[bb][2].z + w2.w * xr[bb][2].w
                  + w3.x * xr[bb][3].x + w3.y * xr[bb][3].y
                  + w3.z * xr[bb][3].z + w3.w * xr[bb][3].w;
        }
#pragma unroll
        for (int bb = 0; bb < 4; bb++) {
            r[bb] += __shfl_xor_sync(0xffffffffu, r[bb], 1);
            r[bb] += __shfl_xor_sync(0xffffffffu, r[bb], 2);
        }
        t[(((size_t)(part * 16 + n)) * kS + o) * kH + e] = r[part];
    }
}

// ---------------------------------------------------------------------------
// calc_y: y[bn][d] = sum_h xsum[bn][h] * w_out[d][n*64+h] (fp32 exact).
// Grid: (16 n * 8 dchunk) = 128 blocks, 128 threads (one d each, all 4 b).
// ---------------------------------------------------------------------------
__global__ __launch_bounds__(128) void calc_y(const float* __restrict__ xsum,
                                              const float* __restrict__ wout,
                                              float* __restrict__ y)
{
    const int n = blockIdx.x & 15, dc = blockIdx.x >> 4;
    __shared__ float xs[4][64];
    {
        int i = threadIdx.x;
        xs[i >> 6][i & 63] = xsum[((i >> 6) * 16 + n) * 64 + (i & 63)];
        i += 128;
        xs[i >> 6][i & 63] = xsum[((i >> 6) * 16 + n) * 64 + (i & 63)];
    }
    __syncthreads();
    const int d = dc * 128 + threadIdx.x;
    const float4* wp = (const float4*)(wout + (size_t)d * kD + n * 64);
    float a0 = 0.f, a1 = 0.f, a2 = 0.f, a3 = 0.f;
#pragma unroll
    for (int q = 0; q < 16; q++) {
        const float4 wv = wp[q];
        const float* x0 = &xs[0][q * 4];
        const float* x1 = &xs[1][q * 4];
        const float* x2 = &xs[2][q * 4];
        const float* x3 = &xs[3][q * 4];
        a0 += wv.x * x0[0] + wv.y * x0[1] + wv.z * x0[2] + wv.w * x0[3];
        a1 += wv.x * x1[0] + wv.y * x1[1] + wv.z * x1[2] + wv.w * x1[3];
        a2 += wv.x * x2[0] + wv.y * x2[1] + wv.z * x2[2] + wv.w * x2[3];
        a3 += wv.x * x3[0] + wv.y * x3[1] + wv.z * x3[2] + wv.w * x3[3];
    }
    y[(0 * 16 + n) * kD + d] = a0;
    y[(1 * 16 + n) * kD + d] = a1;
    y[(2 * 16 + n) * kD + d] = a2;
    y[(3 * 16 + n) * kD + d] = a3;
}

// ---------------------------------------------------------------------------
// gemm_m (split-K): partial M[e][h] += sum_o t*p; tau via ones col.
// fp32 atomicAdd into Mf[bn][col][e]. Grid: (kBN, 8). 128 threads.
// ---------------------------------------------------------------------------
__global__ __launch_bounds__(128) void gemm_m(
    const float* __restrict__ Tg, const float* __restrict__ Pg,
    float* __restrict__ Mf)
{
    __shared__ unsigned As[64 * 36];
    __shared__ unsigned Bs[72 * 36];

    const int bn = blockIdx.x;
    const int o_base = blockIdx.y * 128;
    const int tid = threadIdx.x, lane = tid & 31, wid = tid >> 5;
    const int gid = lane >> 2, tig = lane & 3;
    const float* Tp = Tg + (size_t)bn * kS * kH;
    const float* Pp = Pg + (size_t)bn * kS * kH;

    for (int i = tid; i < 8 * 36; i += 128) {
        const int r = 64 + i / 36, w = i % 36;
        Bs[r * 36 + w] = (r == 64 && w < 32) ? 0x3F803F80u : 0u;
    }

    float acc[9][4];
#pragma unroll
    for (int j = 0; j < 9; j++)
#pragma unroll
        for (int k = 0; k < 4; k++) acc[j][k] = 0.f;

    const int op = tid & 31;
    const int cb = (tid >> 5) * 16;

#pragma unroll
    for (int oi = 0; oi < 2; oi++) {
        const int o0 = o_base + oi * 64;
        __syncthreads();
        {
            const float* r0p = Tp + (size_t)(o0 + 2 * op) * kH + cb;
            const float* r1p = r0p + kH;
#pragma unroll
            for (int q = 0; q < 4; q++) {
                float4 u = *(const float4*)(r0p + q * 4);
                float4 w = *(const float4*)(r1p + q * 4);
                As[(cb + q * 4 + 0) * 36 + op] = pk(u.x, w.x);
                As[(cb + q * 4 + 1) * 36 + op] = pk(u.y, w.y);
                As[(cb + q * 4 + 2) * 36 + op] = pk(u.z, w.z);
                As[(cb + q * 4 + 3) * 36 + op] = pk(u.w, w.w);
            }
        }
        {
            const float* r0p = Pp + (size_t)(o0 + 2 * op) * kH + cb;
            const float* r1p = r0p + kH;
#pragma unroll
            for (int q = 0; q < 4; q++) {
                float4 u = *(const float4*)(r0p + q * 4);
                float4 w = *(const float4*)(r1p + q * 4);
                Bs[(cb + q * 4 + 0) * 36 + op] = pk(u.x, w.x);
                Bs[(cb + q * 4 + 1) * 36 + op] = pk(u.y, w.y);
                Bs[(cb + q * 4 + 2) * 36 + op] = pk(u.z, w.z);
                Bs[(cb + q * 4 + 3) * 36 + op] = pk(u.w, w.w);
            }
        }
        __syncthreads();

        const int mrow = wid * 16 + gid;
#pragma unroll
        for (int j = 0; j < 4; j++) {
            unsigned a0 = As[mrow * 36 + 8 * j + tig];
            unsigned a1 = As[(mrow + 8) * 36 + 8 * j + tig];
            unsigned a2 = As[mrow * 36 + 8 * j + tig + 4];
            unsigned a3 = As[(mrow + 8) * 36 + 8 * j + tig + 4];
#pragma unroll
            for (int nt = 0; nt < 9; nt++) {
                unsigned b0 = Bs[(nt * 8 + gid) * 36 + 8 * j + tig];
                unsigned b1 = Bs[(nt * 8 + gid) * 36 + 8 * j + tig + 4];
                MMA_BF16(acc[nt], a0, a1, a2, a3, b0, b1);
            }
        }
    }

    float* mf = Mf + (size_t)bn * 72 * 64;
    const int mrow = wid * 16 + gid;
#pragma unroll
    for (int nt = 0; nt < 9; nt++) {
        const int col = nt * 8 + 2 * tig;
        if (col < 65) {
            atomicAdd(&mf[col * 64 + mrow],           acc[nt][0]);
            atomicAdd(&mf[col * 64 + mrow + 8],       acc[nt][2]);
            if (col + 1 < 65) {
                atomicAdd(&mf[(col + 1) * 64 + mrow],     acc[nt][1]);
                atomicAdd(&mf[(col + 1) * 64 + mrow + 8], acc[nt][3]);
            }
        }
    }
}

// ---------------------------------------------------------------------------
// gemm_apply: computes correction c = p_s @ M' and denominator l; writes
// a_c[s][n64+h] = c*inv (bf16) and inv[s][n] (fp32). NO xsum add here.
// Grid: (kS/128, kBN). 256 threads.
// ---------------------------------------------------------------------------
__global__ __launch_bounds__(256) void gemm_apply(
    const float* __restrict__ Pg, const float* __restrict__ Mf,
    unsigned* __restrict__ ACb, float* __restrict__ Invg)
{
    __shared__ unsigned Ps[128 * 36];
    __shared__ unsigned Bs[72 * 36];

    const int bn = blockIdx.y;
    const int s0 = blockIdx.x * 128;
    const float* Pp = Pg + (size_t)bn * kS * kH;
    const float* mf = Mf + (size_t)bn * 72 * 64;

    const int tid = threadIdx.x, lane = tid & 31, wid = tid >> 5;
    const int gid = lane >> 2, tig = lane & 3;
    const int mrow = wid * 16 + gid;
    const float ms = 1.f / 2048.f;

    for (int i = tid; i < 72 * 32; i += 256) {
        const int r = i >> 5, w = i & 31;
        float2 v = *(const float2*)(mf + r * 64 + 2 * w);
        Bs[r * 36 + w] = pk(v.x * ms, v.y * ms);
    }
    {
        const int r0 = tid >> 4, c = (tid & 15) * 4;
#pragma unroll
        for (int pass = 0; pass < 8; pass++) {
            const int r = r0 + pass * 16;
            float4 v = *(const float4*)(Pp + (size_t)(s0 + r) * kH + c);
            uint2 w;
            w.x = pk(v.x, v.y);
            w.y = pk(v.z, v.w);
            *(uint2*)&Ps[r * 36 + c / 2] = w;
        }
    }
    __syncthreads();

    float acc[9][4];
#pragma unroll
    for (int j = 0; j < 9; j++)
#pragma unroll
        for (int k = 0; k < 4; k++) acc[j][k] = 0.f;

#pragma unroll
    for (int j = 0; j < 4; j++) {
        unsigned a0 = Ps[mrow * 36 + 8 * j + tig];
        unsigned a1 = Ps[(mrow + 8) * 36 + 8 * j + tig];
        unsigned a2 = Ps[mrow * 36 + 8 * j + tig + 4];
        unsigned a3 = Ps[(mrow + 8) * 36 + 8 * j + tig + 4];
#pragma unroll
        for (int nt = 0; nt < 9; nt++) {
            unsigned b0 = Bs[(nt * 8 + gid) * 36 + 8 * j + tig];
            unsigned b1 = Bs[(nt * 8 + gid) * 36 + 8 * j + tig + 4];
            MMA_BF16(acc[nt], a0, a1, a2, a3, b0, b1);
        }
    }

    const float tau0 = __shfl_sync(0xffffffffu, acc[8][0], lane & 28);
    const float tau1 = __shfl_sync(0xffffffffu, acc[8][2], lane & 28);
    const float inv0 = 1.f / (1024.f + tau0);
    const float inv1 = 1.f / (1024.f + tau1);

    const int b = bn >> 4, n = bn & 15;
    const size_t rglob = (size_t)(b * kS + s0 + mrow);
    unsigned* Cb = ACb + (rglob * kD + n * 64) / 2;
#pragma unroll
    for (int nt = 0; nt < 8; nt++) {
        Cb[nt * 4 + tig]              = pk(acc[nt][0] * inv0, acc[nt][1] * inv0);
        Cb[4 * kD + nt * 4 + tig]     = pk(acc[nt][2] * inv1, acc[nt][3] * inv1);
    }
    if (tig == 0) {
        Invg[rglob * 16 + n]       = inv0;
        Invg[(rglob + 8) * 16 + n] = inv1;
    }
}

// ---------------------------------------------------------------------------
extern "C" void kernel_launch(void* const* d_in, const int* in_sizes, int n_in,
                              void* d_out, int out_size)
{
    (void)in_sizes; (void)n_in; (void)out_size;
    const float* x      = (const float*)d_in[0];
    const float* attn_w = (const float*)d_in[1];
    const float* w_in   = (const float*)d_in[2];
    const float* b_in   = (const float*)d_in[3];
    const float* w_out  = (const float*)d_in[4];
    const float* b_out  = (const float*)d_in[5];
    float* out = (float*)d_out;

    float *pp, *pxs, *pt, *pmf, *pinv, *py;
    unsigned *pxb, *pwinb, *pwoutb, *pacb;
    cudaGetSymbolAddress((void**)&pp,    g_p);
    cudaGetSymbolAddress((void**)&pxs,   g_xsum);
    cudaGetSymbolAddress((void**)&pt,    g_t);
    cudaGetSymbolAddress((void**)&pmf,   g_mf);
    cudaGetSymbolAddress((void**)&pinv,  g_inv);
    cudaGetSymbolAddress((void**)&py,    g_y);
    cudaGetSymbolAddress((void**)&pxb,   g_xb);
    cudaGetSymbolAddress((void**)&pwinb, g_winb);
    cudaGetSymbolAddress((void**)&pwoutb, g_woutb);
    cudaGetSymbolAddress((void**)&pacb,  g_acb);

    cudaFuncSetAttribute(gemm2b<0>, cudaFuncAttributeMaxDynamicSharedMemorySize,
                         GB_SMEM_BYTES);
    cudaFuncSetAttribute(gemm2b<1>, cudaFuncAttributeMaxDynamicSharedMemorySize,
                         GB_SMEM_BYTES);

    // 0) zero xsum + M scratch; convert inputs to bf16
    zero_scratch<<<(kBN * 72 * 64 + 255) / 256, 256>>>(pxs, pmf);
    f32_to_bf16<<<(kB * kS * kD / 2 + 255) / 256, 256>>>(x, pxb, kB * kS * kD / 2);
    f32_to_bf16<<<(kD * kD / 2 + 255) / 256, 256>>>(w_in, pwinb, kD * kD / 2);
    f32_to_bf16<<<(kD * kD / 2 + 255) / 256, 256>>>(w_out, pwoutb, kD * kD / 2);

    // 1+2) h = x @ w_in^T + b_in (bf16 MMA), fused softmax -> p, xsum
    gemm2b<0><<<dim3(kD / 128, (kB * kS) / 128), 256, GB_SMEM_BYTES>>>(
        (const unsigned short*)pxb, (const unsigned short*)pwinb,
        b_in, pp, pxs, nullptr, nullptr);

    // 3) t = W . xsum
    compute_t4<<<2048, 256>>>(attn_w, pxs, pt);

    // 3b) y[bn][d] = xsum . w_out slice (fp32 exact mean path)
    calc_y<<<128, 128>>>(pxs, w_out, py);

    // 4) M = t^T @ p (+tau), split-K, fp32 atomics
    gemm_m<<<dim3(kBN, 8), 128>>>(pt, pp, pmf);

    // 5) correction a_c (bf16, inv-folded) + inv
    gemm_apply<<<dim3(kS / 128, kBN), 256>>>(pp, pmf, pacb, pinv);

    // 6) out = a_c @ w_out^T (bf16) + sum_n inv*y (fp32) + b_out
    gemm2b<1><<<dim3(kD / 128, (kB * kS) / 128), 256, GB_SMEM_BYTES>>>(
        (const unsigned short*)pacb, (const unsigned short*)pwoutb,
        b_out, out, nullptr, py, pinv);
}